// round 1
// baseline (speedup 1.0000x reference)
#include <cuda_runtime.h>

// ---------------- problem constants ----------------
#define B_   4
#define L_   4096
#define D_   1024
#define H_   16
#define BS_  64
#define HD_  64
#define NB_  64
#define TD_  3072           // 3*D
#define SCALE_ 0.125f       // HD^-0.5
#define TEMP_  0.7f

// ---------------- device scratch (allocation-free) ----------------
__device__ float g_qkv  [B_*L_*TD_];          // 192 MB
__device__ float g_qrepr[B_*H_*NB_*HD_];
__device__ float g_krepr[B_*H_*NB_*HD_];
__device__ float g_P    [B_*H_*NB_*NB_];
__device__ float g_ksort[B_*H_*NB_*BS_*HD_];  // 64 MB
__device__ float g_vsort[B_*H_*NB_*BS_*HD_];  // 64 MB
__device__ float g_attn [B_*L_*D_];           // 64 MB

// ---------------- 128x128x8 fp32 SGEMM with bias ----------------
// C[M,N] = A[M,K] @ B[K,N] + bias[N].  M,N multiples of 128, K multiple of 8.
__global__ __launch_bounds__(256) void sgemm_kernel(
    const float* __restrict__ A, const float* __restrict__ Bm,
    const float* __restrict__ bias, float* __restrict__ C,
    int M, int N, int K)
{
    __shared__ float As[8][128];
    __shared__ float Bs[8][128];
    const int tid = threadIdx.x;
    const int tx = tid & 15, ty = tid >> 4;

    const int aRow = tid >> 1;          // 0..127
    const int aCol = (tid & 1) << 2;    // 0 or 4
    const int bRow = tid >> 5;          // 0..7
    const int bCol = (tid & 31) << 2;   // 0..124

    const float* Ag = A + (size_t)(blockIdx.y * 128 + aRow) * K + aCol;
    const float* Bg = Bm + (size_t)bRow * N + blockIdx.x * 128 + bCol;

    float acc[8][8] = {};

    for (int k0 = 0; k0 < K; k0 += 8) {
        float4 a4 = *(const float4*)(Ag + k0);
        float4 b4 = *(const float4*)(Bg + (size_t)k0 * N);
        As[aCol + 0][aRow] = a4.x;
        As[aCol + 1][aRow] = a4.y;
        As[aCol + 2][aRow] = a4.z;
        As[aCol + 3][aRow] = a4.w;
        *(float4*)&Bs[bRow][bCol] = b4;
        __syncthreads();
#pragma unroll
        for (int kk = 0; kk < 8; kk++) {
            float4 a0 = *(float4*)&As[kk][ty * 8];
            float4 a1 = *(float4*)&As[kk][ty * 8 + 4];
            float4 b0 = *(float4*)&Bs[kk][tx * 8];
            float4 b1 = *(float4*)&Bs[kk][tx * 8 + 4];
            float ar[8] = {a0.x, a0.y, a0.z, a0.w, a1.x, a1.y, a1.z, a1.w};
            float br[8] = {b0.x, b0.y, b0.z, b0.w, b1.x, b1.y, b1.z, b1.w};
#pragma unroll
            for (int i = 0; i < 8; i++)
#pragma unroll
                for (int j = 0; j < 8; j++)
                    acc[i][j] += ar[i] * br[j];
        }
        __syncthreads();
    }

    const int row0 = blockIdx.y * 128 + ty * 8;
    const int col0 = blockIdx.x * 128 + tx * 8;
    float bb[8];
#pragma unroll
    for (int j = 0; j < 8; j++) bb[j] = bias[col0 + j];
#pragma unroll
    for (int i = 0; i < 8; i++) {
        float4 c0 = make_float4(acc[i][0] + bb[0], acc[i][1] + bb[1],
                                acc[i][2] + bb[2], acc[i][3] + bb[3]);
        float4 c1 = make_float4(acc[i][4] + bb[4], acc[i][5] + bb[5],
                                acc[i][6] + bb[6], acc[i][7] + bb[7]);
        *(float4*)(C + (size_t)(row0 + i) * N + col0)     = c0;
        *(float4*)(C + (size_t)(row0 + i) * N + col0 + 4) = c1;
    }
}

// ---------------- block mean reprs ----------------
// qrepr/krepr[b,h,n,d] = mean_s qkv[b, n*BS+s, (0|D) + h*HD + d]
__global__ void repr_kernel(const float* __restrict__ qkv,
                            float* __restrict__ qrepr, float* __restrict__ krepr)
{
    int idx = blockIdx.x * blockDim.x + threadIdx.x;  // B*H*NB*HD = 262144
    int d = idx & 63;
    int n = (idx >> 6) & 63;
    int h = (idx >> 12) & 15;
    int b = idx >> 16;
    const float* base = qkv + ((size_t)(b * L_ + n * BS_)) * TD_ + h * HD_ + d;
    float sq = 0.f, sk = 0.f;
#pragma unroll 8
    for (int s = 0; s < BS_; s++) {
        sq += base[(size_t)s * TD_];
        sk += base[(size_t)s * TD_ + D_];
    }
    qrepr[idx] = sq * (1.0f / BS_);
    krepr[idx] = sk * (1.0f / BS_);
}

// ---------------- sim + gumbel + sinkhorn -> P ----------------
// one block per (b,h); 64x64 log-alpha in smem
__global__ __launch_bounds__(256) void sinkhorn_kernel(
    const float* __restrict__ qrepr, const float* __restrict__ krepr,
    const float* __restrict__ gumbel, float* __restrict__ P)
{
    __shared__ float La[64][65];
    const int bh = blockIdx.x;
    const int tid = threadIdx.x;
    const float* qr = qrepr + bh * NB_ * HD_;
    const float* kr = krepr + bh * NB_ * HD_;

    for (int e = tid; e < NB_ * NB_; e += 256) {
        int nn = e >> 6, m = e & 63;
        float s = 0.f;
#pragma unroll 16
        for (int d = 0; d < HD_; d++) s += qr[nn * HD_ + d] * kr[m * HD_ + d];
        La[nn][m] = (s * SCALE_ + gumbel[bh * NB_ * NB_ + e]) * (1.0f / TEMP_);
    }
    __syncthreads();

    for (int it = 0; it < 7; it++) {
        if (tid < 64) {  // row logsumexp (axis -1)
            float mx = -1e30f;
            for (int m = 0; m < 64; m++) mx = fmaxf(mx, La[tid][m]);
            float se = 0.f;
            for (int m = 0; m < 64; m++) se += expf(La[tid][m] - mx);
            float ls = mx + logf(se);
            for (int m = 0; m < 64; m++) La[tid][m] -= ls;
        }
        __syncthreads();
        if (tid < 64) {  // col logsumexp (axis -2)
            float mx = -1e30f;
            for (int r = 0; r < 64; r++) mx = fmaxf(mx, La[r][tid]);
            float se = 0.f;
            for (int r = 0; r < 64; r++) se += expf(La[r][tid] - mx);
            float ls = mx + logf(se);
            for (int r = 0; r < 64; r++) La[r][tid] -= ls;
        }
        __syncthreads();
    }
    for (int e = tid; e < NB_ * NB_; e += 256)
        P[bh * NB_ * NB_ + e] = expf(La[e >> 6][e & 63]);
}

// ---------------- k/v soft permutation (P @ flat blocks) ----------------
// grid (B*H, 16); each thread owns one f = s*HD+d column of the 64x4096 output
__global__ __launch_bounds__(256) void sort_kernel(
    const float* __restrict__ qkv, const float* __restrict__ P,
    float* __restrict__ ksort, float* __restrict__ vsort)
{
    const int bh = blockIdx.x;
    const int b = bh >> 4, h = bh & 15;
    const int f = blockIdx.y * 256 + threadIdx.x;   // 0..4095
    const int s = f >> 6, d = f & 63;

    __shared__ float Ps[64][64];
    for (int e = threadIdx.x; e < 4096; e += 256)
        Ps[e >> 6][e & 63] = P[bh * 4096 + e];
    __syncthreads();

    const float* base = qkv + ((size_t)(b * L_ + s)) * TD_ + h * HD_ + d;
    float km[64], vm[64];
#pragma unroll
    for (int m = 0; m < 64; m++) {
        const float* p = base + (size_t)m * BS_ * TD_;
        km[m] = p[D_];
        vm[m] = p[2 * D_];
    }
    const size_t obase = (size_t)bh * NB_ * BS_ * HD_ + f;
    for (int n2 = 0; n2 < 64; n2++) {
        float sk = 0.f, sv = 0.f;
#pragma unroll
        for (int m = 0; m < 64; m++) {
            sk += Ps[n2][m] * km[m];
            sv += Ps[n2][m] * vm[m];
        }
        ksort[obase + (size_t)n2 * BS_ * HD_] = sk;
        vsort[obase + (size_t)n2 * BS_ * HD_] = sv;
    }
}

// ---------------- block attention ----------------
// one block per (b,h,n). Q[64,64] vs K_local[128,64]; softmax; @ V_local.
// smem layout (floats): Qt[64][68] (d-major), Kt[64][132] (d-major),
// Vs[128][64] (j-major), Sct[128][68] (j-major scores/probs)
#define ATTN_SMEM ((64*68 + 64*132 + 128*64 + 128*68) * 4)
__global__ __launch_bounds__(256) void attn_kernel(
    const float* __restrict__ qkv, const float* __restrict__ ksort,
    const float* __restrict__ vsort, float* __restrict__ aout)
{
    extern __shared__ float sm[];
    float* Qt  = sm;                 // [64][68]
    float* Kt  = Qt + 64 * 68;       // [64][132]
    float* Vs  = Kt + 64 * 132;      // [128][64]
    float* Sct = Vs + 128 * 64;      // [128][68]

    const int blk = blockIdx.x;
    const int n2 = blk & 63;
    const int h = (blk >> 6) & 15;
    const int b = blk >> 10;
    const int bh = b * H_ + h;
    const int tid = threadIdx.x;
    const int nn = (n2 + 1) & 63;

    const float* qbase   = qkv + ((size_t)(b * L_ + n2 * BS_)) * TD_ + h * HD_;
    const float* nbase_k = ksort + ((size_t)(bh * NB_ + nn)) * BS_ * HD_;
    const float* nbase_v = vsort + ((size_t)(bh * NB_ + nn)) * BS_ * HD_;

    for (int i4 = tid; i4 < 1024; i4 += 256) {
        int s  = i4 >> 4;
        int d4 = (i4 & 15) << 2;
        float4 qv = *(const float4*)(qbase + (size_t)s * TD_ + d4);
        float4 kv = *(const float4*)(qbase + (size_t)s * TD_ + D_ + d4);
        float4 vv = *(const float4*)(qbase + (size_t)s * TD_ + 2 * D_ + d4);
        float4 kn = *(const float4*)(nbase_k + s * HD_ + d4);
        float4 vn = *(const float4*)(nbase_v + s * HD_ + d4);
        Qt[(d4 + 0) * 68 + s] = qv.x;  Qt[(d4 + 1) * 68 + s] = qv.y;
        Qt[(d4 + 2) * 68 + s] = qv.z;  Qt[(d4 + 3) * 68 + s] = qv.w;
        Kt[(d4 + 0) * 132 + s] = kv.x; Kt[(d4 + 1) * 132 + s] = kv.y;
        Kt[(d4 + 2) * 132 + s] = kv.z; Kt[(d4 + 3) * 132 + s] = kv.w;
        Kt[(d4 + 0) * 132 + 64 + s] = kn.x; Kt[(d4 + 1) * 132 + 64 + s] = kn.y;
        Kt[(d4 + 2) * 132 + 64 + s] = kn.z; Kt[(d4 + 3) * 132 + 64 + s] = kn.w;
        *(float4*)(Vs + s * 64 + d4)        = vv;
        *(float4*)(Vs + (64 + s) * 64 + d4) = vn;
    }
    __syncthreads();

    // scores: thread tile 4 (s) x 8 (j)
    const int ts = tid >> 4, tc = tid & 15;
    const int s0 = ts * 4, j0 = tc * 8;
    {
        float acc[4][8] = {};
#pragma unroll 16
        for (int d = 0; d < 64; d++) {
            float4 q4  = *(float4*)(Qt + d * 68 + s0);
            float4 k4a = *(float4*)(Kt + d * 132 + j0);
            float4 k4b = *(float4*)(Kt + d * 132 + j0 + 4);
            float qs[4] = {q4.x, q4.y, q4.z, q4.w};
            float ks[8] = {k4a.x, k4a.y, k4a.z, k4a.w, k4b.x, k4b.y, k4b.z, k4b.w};
#pragma unroll
            for (int i = 0; i < 4; i++)
#pragma unroll
                for (int j = 0; j < 8; j++)
                    acc[i][j] += qs[i] * ks[j];
        }
        const bool lastblk = (n2 == NB_ - 1);
#pragma unroll
        for (int i = 0; i < 4; i++)
#pragma unroll
            for (int j = 0; j < 8; j++) {
                float v = acc[i][j] * SCALE_;
                if (lastblk && (j0 + j) >= 64) v = -1e9f;
                Sct[(j0 + j) * 68 + (s0 + i)] = v;
            }
    }
    __syncthreads();

    // softmax per query row (over 128 keys)
    if (tid < 64) {
        const int s = tid;
        float mx = -1e30f;
        for (int j = 0; j < 128; j++) mx = fmaxf(mx, Sct[j * 68 + s]);
        float se = 0.f;
        for (int j = 0; j < 128; j++) se += expf(Sct[j * 68 + s] - mx);
        float inv = 1.0f / se;
        for (int j = 0; j < 128; j++)
            Sct[j * 68 + s] = expf(Sct[j * 68 + s] - mx) * inv;
    }
    __syncthreads();

    // out = P @ V : thread tile 4 (s) x 4 (d)
    const int d0 = (tid & 15) * 4;
    float oacc[4][4] = {};
#pragma unroll 8
    for (int j = 0; j < 128; j++) {
        float4 p4 = *(float4*)(Sct + j * 68 + s0);
        float4 v4 = *(float4*)(Vs + j * 64 + d0);
        float ps[4] = {p4.x, p4.y, p4.z, p4.w};
        float vs[4] = {v4.x, v4.y, v4.z, v4.w};
#pragma unroll
        for (int i = 0; i < 4; i++)
#pragma unroll
            for (int k = 0; k < 4; k++)
                oacc[i][k] += ps[i] * vs[k];
    }
    float* ob = aout + ((size_t)(b * L_ + n2 * BS_)) * D_ + h * HD_;
#pragma unroll
    for (int i = 0; i < 4; i++) {
        float4 w = make_float4(oacc[i][0], oacc[i][1], oacc[i][2], oacc[i][3]);
        *(float4*)(ob + (size_t)(s0 + i) * D_ + d0) = w;
    }
}

// ---------------- launch ----------------
extern "C" void kernel_launch(void* const* d_in, const int* in_sizes, int n_in,
                              void* d_out, int out_size)
{
    const float* x      = (const float*)d_in[0];
    const float* gumbel = (const float*)d_in[1];
    const float* W_qkv  = (const float*)d_in[2];
    const float* b_qkv  = (const float*)d_in[3];
    const float* W_out  = (const float*)d_in[4];
    const float* b_out  = (const float*)d_in[5];
    float* out = (float*)d_out;

    float *qkv, *qr, *kr, *P, *ks, *vs, *at;
    cudaGetSymbolAddress((void**)&qkv, g_qkv);
    cudaGetSymbolAddress((void**)&qr,  g_qrepr);
    cudaGetSymbolAddress((void**)&kr,  g_krepr);
    cudaGetSymbolAddress((void**)&P,   g_P);
    cudaGetSymbolAddress((void**)&ks,  g_ksort);
    cudaGetSymbolAddress((void**)&vs,  g_vsort);
    cudaGetSymbolAddress((void**)&at,  g_attn);

    cudaFuncSetAttribute(attn_kernel,
                         cudaFuncAttributeMaxDynamicSharedMemorySize, ATTN_SMEM);

    // 1) qkv = x @ W_qkv + b_qkv
    sgemm_kernel<<<dim3(TD_ / 128, (B_ * L_) / 128), 256>>>(
        x, W_qkv, b_qkv, qkv, B_ * L_, TD_, D_);

    // 2) block mean reprs
    repr_kernel<<<(B_ * H_ * NB_ * HD_) / 256, 256>>>(qkv, qr, kr);

    // 3) sinkhorn -> P
    sinkhorn_kernel<<<B_ * H_, 256>>>(qr, kr, gumbel, P);

    // 4) soft-permute K/V blocks
    sort_kernel<<<dim3(B_ * H_, (BS_ * HD_) / 256), 256>>>(qkv, P, ks, vs);

    // 5) block attention
    attn_kernel<<<B_ * H_ * NB_, 256, ATTN_SMEM>>>(qkv, ks, vs, at);

    // 6) out = attn @ W_out + b_out
    sgemm_kernel<<<dim3(D_ / 128, (B_ * L_) / 128), 256>>>(
        at, W_out, b_out, out, B_ * L_, D_, D_);
}

// round 2
// speedup vs baseline: 1.8230x; 1.8230x over previous
#include <cuda_runtime.h>
#include <cuda_bf16.h>
#include <cstdint>

// ---------------- problem constants ----------------
#define B_   4
#define L_   4096
#define D_   1024
#define H_   16
#define BS_  64
#define HD_  64
#define NB_  64
#define TD_  3072           // 3*D
#define M_   (B_*L_)        // 16384
#define SCALE_ 0.125f       // HD^-0.5
#define TEMP_  0.7f

typedef __nv_bfloat16 bf16;

// ---------------- device scratch (allocation-free) ----------------
__device__ float g_qkv  [B_*L_*TD_];            // 192 MB fp32
__device__ float g_qrepr[B_*H_*NB_*HD_];
__device__ float g_krepr[B_*H_*NB_*HD_];
__device__ float g_P    [B_*H_*NB_*NB_];
__device__ float g_ksort[B_*H_*NB_*BS_*HD_];    // 64 MB
__device__ float g_vsort[B_*H_*NB_*BS_*HD_];    // 64 MB
__device__ bf16  g_xhi  [M_*D_];                // 32 MB
__device__ bf16  g_xlo  [M_*D_];
__device__ bf16  g_w1hi [TD_*D_];               // W_qkv^T hi  [3072][1024]
__device__ bf16  g_w1lo [TD_*D_];
__device__ bf16  g_w2hi [D_*D_];                // W_out^T hi
__device__ bf16  g_w2lo [D_*D_];
__device__ bf16  g_athi [M_*D_];                // attn out hi
__device__ bf16  g_atlo [M_*D_];

// ---------------- PTX helpers ----------------
__device__ __forceinline__ unsigned smem_u32(const void* p) {
    return (unsigned)__cvta_generic_to_shared(p);
}
__device__ __forceinline__ void ldsm4(unsigned* r, unsigned addr) {
    asm volatile("ldmatrix.sync.aligned.m8n8.x4.shared.b16 {%0,%1,%2,%3}, [%4];\n"
                 : "=r"(r[0]), "=r"(r[1]), "=r"(r[2]), "=r"(r[3]) : "r"(addr));
}
__device__ __forceinline__ void mma16816(float* c, const unsigned* a, const unsigned* b) {
    asm volatile(
        "mma.sync.aligned.m16n8k16.row.col.f32.bf16.bf16.f32 "
        "{%0,%1,%2,%3}, {%4,%5,%6,%7}, {%8,%9}, {%0,%1,%2,%3};\n"
        : "+f"(c[0]), "+f"(c[1]), "+f"(c[2]), "+f"(c[3])
        : "r"(a[0]), "r"(a[1]), "r"(a[2]), "r"(a[3]), "r"(b[0]), "r"(b[1]));
}
#define CP_ASYNC16(dst, src) \
    asm volatile("cp.async.cg.shared.global [%0], [%1], 16;\n" :: "r"(dst), "l"(src))
#define CP_COMMIT() asm volatile("cp.async.commit_group;\n")
#define CP_WAIT(n)  asm volatile("cp.async.wait_group %0;\n" :: "n"(n))

// ---------------- split conversion: f32 -> bf16 hi + lo ----------------
__global__ void split_kernel(const float* __restrict__ src,
                             bf16* __restrict__ hi, bf16* __restrict__ lo, int n4)
{
    int i = blockIdx.x * blockDim.x + threadIdx.x;
    if (i >= n4) return;
    float4 v = ((const float4*)src)[i];
    bf16 h0 = __float2bfloat16_rn(v.x), h1 = __float2bfloat16_rn(v.y);
    bf16 h2 = __float2bfloat16_rn(v.z), h3 = __float2bfloat16_rn(v.w);
    bf16 l0 = __float2bfloat16_rn(v.x - __bfloat162float(h0));
    bf16 l1 = __float2bfloat16_rn(v.y - __bfloat162float(h1));
    bf16 l2 = __float2bfloat16_rn(v.z - __bfloat162float(h2));
    bf16 l3 = __float2bfloat16_rn(v.w - __bfloat162float(h3));
    __nv_bfloat162* hp = (__nv_bfloat162*)(hi + i * 4);
    __nv_bfloat162* lp = (__nv_bfloat162*)(lo + i * 4);
    hp[0] = __nv_bfloat162(h0, h1); hp[1] = __nv_bfloat162(h2, h3);
    lp[0] = __nv_bfloat162(l0, l1); lp[1] = __nv_bfloat162(l2, l3);
}

// ---------------- transpose + split: W[K][N] -> T[N][K] hi/lo ----------------
__global__ void wsplit_kernel(const float* __restrict__ W,
                              bf16* __restrict__ Thi, bf16* __restrict__ Tlo,
                              int Kd, int Nd)
{
    __shared__ float t[32][33];
    const int tx = threadIdx.x, ty = threadIdx.y;
    const int n0 = blockIdx.x * 32, k0 = blockIdx.y * 32;
#pragma unroll
    for (int j = 0; j < 4; j++)
        t[ty + j * 8][tx] = W[(size_t)(k0 + ty + j * 8) * Nd + n0 + tx];
    __syncthreads();
#pragma unroll
    for (int j = 0; j < 4; j++) {
        float v = t[tx][ty + j * 8];
        bf16 h = __float2bfloat16_rn(v);
        bf16 l = __float2bfloat16_rn(v - __bfloat162float(h));
        size_t idx = (size_t)(n0 + ty + j * 8) * Kd + k0 + tx;
        Thi[idx] = h; Tlo[idx] = l;
    }
}

// ---------------- split-bf16 tensor-core GEMM ----------------
// C[M,N] = A[M,K] @ B[K,N] + bias[N], where A = Ahi+Alo, B^T supplied as [N][K].
// block 128x128, 8 warps (warp tile 32x64), K-step 32, double-buffered cp.async.
#define TSTRIDE 40                       // bf16 elems per smem row (80B, conflict-free ldmatrix)
#define TILE_E  (128 * TSTRIDE)          // 5120 elems per tile
#define STAGE_E (4 * TILE_E)             // Ahi, Alo, Bhi, Blo
#define GEMM_SMEM (2 * STAGE_E * 2)      // bytes: 81920

__global__ __launch_bounds__(256) void hgemm_split_kernel(
    const bf16* __restrict__ Ahi, const bf16* __restrict__ Alo,
    const bf16* __restrict__ Bthi, const bf16* __restrict__ Btlo,
    const float* __restrict__ bias, float* __restrict__ C,
    int M, int N, int K)
{
    extern __shared__ bf16 sm[];
    const int tid = threadIdx.x;
    const int lane = tid & 31, wid = tid >> 5;
    const int wm = wid & 3, wn = wid >> 2;       // 4x2 warp grid
    const int quad = lane >> 3, qr = lane & 7;

    const int lrow = tid >> 1;                   // 0..127
    const int lcc  = (tid & 1) * 2;              // chunk 0/1 or 2/3

    const size_t aBase = (size_t)(blockIdx.y * 128 + lrow) * K;
    const size_t bBase = (size_t)(blockIdx.x * 128 + lrow) * K;

    // preload stage 0
    {
        bf16* st = sm;
#pragma unroll
        for (int c = 0; c < 2; c++) {
            int col = (lcc + c) * 8;
            unsigned so = lrow * TSTRIDE + col;
            CP_ASYNC16(smem_u32(st + so),              Ahi  + aBase + col);
            CP_ASYNC16(smem_u32(st + TILE_E + so),     Alo  + aBase + col);
            CP_ASYNC16(smem_u32(st + 2 * TILE_E + so), Bthi + bBase + col);
            CP_ASYNC16(smem_u32(st + 3 * TILE_E + so), Btlo + bBase + col);
        }
        CP_COMMIT();
    }

    float acc[2][8][4] = {};

    for (int k0 = 0; k0 < K; k0 += 32) {
        const int stg = (k0 >> 5) & 1;
        if (k0 + 32 < K) {
            bf16* st = sm + (stg ^ 1) * STAGE_E;
            int kn = k0 + 32;
#pragma unroll
            for (int c = 0; c < 2; c++) {
                int col = (lcc + c) * 8;
                unsigned so = lrow * TSTRIDE + col;
                CP_ASYNC16(smem_u32(st + so),              Ahi  + aBase + kn + col);
                CP_ASYNC16(smem_u32(st + TILE_E + so),     Alo  + aBase + kn + col);
                CP_ASYNC16(smem_u32(st + 2 * TILE_E + so), Bthi + bBase + kn + col);
                CP_ASYNC16(smem_u32(st + 3 * TILE_E + so), Btlo + bBase + kn + col);
            }
            CP_COMMIT();
            CP_WAIT(1);
        } else {
            CP_WAIT(0);
        }
        __syncthreads();

        const bf16* st = sm + stg * STAGE_E;
#pragma unroll
        for (int kk = 0; kk < 32; kk += 16) {
            unsigned afr[2][2][4];   // [ver][mt][4]
#pragma unroll
            for (int mt = 0; mt < 2; mt++) {
                int arow = wm * 32 + mt * 16 + qr + ((quad & 1) << 3);
                int acol = kk + ((quad >> 1) << 3);
                unsigned off = arow * TSTRIDE + acol;
                ldsm4(afr[0][mt], smem_u32(st + off));
                ldsm4(afr[1][mt], smem_u32(st + TILE_E + off));
            }
#pragma unroll
            for (int np = 0; np < 4; np++) {
                int brow = wn * 64 + np * 16 + qr + ((quad >> 1) << 3);
                int bcol = kk + ((quad & 1) << 3);
                unsigned off = brow * TSTRIDE + bcol;
                unsigned bhi[4], blo[4];
                ldsm4(bhi, smem_u32(st + 2 * TILE_E + off));
                ldsm4(blo, smem_u32(st + 3 * TILE_E + off));
#pragma unroll
                for (int mt = 0; mt < 2; mt++) {
                    float* a0 = acc[mt][np * 2];
                    float* a1 = acc[mt][np * 2 + 1];
                    mma16816(a0, afr[0][mt], bhi);
                    mma16816(a0, afr[0][mt], blo);
                    mma16816(a0, afr[1][mt], bhi);
                    mma16816(a1, afr[0][mt], bhi + 2);
                    mma16816(a1, afr[0][mt], blo + 2);
                    mma16816(a1, afr[1][mt], bhi + 2);
                }
            }
        }
        __syncthreads();
    }

    // epilogue
    const int gr0 = blockIdx.y * 128 + wm * 32 + (lane >> 2);
    const int gc0 = blockIdx.x * 128 + wn * 64 + (lane & 3) * 2;
#pragma unroll
    for (int mt = 0; mt < 2; mt++) {
#pragma unroll
        for (int nt = 0; nt < 8; nt++) {
            int r = gr0 + mt * 16;
            int c = gc0 + nt * 8;
            float b0 = bias[c], b1 = bias[c + 1];
            float2 v0 = make_float2(acc[mt][nt][0] + b0, acc[mt][nt][1] + b1);
            float2 v1 = make_float2(acc[mt][nt][2] + b0, acc[mt][nt][3] + b1);
            *(float2*)(C + (size_t)r * N + c)       = v0;
            *(float2*)(C + (size_t)(r + 8) * N + c) = v1;
        }
    }
}

// ---------------- block mean reprs ----------------
__global__ void repr_kernel(const float* __restrict__ qkv,
                            float* __restrict__ qrepr, float* __restrict__ krepr)
{
    int idx = blockIdx.x * blockDim.x + threadIdx.x;
    int d = idx & 63;
    int n = (idx >> 6) & 63;
    int h = (idx >> 12) & 15;
    int b = idx >> 16;
    const float* base = qkv + ((size_t)(b * L_ + n * BS_)) * TD_ + h * HD_ + d;
    float sq = 0.f, sk = 0.f;
#pragma unroll 8
    for (int s = 0; s < BS_; s++) {
        sq += base[(size_t)s * TD_];
        sk += base[(size_t)s * TD_ + D_];
    }
    qrepr[idx] = sq * (1.0f / BS_);
    krepr[idx] = sk * (1.0f / BS_);
}

// ---------------- sinkhorn -> P ----------------
__global__ __launch_bounds__(256) void sinkhorn_kernel(
    const float* __restrict__ qrepr, const float* __restrict__ krepr,
    const float* __restrict__ gumbel, float* __restrict__ P)
{
    __shared__ float La[64][65];
    const int bh = blockIdx.x;
    const int tid = threadIdx.x;
    const float* qr = qrepr + bh * NB_ * HD_;
    const float* kr = krepr + bh * NB_ * HD_;

    for (int e = tid; e < NB_ * NB_; e += 256) {
        int nn = e >> 6, m = e & 63;
        float s = 0.f;
#pragma unroll 16
        for (int d = 0; d < HD_; d++) s += qr[nn * HD_ + d] * kr[m * HD_ + d];
        La[nn][m] = (s * SCALE_ + gumbel[bh * NB_ * NB_ + e]) * (1.0f / TEMP_);
    }
    __syncthreads();

    for (int it = 0; it < 7; it++) {
        if (tid < 64) {
            float mx = -1e30f;
            for (int m = 0; m < 64; m++) mx = fmaxf(mx, La[tid][m]);
            float se = 0.f;
            for (int m = 0; m < 64; m++) se += expf(La[tid][m] - mx);
            float ls = mx + logf(se);
            for (int m = 0; m < 64; m++) La[tid][m] -= ls;
        }
        __syncthreads();
        if (tid < 64) {
            float mx = -1e30f;
            for (int r = 0; r < 64; r++) mx = fmaxf(mx, La[r][tid]);
            float se = 0.f;
            for (int r = 0; r < 64; r++) se += expf(La[r][tid] - mx);
            float ls = mx + logf(se);
            for (int r = 0; r < 64; r++) La[r][tid] -= ls;
        }
        __syncthreads();
    }
    for (int e = tid; e < NB_ * NB_; e += 256)
        P[bh * NB_ * NB_ + e] = expf(La[e >> 6][e & 63]);
}

// ---------------- k/v soft permutation ----------------
__global__ __launch_bounds__(256) void sort_kernel(
    const float* __restrict__ qkv, const float* __restrict__ P,
    float* __restrict__ ksort, float* __restrict__ vsort)
{
    const int bh = blockIdx.x;
    const int b = bh >> 4, h = bh & 15;
    const int f = blockIdx.y * 256 + threadIdx.x;
    const int s = f >> 6, d = f & 63;

    __shared__ float Ps[64][64];
    for (int e = threadIdx.x; e < 4096; e += 256)
        Ps[e >> 6][e & 63] = P[bh * 4096 + e];
    __syncthreads();

    const float* base = qkv + ((size_t)(b * L_ + s)) * TD_ + h * HD_ + d;
    float km[64], vm[64];
#pragma unroll
    for (int m = 0; m < 64; m++) {
        const float* p = base + (size_t)m * BS_ * TD_;
        km[m] = p[D_];
        vm[m] = p[2 * D_];
    }
    const size_t obase = (size_t)bh * NB_ * BS_ * HD_ + f;
    for (int n2 = 0; n2 < 64; n2++) {
        float sk = 0.f, sv = 0.f;
#pragma unroll
        for (int m = 0; m < 64; m++) {
            sk += Ps[n2][m] * km[m];
            sv += Ps[n2][m] * vm[m];
        }
        ksort[obase + (size_t)n2 * BS_ * HD_] = sk;
        vsort[obase + (size_t)n2 * BS_ * HD_] = sv;
    }
}

// ---------------- block attention (epilogue writes bf16 hi/lo) ----------------
#define ATTN_SMEM ((64*68 + 64*132 + 128*64 + 128*68) * 4)
__global__ __launch_bounds__(256) void attn_kernel(
    const float* __restrict__ qkv, const float* __restrict__ ksort,
    const float* __restrict__ vsort,
    bf16* __restrict__ athi, bf16* __restrict__ atlo)
{
    extern __shared__ float smf[];
    float* Qt  = smf;
    float* Kt  = Qt + 64 * 68;
    float* Vs  = Kt + 64 * 132;
    float* Sct = Vs + 128 * 64;

    const int blk = blockIdx.x;
    const int n2 = blk & 63;
    const int h = (blk >> 6) & 15;
    const int b = blk >> 10;
    const int bh = b * H_ + h;
    const int tid = threadIdx.x;
    const int nn = (n2 + 1) & 63;

    const float* qbase   = qkv + ((size_t)(b * L_ + n2 * BS_)) * TD_ + h * HD_;
    const float* nbase_k = ksort + ((size_t)(bh * NB_ + nn)) * BS_ * HD_;
    const float* nbase_v = vsort + ((size_t)(bh * NB_ + nn)) * BS_ * HD_;

    for (int i4 = tid; i4 < 1024; i4 += 256) {
        int s  = i4 >> 4;
        int d4 = (i4 & 15) << 2;
        float4 qv = *(const float4*)(qbase + (size_t)s * TD_ + d4);
        float4 kv = *(const float4*)(qbase + (size_t)s * TD_ + D_ + d4);
        float4 vv = *(const float4*)(qbase + (size_t)s * TD_ + 2 * D_ + d4);
        float4 kn = *(const float4*)(nbase_k + s * HD_ + d4);
        float4 vn = *(const float4*)(nbase_v + s * HD_ + d4);
        Qt[(d4 + 0) * 68 + s] = qv.x;  Qt[(d4 + 1) * 68 + s] = qv.y;
        Qt[(d4 + 2) * 68 + s] = qv.z;  Qt[(d4 + 3) * 68 + s] = qv.w;
        Kt[(d4 + 0) * 132 + s] = kv.x; Kt[(d4 + 1) * 132 + s] = kv.y;
        Kt[(d4 + 2) * 132 + s] = kv.z; Kt[(d4 + 3) * 132 + s] = kv.w;
        Kt[(d4 + 0) * 132 + 64 + s] = kn.x; Kt[(d4 + 1) * 132 + 64 + s] = kn.y;
        Kt[(d4 + 2) * 132 + 64 + s] = kn.z; Kt[(d4 + 3) * 132 + 64 + s] = kn.w;
        *(float4*)(Vs + s * 64 + d4)        = vv;
        *(float4*)(Vs + (64 + s) * 64 + d4) = vn;
    }
    __syncthreads();

    const int ts = tid >> 4, tc = tid & 15;
    const int s0 = ts * 4, j0 = tc * 8;
    {
        float acc[4][8] = {};
#pragma unroll 16
        for (int d = 0; d < 64; d++) {
            float4 q4  = *(float4*)(Qt + d * 68 + s0);
            float4 k4a = *(float4*)(Kt + d * 132 + j0);
            float4 k4b = *(float4*)(Kt + d * 132 + j0 + 4);
            float qs[4] = {q4.x, q4.y, q4.z, q4.w};
            float ks[8] = {k4a.x, k4a.y, k4a.z, k4a.w, k4b.x, k4b.y, k4b.z, k4b.w};
#pragma unroll
            for (int i = 0; i < 4; i++)
#pragma unroll
                for (int j = 0; j < 8; j++)
                    acc[i][j] += qs[i] * ks[j];
        }
        const bool lastblk = (n2 == NB_ - 1);
#pragma unroll
        for (int i = 0; i < 4; i++)
#pragma unroll
            for (int j = 0; j < 8; j++) {
                float v = acc[i][j] * SCALE_;
                if (lastblk && (j0 + j) >= 64) v = -1e9f;
                Sct[(j0 + j) * 68 + (s0 + i)] = v;
            }
    }
    __syncthreads();

    if (tid < 64) {
        const int s = tid;
        float mx = -1e30f;
        for (int j = 0; j < 128; j++) mx = fmaxf(mx, Sct[j * 68 + s]);
        float se = 0.f;
        for (int j = 0; j < 128; j++) se += expf(Sct[j * 68 + s] - mx);
        float inv = 1.0f / se;
        for (int j = 0; j < 128; j++)
            Sct[j * 68 + s] = expf(Sct[j * 68 + s] - mx) * inv;
    }
    __syncthreads();

    const int d0 = (tid & 15) * 4;
    float oacc[4][4] = {};
#pragma unroll 8
    for (int j = 0; j < 128; j++) {
        float4 p4 = *(float4*)(Sct + j * 68 + s0);
        float4 v4 = *(float4*)(Vs + j * 64 + d0);
        float ps[4] = {p4.x, p4.y, p4.z, p4.w};
        float vs[4] = {v4.x, v4.y, v4.z, v4.w};
#pragma unroll
        for (int i = 0; i < 4; i++)
#pragma unroll
            for (int k = 0; k < 4; k++)
                oacc[i][k] += ps[i] * vs[k];
    }
    const size_t ob = ((size_t)(b * L_ + n2 * BS_)) * D_ + h * HD_ + d0;
#pragma unroll
    for (int i = 0; i < 4; i++) {
        __nv_bfloat162 hv[2], lv[2];
#pragma unroll
        for (int p = 0; p < 2; p++) {
            float v0 = oacc[i][p * 2], v1 = oacc[i][p * 2 + 1];
            bf16 h0 = __float2bfloat16_rn(v0), h1 = __float2bfloat16_rn(v1);
            hv[p] = __nv_bfloat162(h0, h1);
            lv[p] = __nv_bfloat162(__float2bfloat16_rn(v0 - __bfloat162float(h0)),
                                   __float2bfloat16_rn(v1 - __bfloat162float(h1)));
        }
        size_t o = ob + (size_t)(s0 + i) * D_;
        *(__nv_bfloat162*)(athi + o)     = hv[0];
        *(__nv_bfloat162*)(athi + o + 2) = hv[1];
        *(__nv_bfloat162*)(atlo + o)     = lv[0];
        *(__nv_bfloat162*)(atlo + o + 2) = lv[1];
    }
}

// ---------------- launch ----------------
extern "C" void kernel_launch(void* const* d_in, const int* in_sizes, int n_in,
                              void* d_out, int out_size)
{
    const float* x      = (const float*)d_in[0];
    const float* gumbel = (const float*)d_in[1];
    const float* W_qkv  = (const float*)d_in[2];
    const float* b_qkv  = (const float*)d_in[3];
    const float* W_out  = (const float*)d_in[4];
    const float* b_out  = (const float*)d_in[5];
    float* out = (float*)d_out;

    float *qkv, *qr, *kr, *P, *ks, *vs;
    bf16 *xhi, *xlo, *w1hi, *w1lo, *w2hi, *w2lo, *athi, *atlo;
    cudaGetSymbolAddress((void**)&qkv, g_qkv);
    cudaGetSymbolAddress((void**)&qr,  g_qrepr);
    cudaGetSymbolAddress((void**)&kr,  g_krepr);
    cudaGetSymbolAddress((void**)&P,   g_P);
    cudaGetSymbolAddress((void**)&ks,  g_ksort);
    cudaGetSymbolAddress((void**)&vs,  g_vsort);
    cudaGetSymbolAddress((void**)&xhi, g_xhi);
    cudaGetSymbolAddress((void**)&xlo, g_xlo);
    cudaGetSymbolAddress((void**)&w1hi, g_w1hi);
    cudaGetSymbolAddress((void**)&w1lo, g_w1lo);
    cudaGetSymbolAddress((void**)&w2hi, g_w2hi);
    cudaGetSymbolAddress((void**)&w2lo, g_w2lo);
    cudaGetSymbolAddress((void**)&athi, g_athi);
    cudaGetSymbolAddress((void**)&atlo, g_atlo);

    cudaFuncSetAttribute(attn_kernel,
                         cudaFuncAttributeMaxDynamicSharedMemorySize, ATTN_SMEM);
    cudaFuncSetAttribute(hgemm_split_kernel,
                         cudaFuncAttributeMaxDynamicSharedMemorySize, GEMM_SMEM);

    // conversions
    split_kernel<<<(M_ * D_ / 4 + 255) / 256, 256>>>(x, xhi, xlo, M_ * D_ / 4);
    wsplit_kernel<<<dim3(TD_ / 32, D_ / 32), dim3(32, 8)>>>(W_qkv, w1hi, w1lo, D_, TD_);
    wsplit_kernel<<<dim3(D_ / 32, D_ / 32), dim3(32, 8)>>>(W_out, w2hi, w2lo, D_, D_);

    // 1) qkv = x @ W_qkv + b_qkv   (tensor cores)
    hgemm_split_kernel<<<dim3(TD_ / 128, M_ / 128), 256, GEMM_SMEM>>>(
        xhi, xlo, w1hi, w1lo, b_qkv, qkv, M_, TD_, D_);

    // 2) block mean reprs
    repr_kernel<<<(B_ * H_ * NB_ * HD_) / 256, 256>>>(qkv, qr, kr);

    // 3) sinkhorn -> P
    sinkhorn_kernel<<<B_ * H_, 256>>>(qr, kr, gumbel, P);

    // 4) soft-permute K/V blocks
    sort_kernel<<<dim3(B_ * H_, (BS_ * HD_) / 256), 256>>>(qkv, P, ks, vs);

    // 5) block attention -> bf16 hi/lo
    attn_kernel<<<B_ * H_ * NB_, 256, ATTN_SMEM>>>(qkv, ks, vs, athi, atlo);

    // 6) out = attn @ W_out + b_out  (tensor cores)
    hgemm_split_kernel<<<dim3(D_ / 128, M_ / 128), 256, GEMM_SMEM>>>(
        athi, atlo, w2hi, w2lo, b_out, out, M_, D_, D_);
}

// round 4
// speedup vs baseline: 1.8312x; 1.0045x over previous
#include <cuda_runtime.h>
#include <cuda_bf16.h>
#include <cstdint>

// ---------------- problem constants ----------------
#define B_   4
#define L_   4096
#define D_   1024
#define H_   16
#define BS_  64
#define HD_  64
#define NB_  64
#define TD_  3072           // 3*D
#define M_   (B_*L_)        // 16384
#define SCALE_ 0.125f       // HD^-0.5
#define TEMP_  0.7f

typedef __nv_bfloat16 bf16;

// ---------------- device scratch (allocation-free) ----------------
__device__ float g_qkv  [B_*L_*TD_];            // 192 MB fp32
__device__ float g_qrepr[B_*H_*NB_*HD_];
__device__ float g_krepr[B_*H_*NB_*HD_];
__device__ float g_P    [B_*H_*NB_*NB_];
__device__ float g_ksort[B_*H_*NB_*BS_*HD_];    // 64 MB
__device__ float g_vsort[B_*H_*NB_*BS_*HD_];    // 64 MB
__device__ bf16  g_xhi  [M_*D_];
__device__ bf16  g_xlo  [M_*D_];
__device__ bf16  g_w1hi [TD_*D_];               // W_qkv^T hi  [3072][1024]
__device__ bf16  g_w1lo [TD_*D_];
__device__ bf16  g_w2hi [D_*D_];                // W_out^T
__device__ bf16  g_w2lo [D_*D_];
__device__ bf16  g_athi [M_*D_];                // attn out hi
__device__ bf16  g_atlo [M_*D_];

// ---------------- PTX helpers ----------------
__device__ __forceinline__ unsigned smem_u32(const void* p) {
    return (unsigned)__cvta_generic_to_shared(p);
}
__device__ __forceinline__ void ldsm4(unsigned* r, unsigned addr) {
    asm volatile("ldmatrix.sync.aligned.m8n8.x4.shared.b16 {%0,%1,%2,%3}, [%4];\n"
                 : "=r"(r[0]), "=r"(r[1]), "=r"(r[2]), "=r"(r[3]) : "r"(addr));
}
__device__ __forceinline__ void mma16816(float* c, const unsigned* a, const unsigned* b) {
    asm volatile(
        "mma.sync.aligned.m16n8k16.row.col.f32.bf16.bf16.f32 "
        "{%0,%1,%2,%3}, {%4,%5,%6,%7}, {%8,%9}, {%0,%1,%2,%3};\n"
        : "+f"(c[0]), "+f"(c[1]), "+f"(c[2]), "+f"(c[3])
        : "r"(a[0]), "r"(a[1]), "r"(a[2]), "r"(a[3]), "r"(b[0]), "r"(b[1]));
}
#define CP_ASYNC16(dst, src) \
    asm volatile("cp.async.cg.shared.global [%0], [%1], 16;\n" :: "r"(dst), "l"(src))
#define CP_COMMIT() asm volatile("cp.async.commit_group;\n")
#define CP_WAIT(n)  asm volatile("cp.async.wait_group %0;\n" :: "n"(n))

// ---------------- split-bf16 tensor-core GEMM (mma.sync path) ----------------
// C[M,N] = (Ahi+Alo)[M,K] @ (Bhi+Blo)[K,N] + bias[N]; B^T supplied as [N][K].
// block 128x128, 8 warps (warp tile 32x64), K-step 32, double-buffered cp.async.
#define TSTRIDE 40                       // bf16 per smem row (80B, conflict-free ldmatrix)
#define TILE_E  (128 * TSTRIDE)          // 5120 elems per tile
#define STAGE_E (4 * TILE_E)             // Ahi, Alo, Bhi, Blo
#define GEMM_SMEM (2 * STAGE_E * 2)      // bytes: 81920

__global__ __launch_bounds__(256, 2) void hgemm_split_kernel(
    const bf16* __restrict__ Ahi, const bf16* __restrict__ Alo,
    const bf16* __restrict__ Bthi, const bf16* __restrict__ Btlo,
    const float* __restrict__ bias, float* __restrict__ C,
    int M, int N, int K)
{
    extern __shared__ bf16 sm[];
    const int tid = threadIdx.x;
    const int lane = tid & 31, wid = tid >> 5;
    const int wm = wid & 3, wn = wid >> 2;       // 4x2 warp grid
    const int quad = lane >> 3, qr = lane & 7;

    const int lrow = tid >> 1;                   // 0..127
    const int lcc  = (tid & 1) * 2;              // chunk 0/1 or 2/3

    const size_t aBase = (size_t)(blockIdx.y * 128 + lrow) * K;
    const size_t bBase = (size_t)(blockIdx.x * 128 + lrow) * K;

    // preload stage 0
    {
        bf16* st = sm;
#pragma unroll
        for (int c = 0; c < 2; c++) {
            int col = (lcc + c) * 8;
            unsigned so = lrow * TSTRIDE + col;
            CP_ASYNC16(smem_u32(st + so),              Ahi  + aBase + col);
            CP_ASYNC16(smem_u32(st + TILE_E + so),     Alo  + aBase + col);
            CP_ASYNC16(smem_u32(st + 2 * TILE_E + so), Bthi + bBase + col);
            CP_ASYNC16(smem_u32(st + 3 * TILE_E + so), Btlo + bBase + col);
        }
        CP_COMMIT();
    }

    float acc[2][8][4] = {};

    for (int k0 = 0; k0 < K; k0 += 32) {
        const int stg = (k0 >> 5) & 1;
        if (k0 + 32 < K) {
            bf16* st = sm + (stg ^ 1) * STAGE_E;
            int kn = k0 + 32;
#pragma unroll
            for (int c = 0; c < 2; c++) {
                int col = (lcc + c) * 8;
                unsigned so = lrow * TSTRIDE + col;
                CP_ASYNC16(smem_u32(st + so),              Ahi  + aBase + kn + col);
                CP_ASYNC16(smem_u32(st + TILE_E + so),     Alo  + aBase + kn + col);
                CP_ASYNC16(smem_u32(st + 2 * TILE_E + so), Bthi + bBase + kn + col);
                CP_ASYNC16(smem_u32(st + 3 * TILE_E + so), Btlo + bBase + kn + col);
            }
            CP_COMMIT();
            CP_WAIT(1);
        } else {
            CP_WAIT(0);
        }
        __syncthreads();

        const bf16* st = sm + stg * STAGE_E;
#pragma unroll
        for (int kk = 0; kk < 32; kk += 16) {
            // A fragments: [ver][mt]
            unsigned afr[2][2][4];
#pragma unroll
            for (int mt = 0; mt < 2; mt++) {
                int arow = wm * 32 + mt * 16 + qr + ((quad & 1) << 3);
                int acol = kk + ((quad >> 1) << 3);
                unsigned off = arow * TSTRIDE + acol;
                ldsm4(afr[0][mt], smem_u32(st + off));
                ldsm4(afr[1][mt], smem_u32(st + TILE_E + off));
            }
#pragma unroll
            for (int np = 0; np < 4; np++) {
                int brow = wn * 64 + np * 16 + qr + ((quad >> 1) << 3);
                int bcol = kk + ((quad & 1) << 3);
                unsigned off = brow * TSTRIDE + bcol;
                unsigned bhi[4], blo[4];
                ldsm4(bhi, smem_u32(st + 2 * TILE_E + off));
                ldsm4(blo, smem_u32(st + 3 * TILE_E + off));
                float* a00 = acc[0][np * 2];
                float* a01 = acc[0][np * 2 + 1];
                float* a10 = acc[1][np * 2];
                float* a11 = acc[1][np * 2 + 1];
                // term-ordered: consecutive MMAs rotate over 4 independent
                // accumulators -> RAW distance 4 instead of 1
                mma16816(a00, afr[0][0], bhi);
                mma16816(a01, afr[0][0], bhi + 2);
                mma16816(a10, afr[0][1], bhi);
                mma16816(a11, afr[0][1], bhi + 2);

                mma16816(a00, afr[0][0], blo);
                mma16816(a01, afr[0][0], blo + 2);
                mma16816(a10, afr[0][1], blo);
                mma16816(a11, afr[0][1], blo + 2);

                mma16816(a00, afr[1][0], bhi);
                mma16816(a01, afr[1][0], bhi + 2);
                mma16816(a10, afr[1][1], bhi);
                mma16816(a11, afr[1][1], bhi + 2);
            }
        }
        __syncthreads();
    }

    // epilogue
    const int gr0 = blockIdx.y * 128 + wm * 32 + (lane >> 2);
    const int gc0 = blockIdx.x * 128 + wn * 64 + (lane & 3) * 2;
#pragma unroll
    for (int mt = 0; mt < 2; mt++) {
#pragma unroll
        for (int nt = 0; nt < 8; nt++) {
            int r = gr0 + mt * 16;
            int c = gc0 + nt * 8;
            float b0 = bias[c], b1 = bias[c + 1];
            float2 v0 = make_float2(acc[mt][nt][0] + b0, acc[mt][nt][1] + b1);
            float2 v1 = make_float2(acc[mt][nt][2] + b0, acc[mt][nt][3] + b1);
            *(float2*)(C + (size_t)r * N + c)       = v0;
            *(float2*)(C + (size_t)(r + 8) * N + c) = v1;
        }
    }
}

// ---------------- split conversion: f32 -> bf16 hi + lo ----------------
__global__ void split_kernel(const float* __restrict__ src,
                             bf16* __restrict__ hi, bf16* __restrict__ lo, int n4)
{
    int i = blockIdx.x * blockDim.x + threadIdx.x;
    if (i >= n4) return;
    float4 v = ((const float4*)src)[i];
    bf16 h0 = __float2bfloat16_rn(v.x), h1 = __float2bfloat16_rn(v.y);
    bf16 h2 = __float2bfloat16_rn(v.z), h3 = __float2bfloat16_rn(v.w);
    bf16 l0 = __float2bfloat16_rn(v.x - __bfloat162float(h0));
    bf16 l1 = __float2bfloat16_rn(v.y - __bfloat162float(h1));
    bf16 l2 = __float2bfloat16_rn(v.z - __bfloat162float(h2));
    bf16 l3 = __float2bfloat16_rn(v.w - __bfloat162float(h3));
    __nv_bfloat162* hp = (__nv_bfloat162*)(hi + i * 4);
    __nv_bfloat162* lp = (__nv_bfloat162*)(lo + i * 4);
    hp[0] = __nv_bfloat162(h0, h1); hp[1] = __nv_bfloat162(h2, h3);
    lp[0] = __nv_bfloat162(l0, l1); lp[1] = __nv_bfloat162(l2, l3);
}

// ---------------- transpose + split: W[K][N] -> T[N][K] hi/lo ----------------
__global__ void wsplit_kernel(const float* __restrict__ W,
                              bf16* __restrict__ Thi, bf16* __restrict__ Tlo,
                              int Kd, int Nd)
{
    __shared__ float t[32][33];
    const int tx = threadIdx.x, ty = threadIdx.y;
    const int n0 = blockIdx.x * 32, k0 = blockIdx.y * 32;
#pragma unroll
    for (int j = 0; j < 4; j++)
        t[ty + j * 8][tx] = W[(size_t)(k0 + ty + j * 8) * Nd + n0 + tx];
    __syncthreads();
#pragma unroll
    for (int j = 0; j < 4; j++) {
        float v = t[tx][ty + j * 8];
        bf16 h = __float2bfloat16_rn(v);
        bf16 l = __float2bfloat16_rn(v - __bfloat162float(h));
        size_t idx = (size_t)(n0 + ty + j * 8) * Kd + k0 + tx;
        Thi[idx] = h; Tlo[idx] = l;
    }
}

// ---------------- block mean reprs ----------------
__global__ void repr_kernel(const float* __restrict__ qkv,
                            float* __restrict__ qrepr, float* __restrict__ krepr)
{
    int idx = blockIdx.x * blockDim.x + threadIdx.x;
    int d = idx & 63;
    int n = (idx >> 6) & 63;
    int h = (idx >> 12) & 15;
    int b = idx >> 16;
    const float* base = qkv + ((size_t)(b * L_ + n * BS_)) * TD_ + h * HD_ + d;
    float sq = 0.f, sk = 0.f;
#pragma unroll 8
    for (int s = 0; s < BS_; s++) {
        sq += base[(size_t)s * TD_];
        sk += base[(size_t)s * TD_ + D_];
    }
    qrepr[idx] = sq * (1.0f / BS_);
    krepr[idx] = sk * (1.0f / BS_);
}

// ---------------- sinkhorn -> P ----------------
__global__ __launch_bounds__(256) void sinkhorn_kernel(
    const float* __restrict__ qrepr, const float* __restrict__ krepr,
    const float* __restrict__ gumbel, float* __restrict__ P)
{
    __shared__ float La[64][65];
    const int bh = blockIdx.x;
    const int tid = threadIdx.x;
    const float* qr = qrepr + bh * NB_ * HD_;
    const float* kr = krepr + bh * NB_ * HD_;

    for (int e = tid; e < NB_ * NB_; e += 256) {
        int nn = e >> 6, m = e & 63;
        float s = 0.f;
#pragma unroll 16
        for (int d = 0; d < HD_; d++) s += qr[nn * HD_ + d] * kr[m * HD_ + d];
        La[nn][m] = (s * SCALE_ + gumbel[bh * NB_ * NB_ + e]) * (1.0f / TEMP_);
    }
    __syncthreads();

    for (int it = 0; it < 7; it++) {
        if (tid < 64) {
            float mx = -1e30f;
            for (int m = 0; m < 64; m++) mx = fmaxf(mx, La[tid][m]);
            float se = 0.f;
            for (int m = 0; m < 64; m++) se += expf(La[tid][m] - mx);
            float ls = mx + logf(se);
            for (int m = 0; m < 64; m++) La[tid][m] -= ls;
        }
        __syncthreads();
        if (tid < 64) {
            float mx = -1e30f;
            for (int r = 0; r < 64; r++) mx = fmaxf(mx, La[r][tid]);
            float se = 0.f;
            for (int r = 0; r < 64; r++) se += expf(La[r][tid] - mx);
            float ls = mx + logf(se);
            for (int r = 0; r < 64; r++) La[r][tid] -= ls;
        }
        __syncthreads();
    }
    for (int e = tid; e < NB_ * NB_; e += 256)
        P[bh * NB_ * NB_ + e] = expf(La[e >> 6][e & 63]);
}

// ---------------- k/v soft permutation, split passes (no spills) ----------------
// grid (B*H, 16, 2); z=0 -> k, z=1 -> v
__global__ __launch_bounds__(256) void sortkv_kernel(
    const float* __restrict__ qkv, const float* __restrict__ P,
    float* __restrict__ ksort, float* __restrict__ vsort)
{
    const int bh = blockIdx.x;
    const int b = bh >> 4, h = bh & 15;
    const int f = blockIdx.y * 256 + threadIdx.x;
    const int s = f >> 6, d = f & 63;
    const int which = blockIdx.z;

    __shared__ float Ps[64][64];
    for (int e = threadIdx.x; e < 4096; e += 256)
        Ps[e >> 6][e & 63] = P[bh * 4096 + e];
    __syncthreads();

    const float* base = qkv + ((size_t)(b * L_ + s)) * TD_ + h * HD_ + d
                        + (which ? 2 * D_ : D_);
    float xm[64];
#pragma unroll
    for (int m = 0; m < 64; m++)
        xm[m] = base[(size_t)m * BS_ * TD_];

    float* dst = which ? vsort : ksort;
    const size_t obase = (size_t)bh * NB_ * BS_ * HD_ + f;
    for (int n2 = 0; n2 < 64; n2++) {
        float acc = 0.f;
#pragma unroll
        for (int m = 0; m < 64; m++) acc += Ps[n2][m] * xm[m];
        dst[obase + (size_t)n2 * BS_ * HD_] = acc;
    }
}

// ---------------- block attention (epilogue writes bf16 hi/lo) ----------------
#define ATTN_SMEM ((64*68 + 64*132 + 128*64 + 128*68) * 4)
__global__ __launch_bounds__(256) void attn_kernel(
    const float* __restrict__ qkv, const float* __restrict__ ksort,
    const float* __restrict__ vsort,
    bf16* __restrict__ athi, bf16* __restrict__ atlo)
{
    extern __shared__ float smf[];
    float* Qt  = smf;
    float* Kt  = Qt + 64 * 68;
    float* Vs  = Kt + 64 * 132;
    float* Sct = Vs + 128 * 64;

    const int blk = blockIdx.x;
    const int n2 = blk & 63;
    const int h = (blk >> 6) & 15;
    const int b = blk >> 10;
    const int bh = b * H_ + h;
    const int tid = threadIdx.x;
    const int nn = (n2 + 1) & 63;

    const float* qbase   = qkv + ((size_t)(b * L_ + n2 * BS_)) * TD_ + h * HD_;
    const float* nbase_k = ksort + ((size_t)(bh * NB_ + nn)) * BS_ * HD_;
    const float* nbase_v = vsort + ((size_t)(bh * NB_ + nn)) * BS_ * HD_;

    for (int i4 = tid; i4 < 1024; i4 += 256) {
        int s  = i4 >> 4;
        int d4 = (i4 & 15) << 2;
        float4 qv = *(const float4*)(qbase + (size_t)s * TD_ + d4);
        float4 kv = *(const float4*)(qbase + (size_t)s * TD_ + D_ + d4);
        float4 vv = *(const float4*)(qbase + (size_t)s * TD_ + 2 * D_ + d4);
        float4 kn = *(const float4*)(nbase_k + s * HD_ + d4);
        float4 vn = *(const float4*)(nbase_v + s * HD_ + d4);
        Qt[(d4 + 0) * 68 + s] = qv.x;  Qt[(d4 + 1) * 68 + s] = qv.y;
        Qt[(d4 + 2) * 68 + s] = qv.z;  Qt[(d4 + 3) * 68 + s] = qv.w;
        Kt[(d4 + 0) * 132 + s] = kv.x; Kt[(d4 + 1) * 132 + s] = kv.y;
        Kt[(d4 + 2) * 132 + s] = kv.z; Kt[(d4 + 3) * 132 + s] = kv.w;
        Kt[(d4 + 0) * 132 + 64 + s] = kn.x; Kt[(d4 + 1) * 132 + 64 + s] = kn.y;
        Kt[(d4 + 2) * 132 + 64 + s] = kn.z; Kt[(d4 + 3) * 132 + 64 + s] = kn.w;
        *(float4*)(Vs + s * 64 + d4)        = vv;
        *(float4*)(Vs + (64 + s) * 64 + d4) = vn;
    }
    __syncthreads();

    const int ts = tid >> 4, tc = tid & 15;
    const int s0 = ts * 4, j0 = tc * 8;
    {
        float acc[4][8] = {};
#pragma unroll 16
        for (int d = 0; d < 64; d++) {
            float4 q4  = *(float4*)(Qt + d * 68 + s0);
            float4 k4a = *(float4*)(Kt + d * 132 + j0);
            float4 k4b = *(float4*)(Kt + d * 132 + j0 + 4);
            float qs[4] = {q4.x, q4.y, q4.z, q4.w};
            float ks[8] = {k4a.x, k4a.y, k4a.z, k4a.w, k4b.x, k4b.y, k4b.z, k4b.w};
#pragma unroll
            for (int i = 0; i < 4; i++)
#pragma unroll
                for (int j = 0; j < 8; j++)
                    acc[i][j] += qs[i] * ks[j];
        }
        const bool lastblk = (n2 == NB_ - 1);
#pragma unroll
        for (int i = 0; i < 4; i++)
#pragma unroll
            for (int j = 0; j < 8; j++) {
                float v = acc[i][j] * SCALE_;
                if (lastblk && (j0 + j) >= 64) v = -1e9f;
                Sct[(j0 + j) * 68 + (s0 + i)] = v;
            }
    }
    __syncthreads();

    if (tid < 64) {
        const int s = tid;
        float mx = -1e30f;
        for (int j = 0; j < 128; j++) mx = fmaxf(mx, Sct[j * 68 + s]);
        float se = 0.f;
        for (int j = 0; j < 128; j++) se += expf(Sct[j * 68 + s] - mx);
        float inv = 1.0f / se;
        for (int j = 0; j < 128; j++)
            Sct[j * 68 + s] = expf(Sct[j * 68 + s] - mx) * inv;
    }
    __syncthreads();

    const int d0 = (tid & 15) * 4;
    float oacc[4][4] = {};
#pragma unroll 8
    for (int j = 0; j < 128; j++) {
        float4 p4 = *(float4*)(Sct + j * 68 + s0);
        float4 v4 = *(float4*)(Vs + j * 64 + d0);
        float ps[4] = {p4.x, p4.y, p4.z, p4.w};
        float vs[4] = {v4.x, v4.y, v4.z, v4.w};
#pragma unroll
        for (int i = 0; i < 4; i++)
#pragma unroll
            for (int k = 0; k < 4; k++)
                oacc[i][k] += ps[i] * vs[k];
    }
    const size_t ob = ((size_t)(b * L_ + n2 * BS_)) * D_ + h * HD_ + d0;
#pragma unroll
    for (int i = 0; i < 4; i++) {
        __nv_bfloat162 hv[2], lv[2];
#pragma unroll
        for (int p = 0; p < 2; p++) {
            float v0 = oacc[i][p * 2], v1 = oacc[i][p * 2 + 1];
            bf16 h0 = __float2bfloat16_rn(v0), h1 = __float2bfloat16_rn(v1);
            hv[p] = __nv_bfloat162(h0, h1);
            lv[p] = __nv_bfloat162(__float2bfloat16_rn(v0 - __bfloat162float(h0)),
                                   __float2bfloat16_rn(v1 - __bfloat162float(h1)));
        }
        size_t o = ob + (size_t)(s0 + i) * D_;
        *(__nv_bfloat162*)(athi + o)     = hv[0];
        *(__nv_bfloat162*)(athi + o + 2) = hv[1];
        *(__nv_bfloat162*)(atlo + o)     = lv[0];
        *(__nv_bfloat162*)(atlo + o + 2) = lv[1];
    }
}

// ---------------- launch ----------------
extern "C" void kernel_launch(void* const* d_in, const int* in_sizes, int n_in,
                              void* d_out, int out_size)
{
    const float* x      = (const float*)d_in[0];
    const float* gumbel = (const float*)d_in[1];
    const float* W_qkv  = (const float*)d_in[2];
    const float* b_qkv  = (const float*)d_in[3];
    const float* W_out  = (const float*)d_in[4];
    const float* b_out  = (const float*)d_in[5];
    float* out = (float*)d_out;

    float *qkv, *qr, *kr, *P, *ks, *vs;
    bf16 *xhi, *xlo, *w1hi, *w1lo, *w2hi, *w2lo, *athi, *atlo;
    cudaGetSymbolAddress((void**)&qkv, g_qkv);
    cudaGetSymbolAddress((void**)&qr,  g_qrepr);
    cudaGetSymbolAddress((void**)&kr,  g_krepr);
    cudaGetSymbolAddress((void**)&P,   g_P);
    cudaGetSymbolAddress((void**)&ks,  g_ksort);
    cudaGetSymbolAddress((void**)&vs,  g_vsort);
    cudaGetSymbolAddress((void**)&xhi, g_xhi);
    cudaGetSymbolAddress((void**)&xlo, g_xlo);
    cudaGetSymbolAddress((void**)&w1hi, g_w1hi);
    cudaGetSymbolAddress((void**)&w1lo, g_w1lo);
    cudaGetSymbolAddress((void**)&w2hi, g_w2hi);
    cudaGetSymbolAddress((void**)&w2lo, g_w2lo);
    cudaGetSymbolAddress((void**)&athi, g_athi);
    cudaGetSymbolAddress((void**)&atlo, g_atlo);

    cudaFuncSetAttribute(attn_kernel,
                         cudaFuncAttributeMaxDynamicSharedMemorySize, ATTN_SMEM);
    cudaFuncSetAttribute(hgemm_split_kernel,
                         cudaFuncAttributeMaxDynamicSharedMemorySize, GEMM_SMEM);

    // conversions
    split_kernel<<<(M_ * D_ / 4 + 255) / 256, 256>>>(x, xhi, xlo, M_ * D_ / 4);
    wsplit_kernel<<<dim3(TD_ / 32, D_ / 32), dim3(32, 8)>>>(W_qkv, w1hi, w1lo, D_, TD_);
    wsplit_kernel<<<dim3(D_ / 32, D_ / 32), dim3(32, 8)>>>(W_out, w2hi, w2lo, D_, D_);

    // 1) qkv = x @ W_qkv + b_qkv   (tensor cores)
    hgemm_split_kernel<<<dim3(TD_ / 128, M_ / 128), 256, GEMM_SMEM>>>(
        xhi, xlo, w1hi, w1lo, b_qkv, qkv, M_, TD_, D_);

    // 2) block mean reprs
    repr_kernel<<<(B_ * H_ * NB_ * HD_) / 256, 256>>>(qkv, qr, kr);

    // 3) sinkhorn -> P
    sinkhorn_kernel<<<B_ * H_, 256>>>(qr, kr, gumbel, P);

    // 4) soft-permute K/V blocks (split passes, no spills)
    sortkv_kernel<<<dim3(B_ * H_, (BS_ * HD_) / 256, 2), 256>>>(qkv, P, ks, vs);

    // 5) block attention -> bf16 hi/lo
    attn_kernel<<<B_ * H_ * NB_, 256, ATTN_SMEM>>>(qkv, ks, vs, athi, atlo);

    // 6) out = attn @ W_out + b_out  (tensor cores)
    hgemm_split_kernel<<<dim3(D_ / 128, M_ / 128), 256, GEMM_SMEM>>>(
        athi, atlo, w2hi, w2lo, b_out, out, M_, D_, D_);
}

// round 5
// speedup vs baseline: 1.9239x; 1.0506x over previous
#include <cuda_runtime.h>
#include <cuda_bf16.h>
#include <cstdint>

// ---------------- problem constants ----------------
#define B_   4
#define L_   4096
#define D_   1024
#define H_   16
#define BS_  64
#define HD_  64
#define NB_  64
#define TD_  3072           // 3*D
#define M_   (B_*L_)        // 16384
#define SCALE_ 0.125f       // HD^-0.5
#define TEMP_  0.7f

typedef __nv_bfloat16 bf16;

// ---------------- device scratch (allocation-free) ----------------
__device__ float g_qkv  [B_*L_*TD_];            // 192 MB fp32
__device__ float g_qrepr[B_*H_*NB_*HD_];
__device__ float g_krepr[B_*H_*NB_*HD_];
__device__ float g_P    [B_*H_*NB_*NB_];
__device__ float g_ksort[B_*H_*NB_*BS_*HD_];    // 64 MB
__device__ float g_vsort[B_*H_*NB_*BS_*HD_];    // 64 MB
__device__ bf16  g_xhi  [M_*D_];
__device__ bf16  g_xlo  [M_*D_];
__device__ bf16  g_w1hi [TD_*D_];               // W_qkv^T hi  [3072][1024]
__device__ bf16  g_w1lo [TD_*D_];
__device__ bf16  g_w2hi [D_*D_];                // W_out^T
__device__ bf16  g_w2lo [D_*D_];
__device__ bf16  g_athi [M_*D_];                // attn out hi
__device__ bf16  g_atlo [M_*D_];

// ---------------- PTX helpers ----------------
__device__ __forceinline__ unsigned smem_u32(const void* p) {
    return (unsigned)__cvta_generic_to_shared(p);
}
__device__ __forceinline__ void ldsm4(unsigned* r, unsigned addr) {
    asm volatile("ldmatrix.sync.aligned.m8n8.x4.shared.b16 {%0,%1,%2,%3}, [%4];\n"
                 : "=r"(r[0]), "=r"(r[1]), "=r"(r[2]), "=r"(r[3]) : "r"(addr));
}
__device__ __forceinline__ void mma16816(float* c, const unsigned* a, const unsigned* b) {
    asm volatile(
        "mma.sync.aligned.m16n8k16.row.col.f32.bf16.bf16.f32 "
        "{%0,%1,%2,%3}, {%4,%5,%6,%7}, {%8,%9}, {%0,%1,%2,%3};\n"
        : "+f"(c[0]), "+f"(c[1]), "+f"(c[2]), "+f"(c[3])
        : "r"(a[0]), "r"(a[1]), "r"(a[2]), "r"(a[3]), "r"(b[0]), "r"(b[1]));
}
#define CP_ASYNC16(dst, src) \
    asm volatile("cp.async.cg.shared.global [%0], [%1], 16;\n" :: "r"(dst), "l"(src))
#define CP_COMMIT() asm volatile("cp.async.commit_group;\n")
#define CP_WAIT(n)  asm volatile("cp.async.wait_group %0;\n" :: "n"(n))

// ---------------- split-bf16 tensor-core GEMM (mma.sync) ----------------
// C[M,N] = (Ahi+Alo)[M,K] @ (Bhi+Blo)[K,N] + bias[N]; B^T supplied as [N][K].
// Block tile 128x256, 8 warps (2x4), warp tile 64x64, K-step 32,
// 3-stage cp.async pipeline, one __syncthreads per chunk.
#define TSTRIDE 40                         // bf16 per smem row (80B)
#define SA_HI   0
#define SA_LO   (128 * TSTRIDE)            // 5120
#define SB_HI   (256 * TSTRIDE)            // 10240
#define SB_LO   (SB_HI + 256 * TSTRIDE)    // 20480
#define STG_E   (SB_LO + 256 * TSTRIDE)    // 30720 elems / stage
#define NSTG    3
#define GEMM_SMEM (NSTG * STG_E * 2)       // 184320 bytes

__global__ __launch_bounds__(256, 1) void hgemm_split_kernel(
    const bf16* __restrict__ Ahi, const bf16* __restrict__ Alo,
    const bf16* __restrict__ Bthi, const bf16* __restrict__ Btlo,
    const float* __restrict__ bias, float* __restrict__ C,
    int M, int N, int K)
{
    extern __shared__ bf16 sm[];
    const uint32_t smb = smem_u32(sm);
    const int tid = threadIdx.x;
    const int lane = tid & 31, wid = tid >> 5;
    const int wm = wid & 1, wn = wid >> 1;       // 2x4 warp grid
    const int quad = lane >> 3, qr = lane & 7;

    const int aRow0 = blockIdx.y * 128;
    const int bRow0 = blockIdx.x * 256;
    const int nchunks = K >> 5;

    // ---- loader: 3072 x 16B chunks per stage, 12 per thread ----
    auto prefetch = [&](int stg, int k0) {
#pragma unroll
        for (int it = 0; it < 12; it++) {
            int c = tid + it * 256;
            int row = c >> 2;                // 0..767
            int ch  = c & 3;
            const bf16* gsrc;
            unsigned soff;
            if (row < 256) {
                int r = row & 127;
                const bf16* s = (row < 128) ? Ahi : Alo;
                gsrc = s + (size_t)(aRow0 + r) * K + k0 + ch * 8;
                soff = (row < 128 ? SA_HI : SA_LO) + r * TSTRIDE + ch * 8;
            } else {
                int r = (row - 256) & 255;
                const bf16* s = (row < 512) ? Bthi : Btlo;
                gsrc = s + (size_t)(bRow0 + r) * K + k0 + ch * 8;
                soff = (row < 512 ? SB_HI : SB_LO) + r * TSTRIDE + ch * 8;
            }
            CP_ASYNC16(smb + (stg * STG_E + soff) * 2, gsrc);
        }
        CP_COMMIT();
    };

    prefetch(0, 0);
    prefetch(1, 32);

    float acc[4][8][4] = {};
    int sidx = 0, pidx = 2;

    for (int ck = 0; ck < nchunks; ck++) {
        if (ck < nchunks - 1) { CP_WAIT(1); } else { CP_WAIT(0); }
        __syncthreads();

        if (ck + 2 < nchunks) {
            prefetch(pidx, (ck + 2) << 5);
            pidx = (pidx == 2) ? 0 : pidx + 1;
        }

        const bf16* st = sm + sidx * STG_E;
        sidx = (sidx == 2) ? 0 : sidx + 1;
#pragma unroll
        for (int kk = 0; kk < 32; kk += 16) {
            unsigned ahi[4][4], alo[4][4];
#pragma unroll
            for (int mt = 0; mt < 4; mt++) {
                int arow = wm * 64 + mt * 16 + qr + ((quad & 1) << 3);
                int acol = kk + ((quad >> 1) << 3);
                unsigned off = arow * TSTRIDE + acol;
                ldsm4(ahi[mt], smem_u32(st + SA_HI + off));
                ldsm4(alo[mt], smem_u32(st + SA_LO + off));
            }
#pragma unroll
            for (int np = 0; np < 4; np++) {
                int brow = wn * 64 + np * 16 + qr + ((quad >> 1) << 3);
                int bcol = kk + ((quad & 1) << 3);
                unsigned boff = brow * TSTRIDE + bcol;
                unsigned bhi[4], blo[4];
                ldsm4(bhi, smem_u32(st + SB_HI + boff));
                ldsm4(blo, smem_u32(st + SB_LO + boff));
                // term-major: 8 independent accs between reuse of any acc
#pragma unroll
                for (int mt = 0; mt < 4; mt++) {
                    mma16816(acc[mt][np * 2],     ahi[mt], bhi);
                    mma16816(acc[mt][np * 2 + 1], ahi[mt], bhi + 2);
                }
#pragma unroll
                for (int mt = 0; mt < 4; mt++) {
                    mma16816(acc[mt][np * 2],     ahi[mt], blo);
                    mma16816(acc[mt][np * 2 + 1], ahi[mt], blo + 2);
                }
#pragma unroll
                for (int mt = 0; mt < 4; mt++) {
                    mma16816(acc[mt][np * 2],     alo[mt], bhi);
                    mma16816(acc[mt][np * 2 + 1], alo[mt], bhi + 2);
                }
            }
        }
    }

    // epilogue
    const int gr0 = blockIdx.y * 128 + wm * 64 + (lane >> 2);
    const int gc0 = blockIdx.x * 256 + wn * 64 + (lane & 3) * 2;
#pragma unroll
    for (int mt = 0; mt < 4; mt++) {
#pragma unroll
        for (int nt = 0; nt < 8; nt++) {
            int r = gr0 + mt * 16;
            int c = gc0 + nt * 8;
            float b0 = bias[c], b1 = bias[c + 1];
            float2 v0 = make_float2(acc[mt][nt][0] + b0, acc[mt][nt][1] + b1);
            float2 v1 = make_float2(acc[mt][nt][2] + b0, acc[mt][nt][3] + b1);
            *(float2*)(C + (size_t)r * N + c)       = v0;
            *(float2*)(C + (size_t)(r + 8) * N + c) = v1;
        }
    }
}

// ---------------- split conversion: f32 -> bf16 hi + lo ----------------
__global__ void split_kernel(const float* __restrict__ src,
                             bf16* __restrict__ hi, bf16* __restrict__ lo, int n4)
{
    int i = blockIdx.x * blockDim.x + threadIdx.x;
    if (i >= n4) return;
    float4 v = ((const float4*)src)[i];
    bf16 h0 = __float2bfloat16_rn(v.x), h1 = __float2bfloat16_rn(v.y);
    bf16 h2 = __float2bfloat16_rn(v.z), h3 = __float2bfloat16_rn(v.w);
    bf16 l0 = __float2bfloat16_rn(v.x - __bfloat162float(h0));
    bf16 l1 = __float2bfloat16_rn(v.y - __bfloat162float(h1));
    bf16 l2 = __float2bfloat16_rn(v.z - __bfloat162float(h2));
    bf16 l3 = __float2bfloat16_rn(v.w - __bfloat162float(h3));
    __nv_bfloat162* hp = (__nv_bfloat162*)(hi + i * 4);
    __nv_bfloat162* lp = (__nv_bfloat162*)(lo + i * 4);
    hp[0] = __nv_bfloat162(h0, h1); hp[1] = __nv_bfloat162(h2, h3);
    lp[0] = __nv_bfloat162(l0, l1); lp[1] = __nv_bfloat162(l2, l3);
}

// ---------------- transpose + split: W[K][N] -> T[N][K] hi/lo ----------------
__global__ void wsplit_kernel(const float* __restrict__ W,
                              bf16* __restrict__ Thi, bf16* __restrict__ Tlo,
                              int Kd, int Nd)
{
    __shared__ float t[32][33];
    const int tx = threadIdx.x, ty = threadIdx.y;
    const int n0 = blockIdx.x * 32, k0 = blockIdx.y * 32;
#pragma unroll
    for (int j = 0; j < 4; j++)
        t[ty + j * 8][tx] = W[(size_t)(k0 + ty + j * 8) * Nd + n0 + tx];
    __syncthreads();
#pragma unroll
    for (int j = 0; j < 4; j++) {
        float v = t[tx][ty + j * 8];
        bf16 h = __float2bfloat16_rn(v);
        bf16 l = __float2bfloat16_rn(v - __bfloat162float(h));
        size_t idx = (size_t)(n0 + ty + j * 8) * Kd + k0 + tx;
        Thi[idx] = h; Tlo[idx] = l;
    }
}

// ---------------- block mean reprs ----------------
__global__ void repr_kernel(const float* __restrict__ qkv,
                            float* __restrict__ qrepr, float* __restrict__ krepr)
{
    int idx = blockIdx.x * blockDim.x + threadIdx.x;
    int d = idx & 63;
    int n = (idx >> 6) & 63;
    int h = (idx >> 12) & 15;
    int b = idx >> 16;
    const float* base = qkv + ((size_t)(b * L_ + n * BS_)) * TD_ + h * HD_ + d;
    float sq = 0.f, sk = 0.f;
#pragma unroll 8
    for (int s = 0; s < BS_; s++) {
        sq += base[(size_t)s * TD_];
        sk += base[(size_t)s * TD_ + D_];
    }
    qrepr[idx] = sq * (1.0f / BS_);
    krepr[idx] = sk * (1.0f / BS_);
}

// ---------------- sinkhorn -> P ----------------
__global__ __launch_bounds__(256) void sinkhorn_kernel(
    const float* __restrict__ qrepr, const float* __restrict__ krepr,
    const float* __restrict__ gumbel, float* __restrict__ P)
{
    __shared__ float La[64][65];
    const int bh = blockIdx.x;
    const int tid = threadIdx.x;
    const float* qr = qrepr + bh * NB_ * HD_;
    const float* kr = krepr + bh * NB_ * HD_;

    for (int e = tid; e < NB_ * NB_; e += 256) {
        int nn = e >> 6, m = e & 63;
        float s = 0.f;
#pragma unroll 16
        for (int d = 0; d < HD_; d++) s += qr[nn * HD_ + d] * kr[m * HD_ + d];
        La[nn][m] = (s * SCALE_ + gumbel[bh * NB_ * NB_ + e]) * (1.0f / TEMP_);
    }
    __syncthreads();

    for (int it = 0; it < 7; it++) {
        if (tid < 64) {
            float mx = -1e30f;
            for (int m = 0; m < 64; m++) mx = fmaxf(mx, La[tid][m]);
            float se = 0.f;
            for (int m = 0; m < 64; m++) se += expf(La[tid][m] - mx);
            float ls = mx + logf(se);
            for (int m = 0; m < 64; m++) La[tid][m] -= ls;
        }
        __syncthreads();
        if (tid < 64) {
            float mx = -1e30f;
            for (int r = 0; r < 64; r++) mx = fmaxf(mx, La[r][tid]);
            float se = 0.f;
            for (int r = 0; r < 64; r++) se += expf(La[r][tid] - mx);
            float ls = mx + logf(se);
            for (int r = 0; r < 64; r++) La[r][tid] -= ls;
        }
        __syncthreads();
    }
    for (int e = tid; e < NB_ * NB_; e += 256)
        P[bh * NB_ * NB_ + e] = expf(La[e >> 6][e & 63]);
}

// ---------------- k/v soft permutation, split passes (no spills) ----------------
__global__ __launch_bounds__(256) void sortkv_kernel(
    const float* __restrict__ qkv, const float* __restrict__ P,
    float* __restrict__ ksort, float* __restrict__ vsort)
{
    const int bh = blockIdx.x;
    const int b = bh >> 4, h = bh & 15;
    const int f = blockIdx.y * 256 + threadIdx.x;
    const int s = f >> 6, d = f & 63;
    const int which = blockIdx.z;

    __shared__ float Ps[64][64];
    for (int e = threadIdx.x; e < 4096; e += 256)
        Ps[e >> 6][e & 63] = P[bh * 4096 + e];
    __syncthreads();

    const float* base = qkv + ((size_t)(b * L_ + s)) * TD_ + h * HD_ + d
                        + (which ? 2 * D_ : D_);
    float xm[64];
#pragma unroll
    for (int m = 0; m < 64; m++)
        xm[m] = base[(size_t)m * BS_ * TD_];

    float* dst = which ? vsort : ksort;
    const size_t obase = (size_t)bh * NB_ * BS_ * HD_ + f;
    for (int n2 = 0; n2 < 64; n2++) {
        float acc = 0.f;
#pragma unroll
        for (int m = 0; m < 64; m++) acc += Ps[n2][m] * xm[m];
        dst[obase + (size_t)n2 * BS_ * HD_] = acc;
    }
}

// ---------------- block attention (parallel softmax, bf16 hi/lo out) ----------------
#define SCT_STRIDE 72
#define ATTN_SMEM ((64*68 + 64*132 + 128*64 + 128*SCT_STRIDE) * 4)
__global__ __launch_bounds__(256) void attn_kernel(
    const float* __restrict__ qkv, const float* __restrict__ ksort,
    const float* __restrict__ vsort,
    bf16* __restrict__ athi, bf16* __restrict__ atlo)
{
    extern __shared__ float smf[];
    float* Qt  = smf;                 // [64][68]  d-major
    float* Kt  = Qt + 64 * 68;        // [64][132] d-major
    float* Vs  = Kt + 64 * 132;       // [128][64] j-major
    float* Sct = Vs + 128 * 64;       // [128][72] j-major scores/probs

    const int blk = blockIdx.x;
    const int n2 = blk & 63;
    const int h = (blk >> 6) & 15;
    const int b = blk >> 10;
    const int bh = b * H_ + h;
    const int tid = threadIdx.x;
    const int nn = (n2 + 1) & 63;

    const float* qbase   = qkv + ((size_t)(b * L_ + n2 * BS_)) * TD_ + h * HD_;
    const float* nbase_k = ksort + ((size_t)(bh * NB_ + nn)) * BS_ * HD_;
    const float* nbase_v = vsort + ((size_t)(bh * NB_ + nn)) * BS_ * HD_;

    for (int i4 = tid; i4 < 1024; i4 += 256) {
        int s  = i4 >> 4;
        int d4 = (i4 & 15) << 2;
        float4 qv = *(const float4*)(qbase + (size_t)s * TD_ + d4);
        float4 kv = *(const float4*)(qbase + (size_t)s * TD_ + D_ + d4);
        float4 vv = *(const float4*)(qbase + (size_t)s * TD_ + 2 * D_ + d4);
        float4 kn = *(const float4*)(nbase_k + s * HD_ + d4);
        float4 vn = *(const float4*)(nbase_v + s * HD_ + d4);
        Qt[(d4 + 0) * 68 + s] = qv.x;  Qt[(d4 + 1) * 68 + s] = qv.y;
        Qt[(d4 + 2) * 68 + s] = qv.z;  Qt[(d4 + 3) * 68 + s] = qv.w;
        Kt[(d4 + 0) * 132 + s] = kv.x; Kt[(d4 + 1) * 132 + s] = kv.y;
        Kt[(d4 + 2) * 132 + s] = kv.z; Kt[(d4 + 3) * 132 + s] = kv.w;
        Kt[(d4 + 0) * 132 + 64 + s] = kn.x; Kt[(d4 + 1) * 132 + 64 + s] = kn.y;
        Kt[(d4 + 2) * 132 + 64 + s] = kn.z; Kt[(d4 + 3) * 132 + 64 + s] = kn.w;
        *(float4*)(Vs + s * 64 + d4)        = vv;
        *(float4*)(Vs + (64 + s) * 64 + d4) = vn;
    }
    __syncthreads();

    const int ts = tid >> 4, tc = tid & 15;
    const int s0 = ts * 4, j0 = tc * 8;
    {
        float acc[4][8] = {};
#pragma unroll 16
        for (int d = 0; d < 64; d++) {
            float4 q4  = *(float4*)(Qt + d * 68 + s0);
            float4 k4a = *(float4*)(Kt + d * 132 + j0);
            float4 k4b = *(float4*)(Kt + d * 132 + j0 + 4);
            float qs[4] = {q4.x, q4.y, q4.z, q4.w};
            float ks[8] = {k4a.x, k4a.y, k4a.z, k4a.w, k4b.x, k4b.y, k4b.z, k4b.w};
#pragma unroll
            for (int i = 0; i < 4; i++)
#pragma unroll
                for (int j = 0; j < 8; j++)
                    acc[i][j] += qs[i] * ks[j];
        }
        const bool lastblk = (n2 == NB_ - 1);
#pragma unroll
        for (int i = 0; i < 4; i++)
#pragma unroll
            for (int j = 0; j < 8; j++) {
                float v = acc[i][j] * SCALE_;
                if (lastblk && (j0 + j) >= 64) v = -1e9f;
                Sct[(j0 + j) * SCT_STRIDE + (s0 + i)] = v;
            }
    }
    __syncthreads();

    // softmax: 4 threads per query row, interleaved columns (j = 32*jj + qd*4 .. )
    {
        const int sr = tid >> 2;          // row 0..63
        const int qd = tid & 3;           // quarter
        float mx = -1e30f;
#pragma unroll
        for (int jj = 0; jj < 32; jj++) {
            int j = jj * 4 + qd;
            mx = fmaxf(mx, Sct[j * SCT_STRIDE + sr]);
        }
        mx = fmaxf(mx, __shfl_xor_sync(0xffffffffu, mx, 1));
        mx = fmaxf(mx, __shfl_xor_sync(0xffffffffu, mx, 2));
        float se = 0.f;
#pragma unroll
        for (int jj = 0; jj < 32; jj++) {
            int j = jj * 4 + qd;
            float e = __expf(Sct[j * SCT_STRIDE + sr] - mx);
            Sct[j * SCT_STRIDE + sr] = e;
            se += e;
        }
        se += __shfl_xor_sync(0xffffffffu, se, 1);
        se += __shfl_xor_sync(0xffffffffu, se, 2);
        float inv = 1.0f / se;
#pragma unroll
        for (int jj = 0; jj < 32; jj++) {
            int j = jj * 4 + qd;
            Sct[j * SCT_STRIDE + sr] *= inv;
        }
    }
    __syncthreads();

    const int d0 = (tid & 15) * 4;
    float oacc[4][4] = {};
#pragma unroll 8
    for (int j = 0; j < 128; j++) {
        float4 p4 = *(float4*)(Sct + j * SCT_STRIDE + s0);
        float4 v4 = *(float4*)(Vs + j * 64 + d0);
        float ps[4] = {p4.x, p4.y, p4.z, p4.w};
        float vs[4] = {v4.x, v4.y, v4.z, v4.w};
#pragma unroll
        for (int i = 0; i < 4; i++)
#pragma unroll
            for (int k = 0; k < 4; k++)
                oacc[i][k] += ps[i] * vs[k];
    }
    const size_t ob = ((size_t)(b * L_ + n2 * BS_)) * D_ + h * HD_ + d0;
#pragma unroll
    for (int i = 0; i < 4; i++) {
        __nv_bfloat162 hv[2], lv[2];
#pragma unroll
        for (int p = 0; p < 2; p++) {
            float v0 = oacc[i][p * 2], v1 = oacc[i][p * 2 + 1];
            bf16 h0 = __float2bfloat16_rn(v0), h1 = __float2bfloat16_rn(v1);
            hv[p] = __nv_bfloat162(h0, h1);
            lv[p] = __nv_bfloat162(__float2bfloat16_rn(v0 - __bfloat162float(h0)),
                                   __float2bfloat16_rn(v1 - __bfloat162float(h1)));
        }
        size_t o = ob + (size_t)(s0 + i) * D_;
        *(__nv_bfloat162*)(athi + o)     = hv[0];
        *(__nv_bfloat162*)(athi + o + 2) = hv[1];
        *(__nv_bfloat162*)(atlo + o)     = lv[0];
        *(__nv_bfloat162*)(atlo + o + 2) = lv[1];
    }
}

// ---------------- launch ----------------
extern "C" void kernel_launch(void* const* d_in, const int* in_sizes, int n_in,
                              void* d_out, int out_size)
{
    const float* x      = (const float*)d_in[0];
    const float* gumbel = (const float*)d_in[1];
    const float* W_qkv  = (const float*)d_in[2];
    const float* b_qkv  = (const float*)d_in[3];
    const float* W_out  = (const float*)d_in[4];
    const float* b_out  = (const float*)d_in[5];
    float* out = (float*)d_out;

    float *qkv, *qr, *kr, *P, *ks, *vs;
    bf16 *xhi, *xlo, *w1hi, *w1lo, *w2hi, *w2lo, *athi, *atlo;
    cudaGetSymbolAddress((void**)&qkv, g_qkv);
    cudaGetSymbolAddress((void**)&qr,  g_qrepr);
    cudaGetSymbolAddress((void**)&kr,  g_krepr);
    cudaGetSymbolAddress((void**)&P,   g_P);
    cudaGetSymbolAddress((void**)&ks,  g_ksort);
    cudaGetSymbolAddress((void**)&vs,  g_vsort);
    cudaGetSymbolAddress((void**)&xhi, g_xhi);
    cudaGetSymbolAddress((void**)&xlo, g_xlo);
    cudaGetSymbolAddress((void**)&w1hi, g_w1hi);
    cudaGetSymbolAddress((void**)&w1lo, g_w1lo);
    cudaGetSymbolAddress((void**)&w2hi, g_w2hi);
    cudaGetSymbolAddress((void**)&w2lo, g_w2lo);
    cudaGetSymbolAddress((void**)&athi, g_athi);
    cudaGetSymbolAddress((void**)&atlo, g_atlo);

    cudaFuncSetAttribute(attn_kernel,
                         cudaFuncAttributeMaxDynamicSharedMemorySize, ATTN_SMEM);
    cudaFuncSetAttribute(hgemm_split_kernel,
                         cudaFuncAttributeMaxDynamicSharedMemorySize, GEMM_SMEM);

    // conversions
    split_kernel<<<(M_ * D_ / 4 + 255) / 256, 256>>>(x, xhi, xlo, M_ * D_ / 4);
    wsplit_kernel<<<dim3(TD_ / 32, D_ / 32), dim3(32, 8)>>>(W_qkv, w1hi, w1lo, D_, TD_);
    wsplit_kernel<<<dim3(D_ / 32, D_ / 32), dim3(32, 8)>>>(W_out, w2hi, w2lo, D_, D_);

    // 1) qkv = x @ W_qkv + b_qkv   (tensor cores)
    hgemm_split_kernel<<<dim3(TD_ / 256, M_ / 128), 256, GEMM_SMEM>>>(
        xhi, xlo, w1hi, w1lo, b_qkv, qkv, M_, TD_, D_);

    // 2) block mean reprs
    repr_kernel<<<(B_ * H_ * NB_ * HD_) / 256, 256>>>(qkv, qr, kr);

    // 3) sinkhorn -> P
    sinkhorn_kernel<<<B_ * H_, 256>>>(qr, kr, gumbel, P);

    // 4) soft-permute K/V blocks (split passes, no spills)
    sortkv_kernel<<<dim3(B_ * H_, (BS_ * HD_) / 256, 2), 256>>>(qkv, P, ks, vs);

    // 5) block attention -> bf16 hi/lo
    attn_kernel<<<B_ * H_ * NB_, 256, ATTN_SMEM>>>(qkv, ks, vs, athi, atlo);

    // 6) out = attn @ W_out + b_out  (tensor cores)
    hgemm_split_kernel<<<dim3(D_ / 256, M_ / 128), 256, GEMM_SMEM>>>(
        athi, atlo, w2hi, w2lo, b_out, out, M_, D_, D_);
}

// round 6
// speedup vs baseline: 2.0389x; 1.0597x over previous
#include <cuda_runtime.h>
#include <cuda_bf16.h>
#include <cstdint>

// ---------------- problem constants ----------------
#define B_   4
#define L_   4096
#define D_   1024
#define H_   16
#define BS_  64
#define HD_  64
#define NB_  64
#define TD_  3072           // 3*D
#define M_   (B_*L_)        // 16384
#define SCALE_ 0.125f       // HD^-0.5
#define TEMP_  0.7f

typedef __nv_bfloat16 bf16;

// ---------------- device scratch (allocation-free) ----------------
__device__ float g_qkv  [B_*L_*TD_];            // 192 MB fp32
__device__ float g_qrepr[B_*H_*NB_*HD_];
__device__ float g_krepr[B_*H_*NB_*HD_];
__device__ float g_P    [B_*H_*NB_*NB_];
__device__ float g_ksort[B_*H_*NB_*BS_*HD_];    // 64 MB
__device__ float g_vsort[B_*H_*NB_*BS_*HD_];    // 64 MB
__device__ bf16  g_xhi  [M_*D_];
__device__ bf16  g_xlo  [M_*D_];
__device__ bf16  g_w1hi [TD_*D_];               // W_qkv^T hi  [3072][1024]
__device__ bf16  g_w1lo [TD_*D_];
__device__ bf16  g_w2hi [D_*D_];                // W_out^T
__device__ bf16  g_w2lo [D_*D_];
__device__ bf16  g_athi [M_*D_];                // attn out hi
__device__ bf16  g_atlo [M_*D_];

// ---------------- PTX helpers ----------------
__device__ __forceinline__ unsigned smem_u32(const void* p) {
    return (unsigned)__cvta_generic_to_shared(p);
}
__device__ __forceinline__ void ldsm4(unsigned* r, unsigned addr) {
    asm volatile("ldmatrix.sync.aligned.m8n8.x4.shared.b16 {%0,%1,%2,%3}, [%4];\n"
                 : "=r"(r[0]), "=r"(r[1]), "=r"(r[2]), "=r"(r[3]) : "r"(addr));
}
__device__ __forceinline__ void mma16816(float* c, const unsigned* a, const unsigned* b) {
    asm volatile(
        "mma.sync.aligned.m16n8k16.row.col.f32.bf16.bf16.f32 "
        "{%0,%1,%2,%3}, {%4,%5,%6,%7}, {%8,%9}, {%0,%1,%2,%3};\n"
        : "+f"(c[0]), "+f"(c[1]), "+f"(c[2]), "+f"(c[3])
        : "r"(a[0]), "r"(a[1]), "r"(a[2]), "r"(a[3]), "r"(b[0]), "r"(b[1]));
}
#define CP_ASYNC16(dst, src) \
    asm volatile("cp.async.cg.shared.global [%0], [%1], 16;\n" :: "r"(dst), "l"(src))
#define CP_COMMIT() asm volatile("cp.async.commit_group;\n")
#define CP_WAIT(n)  asm volatile("cp.async.wait_group %0;\n" :: "n"(n))

// ---------------- split-bf16 tensor-core GEMM (mma.sync) ----------------
#define TSTRIDE 40
#define SA_HI   0
#define SA_LO   (128 * TSTRIDE)
#define SB_HI   (256 * TSTRIDE)
#define SB_LO   (SB_HI + 256 * TSTRIDE)
#define STG_E   (SB_LO + 256 * TSTRIDE)
#define NSTG    3
#define GEMM_SMEM (NSTG * STG_E * 2)

__global__ __launch_bounds__(256, 1) void hgemm_split_kernel(
    const bf16* __restrict__ Ahi, const bf16* __restrict__ Alo,
    const bf16* __restrict__ Bthi, const bf16* __restrict__ Btlo,
    const float* __restrict__ bias, float* __restrict__ C,
    int M, int N, int K)
{
    extern __shared__ bf16 sm[];
    const uint32_t smb = smem_u32(sm);
    const int tid = threadIdx.x;
    const int lane = tid & 31, wid = tid >> 5;
    const int wm = wid & 1, wn = wid >> 1;
    const int quad = lane >> 3, qr = lane & 7;

    const int aRow0 = blockIdx.y * 128;
    const int bRow0 = blockIdx.x * 256;
    const int nchunks = K >> 5;

    auto prefetch = [&](int stg, int k0) {
#pragma unroll
        for (int it = 0; it < 12; it++) {
            int c = tid + it * 256;
            int row = c >> 2;
            int ch  = c & 3;
            const bf16* gsrc;
            unsigned soff;
            if (row < 256) {
                int r = row & 127;
                const bf16* s = (row < 128) ? Ahi : Alo;
                gsrc = s + (size_t)(aRow0 + r) * K + k0 + ch * 8;
                soff = (row < 128 ? SA_HI : SA_LO) + r * TSTRIDE + ch * 8;
            } else {
                int r = (row - 256) & 255;
                const bf16* s = (row < 512) ? Bthi : Btlo;
                gsrc = s + (size_t)(bRow0 + r) * K + k0 + ch * 8;
                soff = (row < 512 ? SB_HI : SB_LO) + r * TSTRIDE + ch * 8;
            }
            CP_ASYNC16(smb + (stg * STG_E + soff) * 2, gsrc);
        }
        CP_COMMIT();
    };

    prefetch(0, 0);
    prefetch(1, 32);

    float acc[4][8][4] = {};
    int sidx = 0, pidx = 2;

    for (int ck = 0; ck < nchunks; ck++) {
        if (ck < nchunks - 1) { CP_WAIT(1); } else { CP_WAIT(0); }
        __syncthreads();

        if (ck + 2 < nchunks) {
            prefetch(pidx, (ck + 2) << 5);
            pidx = (pidx == 2) ? 0 : pidx + 1;
        }

        const bf16* st = sm + sidx * STG_E;
        sidx = (sidx == 2) ? 0 : sidx + 1;
#pragma unroll
        for (int kk = 0; kk < 32; kk += 16) {
            unsigned ahi[4][4], alo[4][4];
#pragma unroll
            for (int mt = 0; mt < 4; mt++) {
                int arow = wm * 64 + mt * 16 + qr + ((quad & 1) << 3);
                int acol = kk + ((quad >> 1) << 3);
                unsigned off = arow * TSTRIDE + acol;
                ldsm4(ahi[mt], smem_u32(st + SA_HI + off));
                ldsm4(alo[mt], smem_u32(st + SA_LO + off));
            }
#pragma unroll
            for (int np = 0; np < 4; np++) {
                int brow = wn * 64 + np * 16 + qr + ((quad >> 1) << 3);
                int bcol = kk + ((quad & 1) << 3);
                unsigned boff = brow * TSTRIDE + bcol;
                unsigned bhi[4], blo[4];
                ldsm4(bhi, smem_u32(st + SB_HI + boff));
                ldsm4(blo, smem_u32(st + SB_LO + boff));
#pragma unroll
                for (int mt = 0; mt < 4; mt++) {
                    mma16816(acc[mt][np * 2],     ahi[mt], bhi);
                    mma16816(acc[mt][np * 2 + 1], ahi[mt], bhi + 2);
                }
#pragma unroll
                for (int mt = 0; mt < 4; mt++) {
                    mma16816(acc[mt][np * 2],     ahi[mt], blo);
                    mma16816(acc[mt][np * 2 + 1], ahi[mt], blo + 2);
                }
#pragma unroll
                for (int mt = 0; mt < 4; mt++) {
                    mma16816(acc[mt][np * 2],     alo[mt], bhi);
                    mma16816(acc[mt][np * 2 + 1], alo[mt], bhi + 2);
                }
            }
        }
    }

    const int gr0 = blockIdx.y * 128 + wm * 64 + (lane >> 2);
    const int gc0 = blockIdx.x * 256 + wn * 64 + (lane & 3) * 2;
#pragma unroll
    for (int mt = 0; mt < 4; mt++) {
#pragma unroll
        for (int nt = 0; nt < 8; nt++) {
            int r = gr0 + mt * 16;
            int c = gc0 + nt * 8;
            float b0 = bias[c], b1 = bias[c + 1];
            float2 v0 = make_float2(acc[mt][nt][0] + b0, acc[mt][nt][1] + b1);
            float2 v1 = make_float2(acc[mt][nt][2] + b0, acc[mt][nt][3] + b1);
            *(float2*)(C + (size_t)r * N + c)       = v0;
            *(float2*)(C + (size_t)(r + 8) * N + c) = v1;
        }
    }
}

// ---------------- split conversion: f32 -> bf16 hi + lo ----------------
__global__ void split_kernel(const float* __restrict__ src,
                             bf16* __restrict__ hi, bf16* __restrict__ lo, int n4)
{
    int i = blockIdx.x * blockDim.x + threadIdx.x;
    if (i >= n4) return;
    float4 v = ((const float4*)src)[i];
    bf16 h0 = __float2bfloat16_rn(v.x), h1 = __float2bfloat16_rn(v.y);
    bf16 h2 = __float2bfloat16_rn(v.z), h3 = __float2bfloat16_rn(v.w);
    bf16 l0 = __float2bfloat16_rn(v.x - __bfloat162float(h0));
    bf16 l1 = __float2bfloat16_rn(v.y - __bfloat162float(h1));
    bf16 l2 = __float2bfloat16_rn(v.z - __bfloat162float(h2));
    bf16 l3 = __float2bfloat16_rn(v.w - __bfloat162float(h3));
    __nv_bfloat162* hp = (__nv_bfloat162*)(hi + i * 4);
    __nv_bfloat162* lp = (__nv_bfloat162*)(lo + i * 4);
    hp[0] = __nv_bfloat162(h0, h1); hp[1] = __nv_bfloat162(h2, h3);
    lp[0] = __nv_bfloat162(l0, l1); lp[1] = __nv_bfloat162(l2, l3);
}

// ---------------- transpose + split: W[K][N] -> T[N][K] hi/lo ----------------
__global__ void wsplit_kernel(const float* __restrict__ W,
                              bf16* __restrict__ Thi, bf16* __restrict__ Tlo,
                              int Kd, int Nd)
{
    __shared__ float t[32][33];
    const int tx = threadIdx.x, ty = threadIdx.y;
    const int n0 = blockIdx.x * 32, k0 = blockIdx.y * 32;
#pragma unroll
    for (int j = 0; j < 4; j++)
        t[ty + j * 8][tx] = W[(size_t)(k0 + ty + j * 8) * Nd + n0 + tx];
    __syncthreads();
#pragma unroll
    for (int j = 0; j < 4; j++) {
        float v = t[tx][ty + j * 8];
        bf16 h = __float2bfloat16_rn(v);
        bf16 l = __float2bfloat16_rn(v - __bfloat162float(h));
        size_t idx = (size_t)(n0 + ty + j * 8) * Kd + k0 + tx;
        Thi[idx] = h; Tlo[idx] = l;
    }
}

// ---------------- block mean reprs ----------------
__global__ void repr_kernel(const float* __restrict__ qkv,
                            float* __restrict__ qrepr, float* __restrict__ krepr)
{
    int idx = blockIdx.x * blockDim.x + threadIdx.x;
    int d = idx & 63;
    int n = (idx >> 6) & 63;
    int h = (idx >> 12) & 15;
    int b = idx >> 16;
    const float* base = qkv + ((size_t)(b * L_ + n * BS_)) * TD_ + h * HD_ + d;
    float sq = 0.f, sk = 0.f;
#pragma unroll 8
    for (int s = 0; s < BS_; s++) {
        sq += base[(size_t)s * TD_];
        sk += base[(size_t)s * TD_ + D_];
    }
    qrepr[idx] = sq * (1.0f / BS_);
    krepr[idx] = sk * (1.0f / BS_);
}

// ---------------- sinkhorn -> P ----------------
__global__ __launch_bounds__(256) void sinkhorn_kernel(
    const float* __restrict__ qrepr, const float* __restrict__ krepr,
    const float* __restrict__ gumbel, float* __restrict__ P)
{
    __shared__ float La[64][65];
    const int bh = blockIdx.x;
    const int tid = threadIdx.x;
    const float* qr = qrepr + bh * NB_ * HD_;
    const float* kr = krepr + bh * NB_ * HD_;

    for (int e = tid; e < NB_ * NB_; e += 256) {
        int nn = e >> 6, m = e & 63;
        float s = 0.f;
#pragma unroll 16
        for (int d = 0; d < HD_; d++) s += qr[nn * HD_ + d] * kr[m * HD_ + d];
        La[nn][m] = (s * SCALE_ + gumbel[bh * NB_ * NB_ + e]) * (1.0f / TEMP_);
    }
    __syncthreads();

    for (int it = 0; it < 7; it++) {
        if (tid < 64) {
            float mx = -1e30f;
            for (int m = 0; m < 64; m++) mx = fmaxf(mx, La[tid][m]);
            float se = 0.f;
            for (int m = 0; m < 64; m++) se += expf(La[tid][m] - mx);
            float ls = mx + logf(se);
            for (int m = 0; m < 64; m++) La[tid][m] -= ls;
        }
        __syncthreads();
        if (tid < 64) {
            float mx = -1e30f;
            for (int r = 0; r < 64; r++) mx = fmaxf(mx, La[r][tid]);
            float se = 0.f;
            for (int r = 0; r < 64; r++) se += expf(La[r][tid] - mx);
            float ls = mx + logf(se);
            for (int r = 0; r < 64; r++) La[r][tid] -= ls;
        }
        __syncthreads();
    }
    for (int e = tid; e < NB_ * NB_; e += 256)
        P[bh * NB_ * NB_ + e] = expf(La[e >> 6][e & 63]);
}

// ---------------- k/v soft permutation, split passes ----------------
__global__ __launch_bounds__(256) void sortkv_kernel(
    const float* __restrict__ qkv, const float* __restrict__ P,
    float* __restrict__ ksort, float* __restrict__ vsort)
{
    const int bh = blockIdx.x;
    const int b = bh >> 4, h = bh & 15;
    const int f = blockIdx.y * 256 + threadIdx.x;
    const int s = f >> 6, d = f & 63;
    const int which = blockIdx.z;

    __shared__ float Ps[64][64];
    for (int e = threadIdx.x; e < 4096; e += 256)
        Ps[e >> 6][e & 63] = P[bh * 4096 + e];
    __syncthreads();

    const float* base = qkv + ((size_t)(b * L_ + s)) * TD_ + h * HD_ + d
                        + (which ? 2 * D_ : D_);
    float xm[64];
#pragma unroll
    for (int m = 0; m < 64; m++)
        xm[m] = base[(size_t)m * BS_ * TD_];

    float* dst = which ? vsort : ksort;
    const size_t obase = (size_t)bh * NB_ * BS_ * HD_ + f;
    for (int n2 = 0; n2 < 64; n2++) {
        float acc = 0.f;
#pragma unroll
        for (int m = 0; m < 64; m++) acc += Ps[n2][m] * xm[m];
        dst[obase + (size_t)n2 * BS_ * HD_] = acc;
    }
}

// ---------------- tensor-core block attention ----------------
// Per block: Q[64,64] x K[128,64]^T -> softmax -> P[64,128] x V[128,64].
// All operands bf16 hi/lo split, 3-term mma.sync; softmax in fp32 smem.
#define AQ_STR 72
#define AK_STR 72
#define AV_STR 136
#define AP_STR 136
#define O_SQH  0
#define O_SQL  9216
#define O_SKH  18432
#define O_SKL  36864
#define O_SVTH 55296
#define O_SVTL 72704
#define O_SPH  90112
#define O_SPL  107520
#define O_SCT  124928
#define ATTN_SMEM (O_SCT + 128 * 72 * 4)    // 161792 bytes

__global__ __launch_bounds__(256) void attn_kernel(
    const float* __restrict__ qkv, const float* __restrict__ ksort,
    const float* __restrict__ vsort,
    bf16* __restrict__ athi, bf16* __restrict__ atlo)
{
    extern __shared__ __align__(16) char smc[];
    bf16* SQH = (bf16*)(smc + O_SQH);     // [64][72]  s-major (A, scores)
    bf16* SQL = (bf16*)(smc + O_SQL);
    bf16* SKH = (bf16*)(smc + O_SKH);     // [128][72] j-major (B, scores)
    bf16* SKL = (bf16*)(smc + O_SKL);
    bf16* SVTH = (bf16*)(smc + O_SVTH);   // [64][136] d-major (B, PV) = V^T
    bf16* SVTL = (bf16*)(smc + O_SVTL);
    bf16* SPH = (bf16*)(smc + O_SPH);     // [64][136] s-major (A, PV)
    bf16* SPL = (bf16*)(smc + O_SPL);
    float* SCT = (float*)(smc + O_SCT);   // [128][72] j-major scores

    const int blk = blockIdx.x;
    const int n2 = blk & 63;
    const int h = (blk >> 6) & 15;
    const int b = blk >> 10;
    const int bh = b * H_ + h;
    const int tid = threadIdx.x;
    const int lane = tid & 31, wid = tid >> 5;
    const int quad = lane >> 3, qr = lane & 7;
    const int nn = (n2 + 1) & 63;

    const float* qbase   = qkv + ((size_t)(b * L_ + n2 * BS_)) * TD_ + h * HD_;
    const float* nbase_k = ksort + ((size_t)(bh * NB_ + nn)) * BS_ * HD_;
    const float* nbase_v = vsort + ((size_t)(bh * NB_ + nn)) * BS_ * HD_;

    // ---- load + split q,k,v,kn,vn into bf16 hi/lo smem ----
    for (int i4 = tid; i4 < 1024; i4 += 256) {
        int s  = i4 >> 4;           // 0..63
        int d4 = (i4 & 15) << 2;    // 0..60
        float4 qv = *(const float4*)(qbase + (size_t)s * TD_ + d4);
        float4 kv = *(const float4*)(qbase + (size_t)s * TD_ + D_ + d4);
        float4 vv = *(const float4*)(qbase + (size_t)s * TD_ + 2 * D_ + d4);
        float4 kn = *(const float4*)(nbase_k + s * HD_ + d4);
        float4 vn = *(const float4*)(nbase_v + s * HD_ + d4);
        float qa[4] = {qv.x, qv.y, qv.z, qv.w};
        float ka[4] = {kv.x, kv.y, kv.z, kv.w};
        float va[4] = {vv.x, vv.y, vv.z, vv.w};
        float kna[4] = {kn.x, kn.y, kn.z, kn.w};
        float vna[4] = {vn.x, vn.y, vn.z, vn.w};
#pragma unroll
        for (int t = 0; t < 4; t++) {
            bf16 hq = __float2bfloat16_rn(qa[t]);
            SQH[s * AQ_STR + d4 + t] = hq;
            SQL[s * AQ_STR + d4 + t] = __float2bfloat16_rn(qa[t] - __bfloat162float(hq));
            bf16 hk = __float2bfloat16_rn(ka[t]);
            SKH[s * AK_STR + d4 + t] = hk;
            SKL[s * AK_STR + d4 + t] = __float2bfloat16_rn(ka[t] - __bfloat162float(hk));
            bf16 hkn = __float2bfloat16_rn(kna[t]);
            SKH[(64 + s) * AK_STR + d4 + t] = hkn;
            SKL[(64 + s) * AK_STR + d4 + t] = __float2bfloat16_rn(kna[t] - __bfloat162float(hkn));
            bf16 hv = __float2bfloat16_rn(va[t]);
            SVTH[(d4 + t) * AV_STR + s] = hv;
            SVTL[(d4 + t) * AV_STR + s] = __float2bfloat16_rn(va[t] - __bfloat162float(hv));
            bf16 hvn = __float2bfloat16_rn(vna[t]);
            SVTH[(d4 + t) * AV_STR + 64 + s] = hvn;
            SVTL[(d4 + t) * AV_STR + 64 + s] = __float2bfloat16_rn(vna[t] - __bfloat162float(hvn));
        }
    }
    __syncthreads();

    // ---- scores via mma: warp tile 16(s) x 64(j) ----
    {
        const int wm = wid & 3, wn = wid >> 2;
        float sacc[8][4] = {};
#pragma unroll
        for (int k16 = 0; k16 < 64; k16 += 16) {
            unsigned aoff = (wm * 16 + qr + ((quad & 1) << 3)) * AQ_STR
                            + k16 + ((quad >> 1) << 3);
            unsigned aH[4], aL[4];
            ldsm4(aH, smem_u32(SQH + aoff));
            ldsm4(aL, smem_u32(SQL + aoff));
#pragma unroll
            for (int nt = 0; nt < 4; nt++) {
                unsigned boff = (wn * 64 + nt * 16 + qr + ((quad >> 1) << 3)) * AK_STR
                                + k16 + ((quad & 1) << 3);
                unsigned bH[4], bL[4];
                ldsm4(bH, smem_u32(SKH + boff));
                ldsm4(bL, smem_u32(SKL + boff));
                mma16816(sacc[nt * 2],     aH, bH);
                mma16816(sacc[nt * 2 + 1], aH, bH + 2);
                mma16816(sacc[nt * 2],     aH, bL);
                mma16816(sacc[nt * 2 + 1], aH, bL + 2);
                mma16816(sacc[nt * 2],     aL, bH);
                mma16816(sacc[nt * 2 + 1], aL, bH + 2);
            }
        }
        const bool maskme = (n2 == NB_ - 1) && (wn == 1);
        const int srow = wm * 16 + (lane >> 2);
#pragma unroll
        for (int p = 0; p < 8; p++) {
            int j0 = wn * 64 + (p >> 1) * 16 + (p & 1) * 8 + (lane & 3) * 2;
            float c0 = sacc[p][0] * SCALE_, c1 = sacc[p][1] * SCALE_;
            float c2 = sacc[p][2] * SCALE_, c3 = sacc[p][3] * SCALE_;
            if (maskme) { c0 = c1 = c2 = c3 = -1e9f; }
            SCT[j0 * 72 + srow]           = c0;
            SCT[(j0 + 1) * 72 + srow]     = c1;
            SCT[j0 * 72 + srow + 8]       = c2;
            SCT[(j0 + 1) * 72 + srow + 8] = c3;
        }
    }
    __syncthreads();

    // ---- softmax: 4 threads per query row ----
    {
        const int sr = tid >> 2;
        const int qd = tid & 3;
        float mx = -1e30f;
#pragma unroll
        for (int jj = 0; jj < 32; jj++) {
            int j = jj * 4 + qd;
            mx = fmaxf(mx, SCT[j * 72 + sr]);
        }
        mx = fmaxf(mx, __shfl_xor_sync(0xffffffffu, mx, 1));
        mx = fmaxf(mx, __shfl_xor_sync(0xffffffffu, mx, 2));
        float se = 0.f;
#pragma unroll
        for (int jj = 0; jj < 32; jj++) {
            int j = jj * 4 + qd;
            float e = __expf(SCT[j * 72 + sr] - mx);
            SCT[j * 72 + sr] = e;
            se += e;
        }
        se += __shfl_xor_sync(0xffffffffu, se, 1);
        se += __shfl_xor_sync(0xffffffffu, se, 2);
        float inv = 1.0f / se;
#pragma unroll
        for (int jj = 0; jj < 32; jj++) {
            int j = jj * 4 + qd;
            SCT[j * 72 + sr] *= inv;
        }
    }
    __syncthreads();

    // ---- split probs to bf16 hi/lo (A operand for PV) ----
    for (int i = tid; i < 8192; i += 256) {
        int s = i & 63, j = i >> 6;
        float p = SCT[j * 72 + s];
        bf16 hp = __float2bfloat16_rn(p);
        SPH[s * AP_STR + j] = hp;
        SPL[s * AP_STR + j] = __float2bfloat16_rn(p - __bfloat162float(hp));
    }
    __syncthreads();

    // ---- PV via mma: warp tile 16(s) x 32(d) ----
    {
        const int wm = wid & 3, wn = wid >> 2;
        float oacc[4][4] = {};
#pragma unroll
        for (int k16 = 0; k16 < 128; k16 += 16) {
            unsigned poff = (wm * 16 + qr + ((quad & 1) << 3)) * AP_STR
                            + k16 + ((quad >> 1) << 3);
            unsigned pH[4], pL[4];
            ldsm4(pH, smem_u32(SPH + poff));
            ldsm4(pL, smem_u32(SPL + poff));
#pragma unroll
            for (int nt = 0; nt < 2; nt++) {
                unsigned voff = (wn * 32 + nt * 16 + qr + ((quad >> 1) << 3)) * AV_STR
                                + k16 + ((quad & 1) << 3);
                unsigned vH[4], vL[4];
                ldsm4(vH, smem_u32(SVTH + voff));
                ldsm4(vL, smem_u32(SVTL + voff));
                mma16816(oacc[nt * 2],     pH, vH);
                mma16816(oacc[nt * 2 + 1], pH, vH + 2);
                mma16816(oacc[nt * 2],     pH, vL);
                mma16816(oacc[nt * 2 + 1], pH, vL + 2);
                mma16816(oacc[nt * 2],     pL, vH);
                mma16816(oacc[nt * 2 + 1], pL, vH + 2);
            }
        }
        // epilogue: split to bf16 hi/lo and store
        const int srow = wm * 16 + (lane >> 2);
        const size_t obase = ((size_t)(b * L_ + n2 * BS_)) * D_ + h * HD_;
#pragma unroll
        for (int p = 0; p < 4; p++) {
            int d0 = wn * 32 + (p >> 1) * 16 + (p & 1) * 8 + (lane & 3) * 2;
#pragma unroll
            for (int rr = 0; rr < 2; rr++) {
                float v0 = oacc[p][rr * 2], v1 = oacc[p][rr * 2 + 1];
                bf16 h0 = __float2bfloat16_rn(v0), h1 = __float2bfloat16_rn(v1);
                __nv_bfloat162 hv(h0, h1);
                __nv_bfloat162 lv(__float2bfloat16_rn(v0 - __bfloat162float(h0)),
                                  __float2bfloat16_rn(v1 - __bfloat162float(h1)));
                size_t o = obase + (size_t)(srow + rr * 8) * D_ + d0;
                *(__nv_bfloat162*)(athi + o) = hv;
                *(__nv_bfloat162*)(atlo + o) = lv;
            }
        }
    }
}

// ---------------- launch ----------------
extern "C" void kernel_launch(void* const* d_in, const int* in_sizes, int n_in,
                              void* d_out, int out_size)
{
    const float* x      = (const float*)d_in[0];
    const float* gumbel = (const float*)d_in[1];
    const float* W_qkv  = (const float*)d_in[2];
    const float* b_qkv  = (const float*)d_in[3];
    const float* W_out  = (const float*)d_in[4];
    const float* b_out  = (const float*)d_in[5];
    float* out = (float*)d_out;

    float *qkv, *qr, *kr, *P, *ks, *vs;
    bf16 *xhi, *xlo, *w1hi, *w1lo, *w2hi, *w2lo, *athi, *atlo;
    cudaGetSymbolAddress((void**)&qkv, g_qkv);
    cudaGetSymbolAddress((void**)&qr,  g_qrepr);
    cudaGetSymbolAddress((void**)&kr,  g_krepr);
    cudaGetSymbolAddress((void**)&P,   g_P);
    cudaGetSymbolAddress((void**)&ks,  g_ksort);
    cudaGetSymbolAddress((void**)&vs,  g_vsort);
    cudaGetSymbolAddress((void**)&xhi, g_xhi);
    cudaGetSymbolAddress((void**)&xlo, g_xlo);
    cudaGetSymbolAddress((void**)&w1hi, g_w1hi);
    cudaGetSymbolAddress((void**)&w1lo, g_w1lo);
    cudaGetSymbolAddress((void**)&w2hi, g_w2hi);
    cudaGetSymbolAddress((void**)&w2lo, g_w2lo);
    cudaGetSymbolAddress((void**)&athi, g_athi);
    cudaGetSymbolAddress((void**)&atlo, g_atlo);

    cudaFuncSetAttribute(attn_kernel,
                         cudaFuncAttributeMaxDynamicSharedMemorySize, ATTN_SMEM);
    cudaFuncSetAttribute(hgemm_split_kernel,
                         cudaFuncAttributeMaxDynamicSharedMemorySize, GEMM_SMEM);

    // conversions
    split_kernel<<<(M_ * D_ / 4 + 255) / 256, 256>>>(x, xhi, xlo, M_ * D_ / 4);
    wsplit_kernel<<<dim3(TD_ / 32, D_ / 32), dim3(32, 8)>>>(W_qkv, w1hi, w1lo, D_, TD_);
    wsplit_kernel<<<dim3(D_ / 32, D_ / 32), dim3(32, 8)>>>(W_out, w2hi, w2lo, D_, D_);

    // 1) qkv = x @ W_qkv + b_qkv
    hgemm_split_kernel<<<dim3(TD_ / 256, M_ / 128), 256, GEMM_SMEM>>>(
        xhi, xlo, w1hi, w1lo, b_qkv, qkv, M_, TD_, D_);

    // 2) block mean reprs
    repr_kernel<<<(B_ * H_ * NB_ * HD_) / 256, 256>>>(qkv, qr, kr);

    // 3) sinkhorn -> P
    sinkhorn_kernel<<<B_ * H_, 256>>>(qr, kr, gumbel, P);

    // 4) soft-permute K/V blocks
    sortkv_kernel<<<dim3(B_ * H_, (BS_ * HD_) / 256, 2), 256>>>(qkv, P, ks, vs);

    // 5) tensor-core block attention -> bf16 hi/lo
    attn_kernel<<<B_ * H_ * NB_, 256, ATTN_SMEM>>>(qkv, ks, vs, athi, atlo);

    // 6) out = attn @ W_out + b_out
    hgemm_split_kernel<<<dim3(D_ / 256, M_ / 128), 256, GEMM_SMEM>>>(
        athi, atlo, w2hi, w2lo, b_out, out, M_, D_, D_);
}

// round 7
// speedup vs baseline: 2.4526x; 1.2029x over previous
#include <cuda_runtime.h>
#include <cuda_bf16.h>
#include <cuda_fp16.h>
#include <cstdint>

// ---------------- problem constants ----------------
#define B_   4
#define L_   4096
#define D_   1024
#define H_   16
#define BS_  64
#define HD_  64
#define NB_  64
#define TD_  3072           // 3*D
#define M_   (B_*L_)        // 16384
#define SCALE_ 0.125f       // HD^-0.5
#define TEMP_  0.7f

typedef __nv_bfloat16 bf16;
typedef __half f16;

// ---------------- device scratch (allocation-free) ----------------
__device__ float g_qkv  [B_*L_*TD_];            // 192 MB fp32
__device__ float g_qrepr[B_*H_*NB_*HD_];
__device__ float g_krepr[B_*H_*NB_*HD_];
__device__ float g_P    [B_*H_*NB_*NB_];
__device__ float g_ksort[B_*H_*NB_*BS_*HD_];    // 64 MB
__device__ float g_vsort[B_*H_*NB_*BS_*HD_];    // 64 MB
__device__ f16   g_xh   [M_*D_];                // x single fp16
__device__ f16   g_w1hi [TD_*D_];               // W_qkv^T hi  [3072][1024]
__device__ f16   g_w1lo [TD_*D_];
__device__ f16   g_w2hi [D_*D_];                // W_out^T
__device__ f16   g_w2lo [D_*D_];
__device__ f16   g_ath  [M_*D_];                // attn out single fp16

// ---------------- PTX helpers ----------------
__device__ __forceinline__ unsigned smem_u32(const void* p) {
    return (unsigned)__cvta_generic_to_shared(p);
}
__device__ __forceinline__ void ldsm4(unsigned* r, unsigned addr) {
    asm volatile("ldmatrix.sync.aligned.m8n8.x4.shared.b16 {%0,%1,%2,%3}, [%4];\n"
                 : "=r"(r[0]), "=r"(r[1]), "=r"(r[2]), "=r"(r[3]) : "r"(addr));
}
// fp16 inputs, fp32 accumulate
__device__ __forceinline__ void mma16816h(float* c, const unsigned* a, const unsigned* b) {
    asm volatile(
        "mma.sync.aligned.m16n8k16.row.col.f32.f16.f16.f32 "
        "{%0,%1,%2,%3}, {%4,%5,%6,%7}, {%8,%9}, {%0,%1,%2,%3};\n"
        : "+f"(c[0]), "+f"(c[1]), "+f"(c[2]), "+f"(c[3])
        : "r"(a[0]), "r"(a[1]), "r"(a[2]), "r"(a[3]), "r"(b[0]), "r"(b[1]));
}
// bf16 inputs, fp32 accumulate (attention)
__device__ __forceinline__ void mma16816(float* c, const unsigned* a, const unsigned* b) {
    asm volatile(
        "mma.sync.aligned.m16n8k16.row.col.f32.bf16.bf16.f32 "
        "{%0,%1,%2,%3}, {%4,%5,%6,%7}, {%8,%9}, {%0,%1,%2,%3};\n"
        : "+f"(c[0]), "+f"(c[1]), "+f"(c[2]), "+f"(c[3])
        : "r"(a[0]), "r"(a[1]), "r"(a[2]), "r"(a[3]), "r"(b[0]), "r"(b[1]));
}
#define CP_ASYNC16(dst, src) \
    asm volatile("cp.async.cg.shared.global [%0], [%1], 16;\n" :: "r"(dst), "l"(src))
#define CP_COMMIT() asm volatile("cp.async.commit_group;\n")
#define CP_WAIT(n)  asm volatile("cp.async.wait_group %0;\n" :: "n"(n))

// ---------------- 2-term fp16 tensor-core GEMM ----------------
// C[M,N] = A[M,K] @ (Bhi+Blo)[K,N] + bias[N]; A single fp16, B^T as [N][K].
// Block tile 128x256, 8 warps (2x4), warp tile 64x64, K-step 32, 3-stage pipe.
#define TSTRIDE 40
#define SA_H    0
#define SB_H    (128 * TSTRIDE)            // 5120
#define SB_L    (SB_H + 256 * TSTRIDE)     // 15360
#define STG_E   (SB_L + 256 * TSTRIDE)     // 25600 elems / stage
#define NSTG    3
#define GEMM_SMEM (NSTG * STG_E * 2)       // 153600 bytes

__global__ __launch_bounds__(256, 1) void hgemm2_kernel(
    const f16* __restrict__ A, const f16* __restrict__ Bthi,
    const f16* __restrict__ Btlo,
    const float* __restrict__ bias, float* __restrict__ C,
    int M, int N, int K)
{
    extern __shared__ f16 sm[];
    const uint32_t smb = smem_u32(sm);
    const int tid = threadIdx.x;
    const int lane = tid & 31, wid = tid >> 5;
    const int wm = wid & 1, wn = wid >> 1;       // 2x4 warp grid
    const int quad = lane >> 3, qr = lane & 7;

    const int aRow0 = blockIdx.y * 128;
    const int bRow0 = blockIdx.x * 256;
    const int nchunks = K >> 5;

    // loader: 640 rows x 4 chunks = 2560 x 16B per stage, 10 per thread
    auto prefetch = [&](int stg, int k0) {
#pragma unroll
        for (int it = 0; it < 10; it++) {
            int c = tid + it * 256;
            int row = c >> 2;                // 0..639
            int ch  = c & 3;
            const f16* gsrc;
            unsigned soff;
            if (row < 128) {
                gsrc = A + (size_t)(aRow0 + row) * K + k0 + ch * 8;
                soff = SA_H + row * TSTRIDE + ch * 8;
            } else if (row < 384) {
                int r = row - 128;
                gsrc = Bthi + (size_t)(bRow0 + r) * K + k0 + ch * 8;
                soff = SB_H + r * TSTRIDE + ch * 8;
            } else {
                int r = row - 384;
                gsrc = Btlo + (size_t)(bRow0 + r) * K + k0 + ch * 8;
                soff = SB_L + r * TSTRIDE + ch * 8;
            }
            CP_ASYNC16(smb + (stg * STG_E + soff) * 2, gsrc);
        }
        CP_COMMIT();
    };

    prefetch(0, 0);
    prefetch(1, 32);

    float acc[4][8][4] = {};
    int sidx = 0, pidx = 2;

    for (int ck = 0; ck < nchunks; ck++) {
        if (ck < nchunks - 1) { CP_WAIT(1); } else { CP_WAIT(0); }
        __syncthreads();

        if (ck + 2 < nchunks) {
            prefetch(pidx, (ck + 2) << 5);
            pidx = (pidx == 2) ? 0 : pidx + 1;
        }

        const f16* st = sm + sidx * STG_E;
        sidx = (sidx == 2) ? 0 : sidx + 1;
#pragma unroll
        for (int kk = 0; kk < 32; kk += 16) {
            unsigned af[4][4];
#pragma unroll
            for (int mt = 0; mt < 4; mt++) {
                int arow = wm * 64 + mt * 16 + qr + ((quad & 1) << 3);
                int acol = kk + ((quad >> 1) << 3);
                ldsm4(af[mt], smem_u32(st + SA_H + arow * TSTRIDE + acol));
            }
#pragma unroll
            for (int np = 0; np < 4; np++) {
                int brow = wn * 64 + np * 16 + qr + ((quad >> 1) << 3);
                int bcol = kk + ((quad & 1) << 3);
                unsigned boff = brow * TSTRIDE + bcol;
                unsigned bhi[4], blo[4];
                ldsm4(bhi, smem_u32(st + SB_H + boff));
                ldsm4(blo, smem_u32(st + SB_L + boff));
#pragma unroll
                for (int mt = 0; mt < 4; mt++) {
                    mma16816h(acc[mt][np * 2],     af[mt], bhi);
                    mma16816h(acc[mt][np * 2 + 1], af[mt], bhi + 2);
                }
#pragma unroll
                for (int mt = 0; mt < 4; mt++) {
                    mma16816h(acc[mt][np * 2],     af[mt], blo);
                    mma16816h(acc[mt][np * 2 + 1], af[mt], blo + 2);
                }
            }
        }
    }

    const int gr0 = blockIdx.y * 128 + wm * 64 + (lane >> 2);
    const int gc0 = blockIdx.x * 256 + wn * 64 + (lane & 3) * 2;
#pragma unroll
    for (int mt = 0; mt < 4; mt++) {
#pragma unroll
        for (int nt = 0; nt < 8; nt++) {
            int r = gr0 + mt * 16;
            int c = gc0 + nt * 8;
            float b0 = bias[c], b1 = bias[c + 1];
            float2 v0 = make_float2(acc[mt][nt][0] + b0, acc[mt][nt][1] + b1);
            float2 v1 = make_float2(acc[mt][nt][2] + b0, acc[mt][nt][3] + b1);
            *(float2*)(C + (size_t)r * N + c)       = v0;
            *(float2*)(C + (size_t)(r + 8) * N + c) = v1;
        }
    }
}

// ---------------- x -> single fp16 ----------------
__global__ void splitx_kernel(const float* __restrict__ src,
                              f16* __restrict__ dst, int n4)
{
    int i = blockIdx.x * blockDim.x + threadIdx.x;
    if (i >= n4) return;
    float4 v = ((const float4*)src)[i];
    __half2* dp = (__half2*)(dst + i * 4);
    dp[0] = __half2(__float2half_rn(v.x), __float2half_rn(v.y));
    dp[1] = __half2(__float2half_rn(v.z), __float2half_rn(v.w));
}

// ---------------- transpose + split: W[K][N] -> T[N][K] fp16 hi/lo ----------------
__global__ void wsplit_kernel(const float* __restrict__ W,
                              f16* __restrict__ Thi, f16* __restrict__ Tlo,
                              int Kd, int Nd)
{
    __shared__ float t[32][33];
    const int tx = threadIdx.x, ty = threadIdx.y;
    const int n0 = blockIdx.x * 32, k0 = blockIdx.y * 32;
#pragma unroll
    for (int j = 0; j < 4; j++)
        t[ty + j * 8][tx] = W[(size_t)(k0 + ty + j * 8) * Nd + n0 + tx];
    __syncthreads();
#pragma unroll
    for (int j = 0; j < 4; j++) {
        float v = t[tx][ty + j * 8];
        f16 h = __float2half_rn(v);
        f16 l = __float2half_rn(v - __half2float(h));
        size_t idx = (size_t)(n0 + ty + j * 8) * Kd + k0 + tx;
        Thi[idx] = h; Tlo[idx] = l;
    }
}

// ---------------- block mean reprs ----------------
__global__ void repr_kernel(const float* __restrict__ qkv,
                            float* __restrict__ qrepr, float* __restrict__ krepr)
{
    int idx = blockIdx.x * blockDim.x + threadIdx.x;
    int d = idx & 63;
    int n = (idx >> 6) & 63;
    int h = (idx >> 12) & 15;
    int b = idx >> 16;
    const float* base = qkv + ((size_t)(b * L_ + n * BS_)) * TD_ + h * HD_ + d;
    float sq = 0.f, sk = 0.f;
#pragma unroll 8
    for (int s = 0; s < BS_; s++) {
        sq += base[(size_t)s * TD_];
        sk += base[(size_t)s * TD_ + D_];
    }
    qrepr[idx] = sq * (1.0f / BS_);
    krepr[idx] = sk * (1.0f / BS_);
}

// ---------------- sinkhorn -> P ----------------
__global__ __launch_bounds__(256) void sinkhorn_kernel(
    const float* __restrict__ qrepr, const float* __restrict__ krepr,
    const float* __restrict__ gumbel, float* __restrict__ P)
{
    __shared__ float La[64][65];
    const int bh = blockIdx.x;
    const int tid = threadIdx.x;
    const float* qr = qrepr + bh * NB_ * HD_;
    const float* kr = krepr + bh * NB_ * HD_;

    for (int e = tid; e < NB_ * NB_; e += 256) {
        int nn = e >> 6, m = e & 63;
        float s = 0.f;
#pragma unroll 16
        for (int d = 0; d < HD_; d++) s += qr[nn * HD_ + d] * kr[m * HD_ + d];
        La[nn][m] = (s * SCALE_ + gumbel[bh * NB_ * NB_ + e]) * (1.0f / TEMP_);
    }
    __syncthreads();

    for (int it = 0; it < 7; it++) {
        if (tid < 64) {
            float mx = -1e30f;
            for (int m = 0; m < 64; m++) mx = fmaxf(mx, La[tid][m]);
            float se = 0.f;
            for (int m = 0; m < 64; m++) se += expf(La[tid][m] - mx);
            float ls = mx + logf(se);
            for (int m = 0; m < 64; m++) La[tid][m] -= ls;
        }
        __syncthreads();
        if (tid < 64) {
            float mx = -1e30f;
            for (int r = 0; r < 64; r++) mx = fmaxf(mx, La[r][tid]);
            float se = 0.f;
            for (int r = 0; r < 64; r++) se += expf(La[r][tid] - mx);
            float ls = mx + logf(se);
            for (int r = 0; r < 64; r++) La[r][tid] -= ls;
        }
        __syncthreads();
    }
    for (int e = tid; e < NB_ * NB_; e += 256)
        P[bh * NB_ * NB_ + e] = expf(La[e >> 6][e & 63]);
}

// ---------------- k/v soft permutation, split passes ----------------
__global__ __launch_bounds__(256) void sortkv_kernel(
    const float* __restrict__ qkv, const float* __restrict__ P,
    float* __restrict__ ksort, float* __restrict__ vsort)
{
    const int bh = blockIdx.x;
    const int b = bh >> 4, h = bh & 15;
    const int f = blockIdx.y * 256 + threadIdx.x;
    const int s = f >> 6, d = f & 63;
    const int which = blockIdx.z;

    __shared__ float Ps[64][64];
    for (int e = threadIdx.x; e < 4096; e += 256)
        Ps[e >> 6][e & 63] = P[bh * 4096 + e];
    __syncthreads();

    const float* base = qkv + ((size_t)(b * L_ + s)) * TD_ + h * HD_ + d
                        + (which ? 2 * D_ : D_);
    float xm[64];
#pragma unroll
    for (int m = 0; m < 64; m++)
        xm[m] = base[(size_t)m * BS_ * TD_];

    float* dst = which ? vsort : ksort;
    const size_t obase = (size_t)bh * NB_ * BS_ * HD_ + f;
    for (int n2 = 0; n2 < 64; n2++) {
        float acc = 0.f;
#pragma unroll
        for (int m = 0; m < 64; m++) acc += Ps[n2][m] * xm[m];
        dst[obase + (size_t)n2 * BS_ * HD_] = acc;
    }
}

// ---------------- tensor-core block attention (bf16 3-term inside) ----------------
#define AQ_STR 72
#define AK_STR 72
#define AV_STR 136
#define AP_STR 136
#define O_SQH  0
#define O_SQL  9216
#define O_SKH  18432
#define O_SKL  36864
#define O_SVTH 55296
#define O_SVTL 72704
#define O_SPH  90112
#define O_SPL  107520
#define O_SCT  124928
#define ATTN_SMEM (O_SCT + 128 * 72 * 4)    // 161792 bytes

__global__ __launch_bounds__(256) void attn_kernel(
    const float* __restrict__ qkv, const float* __restrict__ ksort,
    const float* __restrict__ vsort, f16* __restrict__ ath)
{
    extern __shared__ __align__(16) char smc[];
    bf16* SQH = (bf16*)(smc + O_SQH);     // [64][72]  s-major
    bf16* SQL = (bf16*)(smc + O_SQL);
    bf16* SKH = (bf16*)(smc + O_SKH);     // [128][72] j-major
    bf16* SKL = (bf16*)(smc + O_SKL);
    bf16* SVTH = (bf16*)(smc + O_SVTH);   // [64][136] d-major = V^T
    bf16* SVTL = (bf16*)(smc + O_SVTL);
    bf16* SPH = (bf16*)(smc + O_SPH);     // [64][136] s-major
    bf16* SPL = (bf16*)(smc + O_SPL);
    float* SCT = (float*)(smc + O_SCT);   // [128][72] j-major scores

    const int blk = blockIdx.x;
    const int n2 = blk & 63;
    const int h = (blk >> 6) & 15;
    const int b = blk >> 10;
    const int bh = b * H_ + h;
    const int tid = threadIdx.x;
    const int lane = tid & 31, wid = tid >> 5;
    const int quad = lane >> 3, qr = lane & 7;
    const int nn = (n2 + 1) & 63;

    const float* qbase   = qkv + ((size_t)(b * L_ + n2 * BS_)) * TD_ + h * HD_;
    const float* nbase_k = ksort + ((size_t)(bh * NB_ + nn)) * BS_ * HD_;
    const float* nbase_v = vsort + ((size_t)(bh * NB_ + nn)) * BS_ * HD_;

    for (int i4 = tid; i4 < 1024; i4 += 256) {
        int s  = i4 >> 4;
        int d4 = (i4 & 15) << 2;
        float4 qv = *(const float4*)(qbase + (size_t)s * TD_ + d4);
        float4 kv = *(const float4*)(qbase + (size_t)s * TD_ + D_ + d4);
        float4 vv = *(const float4*)(qbase + (size_t)s * TD_ + 2 * D_ + d4);
        float4 kn = *(const float4*)(nbase_k + s * HD_ + d4);
        float4 vn = *(const float4*)(nbase_v + s * HD_ + d4);
        float qa[4] = {qv.x, qv.y, qv.z, qv.w};
        float ka[4] = {kv.x, kv.y, kv.z, kv.w};
        float va[4] = {vv.x, vv.y, vv.z, vv.w};
        float kna[4] = {kn.x, kn.y, kn.z, kn.w};
        float vna[4] = {vn.x, vn.y, vn.z, vn.w};
#pragma unroll
        for (int t = 0; t < 4; t++) {
            bf16 hq = __float2bfloat16_rn(qa[t]);
            SQH[s * AQ_STR + d4 + t] = hq;
            SQL[s * AQ_STR + d4 + t] = __float2bfloat16_rn(qa[t] - __bfloat162float(hq));
            bf16 hk = __float2bfloat16_rn(ka[t]);
            SKH[s * AK_STR + d4 + t] = hk;
            SKL[s * AK_STR + d4 + t] = __float2bfloat16_rn(ka[t] - __bfloat162float(hk));
            bf16 hkn = __float2bfloat16_rn(kna[t]);
            SKH[(64 + s) * AK_STR + d4 + t] = hkn;
            SKL[(64 + s) * AK_STR + d4 + t] = __float2bfloat16_rn(kna[t] - __bfloat162float(hkn));
            bf16 hv = __float2bfloat16_rn(va[t]);
            SVTH[(d4 + t) * AV_STR + s] = hv;
            SVTL[(d4 + t) * AV_STR + s] = __float2bfloat16_rn(va[t] - __bfloat162float(hv));
            bf16 hvn = __float2bfloat16_rn(vna[t]);
            SVTH[(d4 + t) * AV_STR + 64 + s] = hvn;
            SVTL[(d4 + t) * AV_STR + 64 + s] = __float2bfloat16_rn(vna[t] - __bfloat162float(hvn));
        }
    }
    __syncthreads();

    // scores via mma: warp tile 16(s) x 64(j)
    {
        const int wm = wid & 3, wn = wid >> 2;
        float sacc[8][4] = {};
#pragma unroll
        for (int k16 = 0; k16 < 64; k16 += 16) {
            unsigned aoff = (wm * 16 + qr + ((quad & 1) << 3)) * AQ_STR
                            + k16 + ((quad >> 1) << 3);
            unsigned aH[4], aL[4];
            ldsm4(aH, smem_u32(SQH + aoff));
            ldsm4(aL, smem_u32(SQL + aoff));
#pragma unroll
            for (int nt = 0; nt < 4; nt++) {
                unsigned boff = (wn * 64 + nt * 16 + qr + ((quad >> 1) << 3)) * AK_STR
                                + k16 + ((quad & 1) << 3);
                unsigned bH[4], bL[4];
                ldsm4(bH, smem_u32(SKH + boff));
                ldsm4(bL, smem_u32(SKL + boff));
                mma16816(sacc[nt * 2],     aH, bH);
                mma16816(sacc[nt * 2 + 1], aH, bH + 2);
                mma16816(sacc[nt * 2],     aH, bL);
                mma16816(sacc[nt * 2 + 1], aH, bL + 2);
                mma16816(sacc[nt * 2],     aL, bH);
                mma16816(sacc[nt * 2 + 1], aL, bH + 2);
            }
        }
        const bool maskme = (n2 == NB_ - 1) && (wn == 1);
        const int srow = wm * 16 + (lane >> 2);
#pragma unroll
        for (int p = 0; p < 8; p++) {
            int j0 = wn * 64 + (p >> 1) * 16 + (p & 1) * 8 + (lane & 3) * 2;
            float c0 = sacc[p][0] * SCALE_, c1 = sacc[p][1] * SCALE_;
            float c2 = sacc[p][2] * SCALE_, c3 = sacc[p][3] * SCALE_;
            if (maskme) { c0 = c1 = c2 = c3 = -1e9f; }
            SCT[j0 * 72 + srow]           = c0;
            SCT[(j0 + 1) * 72 + srow]     = c1;
            SCT[j0 * 72 + srow + 8]       = c2;
            SCT[(j0 + 1) * 72 + srow + 8] = c3;
        }
    }
    __syncthreads();

    // softmax: 4 threads per query row
    {
        const int sr = tid >> 2;
        const int qd = tid & 3;
        float mx = -1e30f;
#pragma unroll
        for (int jj = 0; jj < 32; jj++) {
            int j = jj * 4 + qd;
            mx = fmaxf(mx, SCT[j * 72 + sr]);
        }
        mx = fmaxf(mx, __shfl_xor_sync(0xffffffffu, mx, 1));
        mx = fmaxf(mx, __shfl_xor_sync(0xffffffffu, mx, 2));
        float se = 0.f;
#pragma unroll
        for (int jj = 0; jj < 32; jj++) {
            int j = jj * 4 + qd;
            float e = __expf(SCT[j * 72 + sr] - mx);
            SCT[j * 72 + sr] = e;
            se += e;
        }
        se += __shfl_xor_sync(0xffffffffu, se, 1);
        se += __shfl_xor_sync(0xffffffffu, se, 2);
        float inv = 1.0f / se;
#pragma unroll
        for (int jj = 0; jj < 32; jj++) {
            int j = jj * 4 + qd;
            SCT[j * 72 + sr] *= inv;
        }
    }
    __syncthreads();

    // split probs to bf16 hi/lo
    for (int i = tid; i < 8192; i += 256) {
        int s = i & 63, j = i >> 6;
        float p = SCT[j * 72 + s];
        bf16 hp = __float2bfloat16_rn(p);
        SPH[s * AP_STR + j] = hp;
        SPL[s * AP_STR + j] = __float2bfloat16_rn(p - __bfloat162float(hp));
    }
    __syncthreads();

    // PV via mma: warp tile 16(s) x 32(d); epilogue -> single fp16
    {
        const int wm = wid & 3, wn = wid >> 2;
        float oacc[4][4] = {};
#pragma unroll
        for (int k16 = 0; k16 < 128; k16 += 16) {
            unsigned poff = (wm * 16 + qr + ((quad & 1) << 3)) * AP_STR
                            + k16 + ((quad >> 1) << 3);
            unsigned pH[4], pL[4];
            ldsm4(pH, smem_u32(SPH + poff));
            ldsm4(pL, smem_u32(SPL + poff));
#pragma unroll
            for (int nt = 0; nt < 2; nt++) {
                unsigned voff = (wn * 32 + nt * 16 + qr + ((quad >> 1) << 3)) * AV_STR
                                + k16 + ((quad & 1) << 3);
                unsigned vH[4], vL[4];
                ldsm4(vH, smem_u32(SVTH + voff));
                ldsm4(vL, smem_u32(SVTL + voff));
                mma16816(oacc[nt * 2],     pH, vH);
                mma16816(oacc[nt * 2 + 1], pH, vH + 2);
                mma16816(oacc[nt * 2],     pH, vL);
                mma16816(oacc[nt * 2 + 1], pH, vL + 2);
                mma16816(oacc[nt * 2],     pL, vH);
                mma16816(oacc[nt * 2 + 1], pL, vH + 2);
            }
        }
        const int srow = wm * 16 + (lane >> 2);
        const size_t obase = ((size_t)(b * L_ + n2 * BS_)) * D_ + h * HD_;
#pragma unroll
        for (int p = 0; p < 4; p++) {
            int d0 = wn * 32 + (p >> 1) * 16 + (p & 1) * 8 + (lane & 3) * 2;
#pragma unroll
            for (int rr = 0; rr < 2; rr++) {
                float v0 = oacc[p][rr * 2], v1 = oacc[p][rr * 2 + 1];
                size_t o = obase + (size_t)(srow + rr * 8) * D_ + d0;
                *(__half2*)(ath + o) =
                    __half2(__float2half_rn(v0), __float2half_rn(v1));
            }
        }
    }
}

// ---------------- launch ----------------
extern "C" void kernel_launch(void* const* d_in, const int* in_sizes, int n_in,
                              void* d_out, int out_size)
{
    const float* x      = (const float*)d_in[0];
    const float* gumbel = (const float*)d_in[1];
    const float* W_qkv  = (const float*)d_in[2];
    const float* b_qkv  = (const float*)d_in[3];
    const float* W_out  = (const float*)d_in[4];
    const float* b_out  = (const float*)d_in[5];
    float* out = (float*)d_out;

    float *qkv, *qr, *kr, *P, *ks, *vs;
    f16 *xh, *w1hi, *w1lo, *w2hi, *w2lo, *ath;
    cudaGetSymbolAddress((void**)&qkv, g_qkv);
    cudaGetSymbolAddress((void**)&qr,  g_qrepr);
    cudaGetSymbolAddress((void**)&kr,  g_krepr);
    cudaGetSymbolAddress((void**)&P,   g_P);
    cudaGetSymbolAddress((void**)&ks,  g_ksort);
    cudaGetSymbolAddress((void**)&vs,  g_vsort);
    cudaGetSymbolAddress((void**)&xh,  g_xh);
    cudaGetSymbolAddress((void**)&w1hi, g_w1hi);
    cudaGetSymbolAddress((void**)&w1lo, g_w1lo);
    cudaGetSymbolAddress((void**)&w2hi, g_w2hi);
    cudaGetSymbolAddress((void**)&w2lo, g_w2lo);
    cudaGetSymbolAddress((void**)&ath, g_ath);

    cudaFuncSetAttribute(attn_kernel,
                         cudaFuncAttributeMaxDynamicSharedMemorySize, ATTN_SMEM);
    cudaFuncSetAttribute(hgemm2_kernel,
                         cudaFuncAttributeMaxDynamicSharedMemorySize, GEMM_SMEM);

    // conversions
    splitx_kernel<<<(M_ * D_ / 4 + 255) / 256, 256>>>(x, xh, M_ * D_ / 4);
    wsplit_kernel<<<dim3(TD_ / 32, D_ / 32), dim3(32, 8)>>>(W_qkv, w1hi, w1lo, D_, TD_);
    wsplit_kernel<<<dim3(D_ / 32, D_ / 32), dim3(32, 8)>>>(W_out, w2hi, w2lo, D_, D_);

    // 1) qkv = x @ W_qkv + b_qkv   (fp16 2-term)
    hgemm2_kernel<<<dim3(TD_ / 256, M_ / 128), 256, GEMM_SMEM>>>(
        xh, w1hi, w1lo, b_qkv, qkv, M_, TD_, D_);

    // 2) block mean reprs
    repr_kernel<<<(B_ * H_ * NB_ * HD_) / 256, 256>>>(qkv, qr, kr);

    // 3) sinkhorn -> P
    sinkhorn_kernel<<<B_ * H_, 256>>>(qr, kr, gumbel, P);

    // 4) soft-permute K/V blocks
    sortkv_kernel<<<dim3(B_ * H_, (BS_ * HD_) / 256, 2), 256>>>(qkv, P, ks, vs);

    // 5) tensor-core block attention -> single fp16
    attn_kernel<<<B_ * H_ * NB_, 256, ATTN_SMEM>>>(qkv, ks, vs, ath);

    // 6) out = attn @ W_out + b_out  (fp16 2-term)
    hgemm2_kernel<<<dim3(D_ / 256, M_ / 128), 256, GEMM_SMEM>>>(
        ath, w2hi, w2lo, b_out, out, M_, D_, D_);
}

// round 8
// speedup vs baseline: 3.2139x; 1.3104x over previous
#include <cuda_runtime.h>
#include <cuda_bf16.h>
#include <cuda_fp16.h>
#include <cstdint>

// ---------------- problem constants ----------------
#define B_   4
#define L_   4096
#define D_   1024
#define H_   16
#define BS_  64
#define HD_  64
#define NB_  64
#define TD_  3072           // 3*D
#define M_   (B_*L_)        // 16384
#define SCALE_ 0.125f       // HD^-0.5
#define TEMP_  0.7f

typedef __nv_bfloat16 bf16;
typedef __half f16;

// ---------------- device scratch (allocation-free) ----------------
__device__ float g_qkv  [B_*L_*TD_];            // 192 MB fp32
__device__ float g_qrepr[B_*H_*NB_*HD_];
__device__ float g_krepr[B_*H_*NB_*HD_];
__device__ float g_P    [B_*H_*NB_*NB_];
__device__ float g_ksort[B_*H_*NB_*BS_*HD_];    // 64 MB
__device__ float g_vsort[B_*H_*NB_*BS_*HD_];    // 64 MB
__device__ f16   g_xh   [M_*D_];                // x single fp16
__device__ f16   g_w1h  [TD_*D_];               // W_qkv^T fp16 [3072][1024]
__device__ f16   g_w2h  [D_*D_];                // W_out^T fp16
__device__ f16   g_ath  [M_*D_];                // attn out single fp16

// ---------------- PTX helpers ----------------
__device__ __forceinline__ unsigned smem_u32(const void* p) {
    return (unsigned)__cvta_generic_to_shared(p);
}
__device__ __forceinline__ void ldsm4(unsigned* r, unsigned addr) {
    asm volatile("ldmatrix.sync.aligned.m8n8.x4.shared.b16 {%0,%1,%2,%3}, [%4];\n"
                 : "=r"(r[0]), "=r"(r[1]), "=r"(r[2]), "=r"(r[3]) : "r"(addr));
}
// fp16 inputs, fp32 accumulate
__device__ __forceinline__ void mma16816h(float* c, const unsigned* a, const unsigned* b) {
    asm volatile(
        "mma.sync.aligned.m16n8k16.row.col.f32.f16.f16.f32 "
        "{%0,%1,%2,%3}, {%4,%5,%6,%7}, {%8,%9}, {%0,%1,%2,%3};\n"
        : "+f"(c[0]), "+f"(c[1]), "+f"(c[2]), "+f"(c[3])
        : "r"(a[0]), "r"(a[1]), "r"(a[2]), "r"(a[3]), "r"(b[0]), "r"(b[1]));
}
// bf16 inputs, fp32 accumulate (attention)
__device__ __forceinline__ void mma16816(float* c, const unsigned* a, const unsigned* b) {
    asm volatile(
        "mma.sync.aligned.m16n8k16.row.col.f32.bf16.bf16.f32 "
        "{%0,%1,%2,%3}, {%4,%5,%6,%7}, {%8,%9}, {%0,%1,%2,%3};\n"
        : "+f"(c[0]), "+f"(c[1]), "+f"(c[2]), "+f"(c[3])
        : "r"(a[0]), "r"(a[1]), "r"(a[2]), "r"(a[3]), "r"(b[0]), "r"(b[1]));
}
#define CP_ASYNC16(dst, src) \
    asm volatile("cp.async.cg.shared.global [%0], [%1], 16;\n" :: "r"(dst), "l"(src))
#define CP_COMMIT() asm volatile("cp.async.commit_group;\n")
#define CP_WAIT(n)  asm volatile("cp.async.wait_group %0;\n" :: "n"(n))

// ---------------- single-fp16 tensor-core GEMM ----------------
// C[M,N] = A[M,K] @ B[K,N] + bias[N]; A,B single fp16, B^T supplied as [N][K].
// Block tile 128x256, 8 warps (2x4), warp tile 64x64, K-step 32, 3-stage pipe.
#define TSTRIDE 40
#define SA_H    0
#define SB_H    (128 * TSTRIDE)            // 5120
#define STG_E   (SB_H + 256 * TSTRIDE)     // 15360 elems / stage
#define NSTG    3
#define GEMM_SMEM (NSTG * STG_E * 2)       // 92160 bytes

__global__ __launch_bounds__(256, 1) void hgemm1_kernel(
    const f16* __restrict__ A, const f16* __restrict__ Bt,
    const float* __restrict__ bias, float* __restrict__ C,
    int M, int N, int K)
{
    extern __shared__ f16 sm[];
    const uint32_t smb = smem_u32(sm);
    const int tid = threadIdx.x;
    const int lane = tid & 31, wid = tid >> 5;
    const int wm = wid & 1, wn = wid >> 1;       // 2x4 warp grid
    const int quad = lane >> 3, qr = lane & 7;

    const int aRow0 = blockIdx.y * 128;
    const int bRow0 = blockIdx.x * 256;
    const int nchunks = K >> 5;

    // loader: 384 rows x 4 chunks = 1536 x 16B per stage, 6 per thread
    auto prefetch = [&](int stg, int k0) {
#pragma unroll
        for (int it = 0; it < 6; it++) {
            int c = tid + it * 256;
            int row = c >> 2;                // 0..383
            int ch  = c & 3;
            const f16* gsrc;
            unsigned soff;
            if (row < 128) {
                gsrc = A + (size_t)(aRow0 + row) * K + k0 + ch * 8;
                soff = SA_H + row * TSTRIDE + ch * 8;
            } else {
                int r = row - 128;
                gsrc = Bt + (size_t)(bRow0 + r) * K + k0 + ch * 8;
                soff = SB_H + r * TSTRIDE + ch * 8;
            }
            CP_ASYNC16(smb + (stg * STG_E + soff) * 2, gsrc);
        }
        CP_COMMIT();
    };

    prefetch(0, 0);
    prefetch(1, 32);

    float acc[4][8][4] = {};
    int sidx = 0, pidx = 2;

    for (int ck = 0; ck < nchunks; ck++) {
        if (ck < nchunks - 1) { CP_WAIT(1); } else { CP_WAIT(0); }
        __syncthreads();

        if (ck + 2 < nchunks) {
            prefetch(pidx, (ck + 2) << 5);
            pidx = (pidx == 2) ? 0 : pidx + 1;
        }

        const f16* st = sm + sidx * STG_E;
        sidx = (sidx == 2) ? 0 : sidx + 1;
#pragma unroll
        for (int kk = 0; kk < 32; kk += 16) {
            unsigned af[4][4];
#pragma unroll
            for (int mt = 0; mt < 4; mt++) {
                int arow = wm * 64 + mt * 16 + qr + ((quad & 1) << 3);
                int acol = kk + ((quad >> 1) << 3);
                ldsm4(af[mt], smem_u32(st + SA_H + arow * TSTRIDE + acol));
            }
#pragma unroll
            for (int np = 0; np < 4; np++) {
                int brow = wn * 64 + np * 16 + qr + ((quad >> 1) << 3);
                int bcol = kk + ((quad & 1) << 3);
                unsigned bf[4];
                ldsm4(bf, smem_u32(st + SB_H + brow * TSTRIDE + bcol));
#pragma unroll
                for (int mt = 0; mt < 4; mt++) {
                    mma16816h(acc[mt][np * 2],     af[mt], bf);
                    mma16816h(acc[mt][np * 2 + 1], af[mt], bf + 2);
                }
            }
        }
    }

    const int gr0 = blockIdx.y * 128 + wm * 64 + (lane >> 2);
    const int gc0 = blockIdx.x * 256 + wn * 64 + (lane & 3) * 2;
#pragma unroll
    for (int mt = 0; mt < 4; mt++) {
#pragma unroll
        for (int nt = 0; nt < 8; nt++) {
            int r = gr0 + mt * 16;
            int c = gc0 + nt * 8;
            float b0 = bias[c], b1 = bias[c + 1];
            float2 v0 = make_float2(acc[mt][nt][0] + b0, acc[mt][nt][1] + b1);
            float2 v1 = make_float2(acc[mt][nt][2] + b0, acc[mt][nt][3] + b1);
            *(float2*)(C + (size_t)r * N + c)       = v0;
            *(float2*)(C + (size_t)(r + 8) * N + c) = v1;
        }
    }
}

// ---------------- x -> single fp16 ----------------
__global__ void splitx_kernel(const float* __restrict__ src,
                              f16* __restrict__ dst, int n4)
{
    int i = blockIdx.x * blockDim.x + threadIdx.x;
    if (i >= n4) return;
    float4 v = ((const float4*)src)[i];
    __half2* dp = (__half2*)(dst + i * 4);
    dp[0] = __half2(__float2half_rn(v.x), __float2half_rn(v.y));
    dp[1] = __half2(__float2half_rn(v.z), __float2half_rn(v.w));
}

// ---------------- transpose + convert: W[K][N] -> T[N][K] fp16 ----------------
__global__ void wconv_kernel(const float* __restrict__ W,
                             f16* __restrict__ T, int Kd, int Nd)
{
    __shared__ float t[32][33];
    const int tx = threadIdx.x, ty = threadIdx.y;
    const int n0 = blockIdx.x * 32, k0 = blockIdx.y * 32;
#pragma unroll
    for (int j = 0; j < 4; j++)
        t[ty + j * 8][tx] = W[(size_t)(k0 + ty + j * 8) * Nd + n0 + tx];
    __syncthreads();
#pragma unroll
    for (int j = 0; j < 4; j++) {
        float v = t[tx][ty + j * 8];
        size_t idx = (size_t)(n0 + ty + j * 8) * Kd + k0 + tx;
        T[idx] = __float2half_rn(v);
    }
}

// ---------------- block mean reprs ----------------
__global__ void repr_kernel(const float* __restrict__ qkv,
                            float* __restrict__ qrepr, float* __restrict__ krepr)
{
    int idx = blockIdx.x * blockDim.x + threadIdx.x;
    int d = idx & 63;
    int n = (idx >> 6) & 63;
    int h = (idx >> 12) & 15;
    int b = idx >> 16;
    const float* base = qkv + ((size_t)(b * L_ + n * BS_)) * TD_ + h * HD_ + d;
    float sq = 0.f, sk = 0.f;
#pragma unroll 8
    for (int s = 0; s < BS_; s++) {
        sq += base[(size_t)s * TD_];
        sk += base[(size_t)s * TD_ + D_];
    }
    qrepr[idx] = sq * (1.0f / BS_);
    krepr[idx] = sk * (1.0f / BS_);
}

// ---------------- sinkhorn -> P ----------------
__global__ __launch_bounds__(256) void sinkhorn_kernel(
    const float* __restrict__ qrepr, const float* __restrict__ krepr,
    const float* __restrict__ gumbel, float* __restrict__ P)
{
    __shared__ float La[64][65];
    const int bh = blockIdx.x;
    const int tid = threadIdx.x;
    const float* qr = qrepr + bh * NB_ * HD_;
    const float* kr = krepr + bh * NB_ * HD_;

    for (int e = tid; e < NB_ * NB_; e += 256) {
        int nn = e >> 6, m = e & 63;
        float s = 0.f;
#pragma unroll 16
        for (int d = 0; d < HD_; d++) s += qr[nn * HD_ + d] * kr[m * HD_ + d];
        La[nn][m] = (s * SCALE_ + gumbel[bh * NB_ * NB_ + e]) * (1.0f / TEMP_);
    }
    __syncthreads();

    for (int it = 0; it < 7; it++) {
        if (tid < 64) {
            float mx = -1e30f;
            for (int m = 0; m < 64; m++) mx = fmaxf(mx, La[tid][m]);
            float se = 0.f;
            for (int m = 0; m < 64; m++) se += expf(La[tid][m] - mx);
            float ls = mx + logf(se);
            for (int m = 0; m < 64; m++) La[tid][m] -= ls;
        }
        __syncthreads();
        if (tid < 64) {
            float mx = -1e30f;
            for (int r = 0; r < 64; r++) mx = fmaxf(mx, La[r][tid]);
            float se = 0.f;
            for (int r = 0; r < 64; r++) se += expf(La[r][tid] - mx);
            float ls = mx + logf(se);
            for (int r = 0; r < 64; r++) La[r][tid] -= ls;
        }
        __syncthreads();
    }
    for (int e = tid; e < NB_ * NB_; e += 256)
        P[bh * NB_ * NB_ + e] = expf(La[e >> 6][e & 63]);
}

// ---------------- k/v soft permutation, split passes ----------------
__global__ __launch_bounds__(256) void sortkv_kernel(
    const float* __restrict__ qkv, const float* __restrict__ P,
    float* __restrict__ ksort, float* __restrict__ vsort)
{
    const int bh = blockIdx.x;
    const int b = bh >> 4, h = bh & 15;
    const int f = blockIdx.y * 256 + threadIdx.x;
    const int s = f >> 6, d = f & 63;
    const int which = blockIdx.z;

    __shared__ float Ps[64][64];
    for (int e = threadIdx.x; e < 4096; e += 256)
        Ps[e >> 6][e & 63] = P[bh * 4096 + e];
    __syncthreads();

    const float* base = qkv + ((size_t)(b * L_ + s)) * TD_ + h * HD_ + d
                        + (which ? 2 * D_ : D_);
    float xm[64];
#pragma unroll
    for (int m = 0; m < 64; m++)
        xm[m] = base[(size_t)m * BS_ * TD_];

    float* dst = which ? vsort : ksort;
    const size_t obase = (size_t)bh * NB_ * BS_ * HD_ + f;
    for (int n2 = 0; n2 < 64; n2++) {
        float acc = 0.f;
#pragma unroll
        for (int m = 0; m < 64; m++) acc += Ps[n2][m] * xm[m];
        dst[obase + (size_t)n2 * BS_ * HD_] = acc;
    }
}

// ---------------- tensor-core block attention (bf16 3-term inside) ----------------
#define AQ_STR 72
#define AK_STR 72
#define AV_STR 136
#define AP_STR 136
#define O_SQH  0
#define O_SQL  9216
#define O_SKH  18432
#define O_SKL  36864
#define O_SVTH 55296
#define O_SVTL 72704
#define O_SPH  90112
#define O_SPL  107520
#define O_SCT  124928
#define ATTN_SMEM (O_SCT + 128 * 72 * 4)    // 161792 bytes

__global__ __launch_bounds__(256) void attn_kernel(
    const float* __restrict__ qkv, const float* __restrict__ ksort,
    const float* __restrict__ vsort, f16* __restrict__ ath)
{
    extern __shared__ __align__(16) char smc[];
    bf16* SQH = (bf16*)(smc + O_SQH);     // [64][72]  s-major
    bf16* SQL = (bf16*)(smc + O_SQL);
    bf16* SKH = (bf16*)(smc + O_SKH);     // [128][72] j-major
    bf16* SKL = (bf16*)(smc + O_SKL);
    bf16* SVTH = (bf16*)(smc + O_SVTH);   // [64][136] d-major = V^T
    bf16* SVTL = (bf16*)(smc + O_SVTL);
    bf16* SPH = (bf16*)(smc + O_SPH);     // [64][136] s-major
    bf16* SPL = (bf16*)(smc + O_SPL);
    float* SCT = (float*)(smc + O_SCT);   // [128][72] j-major scores

    const int blk = blockIdx.x;
    const int n2 = blk & 63;
    const int h = (blk >> 6) & 15;
    const int b = blk >> 10;
    const int bh = b * H_ + h;
    const int tid = threadIdx.x;
    const int lane = tid & 31, wid = tid >> 5;
    const int quad = lane >> 3, qr = lane & 7;
    const int nn = (n2 + 1) & 63;

    const float* qbase   = qkv + ((size_t)(b * L_ + n2 * BS_)) * TD_ + h * HD_;
    const float* nbase_k = ksort + ((size_t)(bh * NB_ + nn)) * BS_ * HD_;
    const float* nbase_v = vsort + ((size_t)(bh * NB_ + nn)) * BS_ * HD_;

    for (int i4 = tid; i4 < 1024; i4 += 256) {
        int s  = i4 >> 4;
        int d4 = (i4 & 15) << 2;
        float4 qv = *(const float4*)(qbase + (size_t)s * TD_ + d4);
        float4 kv = *(const float4*)(qbase + (size_t)s * TD_ + D_ + d4);
        float4 vv = *(const float4*)(qbase + (size_t)s * TD_ + 2 * D_ + d4);
        float4 kn = *(const float4*)(nbase_k + s * HD_ + d4);
        float4 vn = *(const float4*)(nbase_v + s * HD_ + d4);
        float qa[4] = {qv.x, qv.y, qv.z, qv.w};
        float ka[4] = {kv.x, kv.y, kv.z, kv.w};
        float va[4] = {vv.x, vv.y, vv.z, vv.w};
        float kna[4] = {kn.x, kn.y, kn.z, kn.w};
        float vna[4] = {vn.x, vn.y, vn.z, vn.w};
#pragma unroll
        for (int t = 0; t < 4; t++) {
            bf16 hq = __float2bfloat16_rn(qa[t]);
            SQH[s * AQ_STR + d4 + t] = hq;
            SQL[s * AQ_STR + d4 + t] = __float2bfloat16_rn(qa[t] - __bfloat162float(hq));
            bf16 hk = __float2bfloat16_rn(ka[t]);
            SKH[s * AK_STR + d4 + t] = hk;
            SKL[s * AK_STR + d4 + t] = __float2bfloat16_rn(ka[t] - __bfloat162float(hk));
            bf16 hkn = __float2bfloat16_rn(kna[t]);
            SKH[(64 + s) * AK_STR + d4 + t] = hkn;
            SKL[(64 + s) * AK_STR + d4 + t] = __float2bfloat16_rn(kna[t] - __bfloat162float(hkn));
            bf16 hv = __float2bfloat16_rn(va[t]);
            SVTH[(d4 + t) * AV_STR + s] = hv;
            SVTL[(d4 + t) * AV_STR + s] = __float2bfloat16_rn(va[t] - __bfloat162float(hv));
            bf16 hvn = __float2bfloat16_rn(vna[t]);
            SVTH[(d4 + t) * AV_STR + 64 + s] = hvn;
            SVTL[(d4 + t) * AV_STR + 64 + s] = __float2bfloat16_rn(vna[t] - __bfloat162float(hvn));
        }
    }
    __syncthreads();

    // scores via mma: warp tile 16(s) x 64(j)
    {
        const int wm = wid & 3, wn = wid >> 2;
        float sacc[8][4] = {};
#pragma unroll
        for (int k16 = 0; k16 < 64; k16 += 16) {
            unsigned aoff = (wm * 16 + qr + ((quad & 1) << 3)) * AQ_STR
                            + k16 + ((quad >> 1) << 3);
            unsigned aH[4], aL[4];
            ldsm4(aH, smem_u32(SQH + aoff));
            ldsm4(aL, smem_u32(SQL + aoff));
#pragma unroll
            for (int nt = 0; nt < 4; nt++) {
                unsigned boff = (wn * 64 + nt * 16 + qr + ((quad >> 1) << 3)) * AK_STR
                                + k16 + ((quad & 1) << 3);
                unsigned bH[4], bL[4];
                ldsm4(bH, smem_u32(SKH + boff));
                ldsm4(bL, smem_u32(SKL + boff));
                mma16816(sacc[nt * 2],     aH, bH);
                mma16816(sacc[nt * 2 + 1], aH, bH + 2);
                mma16816(sacc[nt * 2],     aH, bL);
                mma16816(sacc[nt * 2 + 1], aH, bL + 2);
                mma16816(sacc[nt * 2],     aL, bH);
                mma16816(sacc[nt * 2 + 1], aL, bH + 2);
            }
        }
        const bool maskme = (n2 == NB_ - 1) && (wn == 1);
        const int srow = wm * 16 + (lane >> 2);
#pragma unroll
        for (int p = 0; p < 8; p++) {
            int j0 = wn * 64 + (p >> 1) * 16 + (p & 1) * 8 + (lane & 3) * 2;
            float c0 = sacc[p][0] * SCALE_, c1 = sacc[p][1] * SCALE_;
            float c2 = sacc[p][2] * SCALE_, c3 = sacc[p][3] * SCALE_;
            if (maskme) { c0 = c1 = c2 = c3 = -1e9f; }
            SCT[j0 * 72 + srow]           = c0;
            SCT[(j0 + 1) * 72 + srow]     = c1;
            SCT[j0 * 72 + srow + 8]       = c2;
            SCT[(j0 + 1) * 72 + srow + 8] = c3;
        }
    }
    __syncthreads();

    // softmax: 4 threads per query row
    {
        const int sr = tid >> 2;
        const int qd = tid & 3;
        float mx = -1e30f;
#pragma unroll
        for (int jj = 0; jj < 32; jj++) {
            int j = jj * 4 + qd;
            mx = fmaxf(mx, SCT[j * 72 + sr]);
        }
        mx = fmaxf(mx, __shfl_xor_sync(0xffffffffu, mx, 1));
        mx = fmaxf(mx, __shfl_xor_sync(0xffffffffu, mx, 2));
        float se = 0.f;
#pragma unroll
        for (int jj = 0; jj < 32; jj++) {
            int j = jj * 4 + qd;
            float e = __expf(SCT[j * 72 + sr] - mx);
            SCT[j * 72 + sr] = e;
            se += e;
        }
        se += __shfl_xor_sync(0xffffffffu, se, 1);
        se += __shfl_xor_sync(0xffffffffu, se, 2);
        float inv = 1.0f / se;
#pragma unroll
        for (int jj = 0; jj < 32; jj++) {
            int j = jj * 4 + qd;
            SCT[j * 72 + sr] *= inv;
        }
    }
    __syncthreads();

    // split probs to bf16 hi/lo
    for (int i = tid; i < 8192; i += 256) {
        int s = i & 63, j = i >> 6;
        float p = SCT[j * 72 + s];
        bf16 hp = __float2bfloat16_rn(p);
        SPH[s * AP_STR + j] = hp;
        SPL[s * AP_STR + j] = __float2bfloat16_rn(p - __bfloat162float(hp));
    }
    __syncthreads();

    // PV via mma: warp tile 16(s) x 32(d); epilogue -> single fp16
    {
        const int wm = wid & 3, wn = wid >> 2;
        float oacc[4][4] = {};
#pragma unroll
        for (int k16 = 0; k16 < 128; k16 += 16) {
            unsigned poff = (wm * 16 + qr + ((quad & 1) << 3)) * AP_STR
                            + k16 + ((quad >> 1) << 3);
            unsigned pH[4], pL[4];
            ldsm4(pH, smem_u32(SPH + poff));
            ldsm4(pL, smem_u32(SPL + poff));
#pragma unroll
            for (int nt = 0; nt < 2; nt++) {
                unsigned voff = (wn * 32 + nt * 16 + qr + ((quad >> 1) << 3)) * AV_STR
                                + k16 + ((quad & 1) << 3);
                unsigned vH[4], vL[4];
                ldsm4(vH, smem_u32(SVTH + voff));
                ldsm4(vL, smem_u32(SVTL + voff));
                mma16816(oacc[nt * 2],     pH, vH);
                mma16816(oacc[nt * 2 + 1], pH, vH + 2);
                mma16816(oacc[nt * 2],     pH, vL);
                mma16816(oacc[nt * 2 + 1], pH, vL + 2);
                mma16816(oacc[nt * 2],     pL, vH);
                mma16816(oacc[nt * 2 + 1], pL, vH + 2);
            }
        }
        const int srow = wm * 16 + (lane >> 2);
        const size_t obase = ((size_t)(b * L_ + n2 * BS_)) * D_ + h * HD_;
#pragma unroll
        for (int p = 0; p < 4; p++) {
            int d0 = wn * 32 + (p >> 1) * 16 + (p & 1) * 8 + (lane & 3) * 2;
#pragma unroll
            for (int rr = 0; rr < 2; rr++) {
                float v0 = oacc[p][rr * 2], v1 = oacc[p][rr * 2 + 1];
                size_t o = obase + (size_t)(srow + rr * 8) * D_ + d0;
                *(__half2*)(ath + o) =
                    __half2(__float2half_rn(v0), __float2half_rn(v1));
            }
        }
    }
}

// ---------------- launch ----------------
extern "C" void kernel_launch(void* const* d_in, const int* in_sizes, int n_in,
                              void* d_out, int out_size)
{
    const float* x      = (const float*)d_in[0];
    const float* gumbel = (const float*)d_in[1];
    const float* W_qkv  = (const float*)d_in[2];
    const float* b_qkv  = (const float*)d_in[3];
    const float* W_out  = (const float*)d_in[4];
    const float* b_out  = (const float*)d_in[5];
    float* out = (float*)d_out;

    float *qkv, *qr, *kr, *P, *ks, *vs;
    f16 *xh, *w1h, *w2h, *ath;
    cudaGetSymbolAddress((void**)&qkv, g_qkv);
    cudaGetSymbolAddress((void**)&qr,  g_qrepr);
    cudaGetSymbolAddress((void**)&kr,  g_krepr);
    cudaGetSymbolAddress((void**)&P,   g_P);
    cudaGetSymbolAddress((void**)&ks,  g_ksort);
    cudaGetSymbolAddress((void**)&vs,  g_vsort);
    cudaGetSymbolAddress((void**)&xh,  g_xh);
    cudaGetSymbolAddress((void**)&w1h, g_w1h);
    cudaGetSymbolAddress((void**)&w2h, g_w2h);
    cudaGetSymbolAddress((void**)&ath, g_ath);

    cudaFuncSetAttribute(attn_kernel,
                         cudaFuncAttributeMaxDynamicSharedMemorySize, ATTN_SMEM);
    cudaFuncSetAttribute(hgemm1_kernel,
                         cudaFuncAttributeMaxDynamicSharedMemorySize, GEMM_SMEM);

    // conversions
    splitx_kernel<<<(M_ * D_ / 4 + 255) / 256, 256>>>(x, xh, M_ * D_ / 4);
    wconv_kernel<<<dim3(TD_ / 32, D_ / 32), dim3(32, 8)>>>(W_qkv, w1h, D_, TD_);
    wconv_kernel<<<dim3(D_ / 32, D_ / 32), dim3(32, 8)>>>(W_out, w2h, D_, D_);

    // 1) qkv = x @ W_qkv + b_qkv   (single fp16)
    hgemm1_kernel<<<dim3(TD_ / 256, M_ / 128), 256, GEMM_SMEM>>>(
        xh, w1h, b_qkv, qkv, M_, TD_, D_);

    // 2) block mean reprs
    repr_kernel<<<(B_ * H_ * NB_ * HD_) / 256, 256>>>(qkv, qr, kr);

    // 3) sinkhorn -> P
    sinkhorn_kernel<<<B_ * H_, 256>>>(qr, kr, gumbel, P);

    // 4) soft-permute K/V blocks
    sortkv_kernel<<<dim3(B_ * H_, (BS_ * HD_) / 256, 2), 256>>>(qkv, P, ks, vs);

    // 5) tensor-core block attention -> single fp16
    attn_kernel<<<B_ * H_ * NB_, 256, ATTN_SMEM>>>(qkv, ks, vs, ath);

    // 6) out = attn @ W_out + b_out  (single fp16)
    hgemm1_kernel<<<dim3(D_ / 256, M_ / 128), 256, GEMM_SMEM>>>(
        ath, w2h, b_out, out, M_, D_, D_);
}

// round 9
// speedup vs baseline: 3.6774x; 1.1442x over previous
#include <cuda_runtime.h>
#include <cuda_bf16.h>
#include <cuda_fp16.h>
#include <cstdint>

// ---------------- problem constants ----------------
#define B_   4
#define L_   4096
#define D_   1024
#define H_   16
#define BS_  64
#define HD_  64
#define NB_  64
#define TD_  3072           // 3*D
#define M_   (B_*L_)        // 16384
#define SCALE_ 0.125f       // HD^-0.5
#define TEMP_  0.7f

typedef __half f16;

// ---------------- device scratch (allocation-free) ----------------
__device__ float g_qkv  [B_*L_*TD_];            // fp32 qkv (repr/sinkhorn/sortkv)
__device__ f16   g_qkv16[B_*L_*TD_];            // fp16 qkv (attn)
__device__ float g_qrepr[B_*H_*NB_*HD_];
__device__ float g_krepr[B_*H_*NB_*HD_];
__device__ float g_P    [B_*H_*NB_*NB_];
__device__ f16   g_ks16 [B_*H_*NB_*BS_*HD_];    // sorted K fp16
__device__ f16   g_vs16 [B_*H_*NB_*BS_*HD_];    // sorted V fp16
__device__ f16   g_xh   [M_*D_];                // x fp16
__device__ f16   g_w1h  [TD_*D_];               // W_qkv^T fp16 [3072][1024]
__device__ f16   g_w2h  [D_*D_];                // W_out^T fp16
__device__ f16   g_ath  [M_*D_];                // attn out fp16

// ---------------- PTX helpers ----------------
__device__ __forceinline__ unsigned smem_u32(const void* p) {
    return (unsigned)__cvta_generic_to_shared(p);
}
__device__ __forceinline__ void ldsm4(unsigned* r, unsigned addr) {
    asm volatile("ldmatrix.sync.aligned.m8n8.x4.shared.b16 {%0,%1,%2,%3}, [%4];\n"
                 : "=r"(r[0]), "=r"(r[1]), "=r"(r[2]), "=r"(r[3]) : "r"(addr));
}
__device__ __forceinline__ void ldsm4t(unsigned* r, unsigned addr) {
    asm volatile("ldmatrix.sync.aligned.m8n8.x4.trans.shared.b16 {%0,%1,%2,%3}, [%4];\n"
                 : "=r"(r[0]), "=r"(r[1]), "=r"(r[2]), "=r"(r[3]) : "r"(addr));
}
__device__ __forceinline__ void mma16816h(float* c, const unsigned* a, const unsigned* b) {
    asm volatile(
        "mma.sync.aligned.m16n8k16.row.col.f32.f16.f16.f32 "
        "{%0,%1,%2,%3}, {%4,%5,%6,%7}, {%8,%9}, {%0,%1,%2,%3};\n"
        : "+f"(c[0]), "+f"(c[1]), "+f"(c[2]), "+f"(c[3])
        : "r"(a[0]), "r"(a[1]), "r"(a[2]), "r"(a[3]), "r"(b[0]), "r"(b[1]));
}
#define CP_ASYNC16(dst, src) \
    asm volatile("cp.async.cg.shared.global [%0], [%1], 16;\n" :: "r"(dst), "l"(src))
#define CP_COMMIT() asm volatile("cp.async.commit_group;\n")
#define CP_WAIT(n)  asm volatile("cp.async.wait_group %0;\n" :: "n"(n))

// ---------------- single-fp16 tensor-core GEMM (+ optional fp16 copy out) ----------------
#define TSTRIDE 40
#define SA_H    0
#define SB_H    (128 * TSTRIDE)
#define STG_E   (SB_H + 256 * TSTRIDE)     // 15360 elems / stage
#define NSTG    3
#define GEMM_SMEM (NSTG * STG_E * 2)       // 92160 bytes

__global__ __launch_bounds__(256, 1) void hgemm1_kernel(
    const f16* __restrict__ A, const f16* __restrict__ Bt,
    const float* __restrict__ bias, float* __restrict__ C,
    f16* __restrict__ C16,
    int M, int N, int K)
{
    extern __shared__ f16 sm[];
    const uint32_t smb = smem_u32(sm);
    const int tid = threadIdx.x;
    const int lane = tid & 31, wid = tid >> 5;
    const int wm = wid & 1, wn = wid >> 1;       // 2x4 warp grid
    const int quad = lane >> 3, qr = lane & 7;

    const int aRow0 = blockIdx.y * 128;
    const int bRow0 = blockIdx.x * 256;
    const int nchunks = K >> 5;

    auto prefetch = [&](int stg, int k0) {
#pragma unroll
        for (int it = 0; it < 6; it++) {
            int c = tid + it * 256;
            int row = c >> 2;
            int ch  = c & 3;
            const f16* gsrc;
            unsigned soff;
            if (row < 128) {
                gsrc = A + (size_t)(aRow0 + row) * K + k0 + ch * 8;
                soff = SA_H + row * TSTRIDE + ch * 8;
            } else {
                int r = row - 128;
                gsrc = Bt + (size_t)(bRow0 + r) * K + k0 + ch * 8;
                soff = SB_H + r * TSTRIDE + ch * 8;
            }
            CP_ASYNC16(smb + (stg * STG_E + soff) * 2, gsrc);
        }
        CP_COMMIT();
    };

    prefetch(0, 0);
    prefetch(1, 32);

    float acc[4][8][4] = {};
    int sidx = 0, pidx = 2;

    for (int ck = 0; ck < nchunks; ck++) {
        if (ck < nchunks - 1) { CP_WAIT(1); } else { CP_WAIT(0); }
        __syncthreads();

        if (ck + 2 < nchunks) {
            prefetch(pidx, (ck + 2) << 5);
            pidx = (pidx == 2) ? 0 : pidx + 1;
        }

        const f16* st = sm + sidx * STG_E;
        sidx = (sidx == 2) ? 0 : sidx + 1;
#pragma unroll
        for (int kk = 0; kk < 32; kk += 16) {
            unsigned af[4][4];
#pragma unroll
            for (int mt = 0; mt < 4; mt++) {
                int arow = wm * 64 + mt * 16 + qr + ((quad & 1) << 3);
                int acol = kk + ((quad >> 1) << 3);
                ldsm4(af[mt], smem_u32(st + SA_H + arow * TSTRIDE + acol));
            }
#pragma unroll
            for (int np = 0; np < 4; np++) {
                int brow = wn * 64 + np * 16 + qr + ((quad >> 1) << 3);
                int bcol = kk + ((quad & 1) << 3);
                unsigned bf[4];
                ldsm4(bf, smem_u32(st + SB_H + brow * TSTRIDE + bcol));
#pragma unroll
                for (int mt = 0; mt < 4; mt++) {
                    mma16816h(acc[mt][np * 2],     af[mt], bf);
                    mma16816h(acc[mt][np * 2 + 1], af[mt], bf + 2);
                }
            }
        }
    }

    const int gr0 = blockIdx.y * 128 + wm * 64 + (lane >> 2);
    const int gc0 = blockIdx.x * 256 + wn * 64 + (lane & 3) * 2;
#pragma unroll
    for (int mt = 0; mt < 4; mt++) {
#pragma unroll
        for (int nt = 0; nt < 8; nt++) {
            int r = gr0 + mt * 16;
            int c = gc0 + nt * 8;
            float b0 = bias[c], b1 = bias[c + 1];
            float v00 = acc[mt][nt][0] + b0, v01 = acc[mt][nt][1] + b1;
            float v10 = acc[mt][nt][2] + b0, v11 = acc[mt][nt][3] + b1;
            *(float2*)(C + (size_t)r * N + c)       = make_float2(v00, v01);
            *(float2*)(C + (size_t)(r + 8) * N + c) = make_float2(v10, v11);
            if (C16) {
                *(__half2*)(C16 + (size_t)r * N + c) =
                    __half2(__float2half_rn(v00), __float2half_rn(v01));
                *(__half2*)(C16 + (size_t)(r + 8) * N + c) =
                    __half2(__float2half_rn(v10), __float2half_rn(v11));
            }
        }
    }
}

// ---------------- x -> fp16 ----------------
__global__ void splitx_kernel(const float* __restrict__ src,
                              f16* __restrict__ dst, int n4)
{
    int i = blockIdx.x * blockDim.x + threadIdx.x;
    if (i >= n4) return;
    float4 v = ((const float4*)src)[i];
    __half2* dp = (__half2*)(dst + i * 4);
    dp[0] = __half2(__float2half_rn(v.x), __float2half_rn(v.y));
    dp[1] = __half2(__float2half_rn(v.z), __float2half_rn(v.w));
}

// ---------------- transpose + convert: W[K][N] -> T[N][K] fp16 ----------------
__global__ void wconv_kernel(const float* __restrict__ W,
                             f16* __restrict__ T, int Kd, int Nd)
{
    __shared__ float t[32][33];
    const int tx = threadIdx.x, ty = threadIdx.y;
    const int n0 = blockIdx.x * 32, k0 = blockIdx.y * 32;
#pragma unroll
    for (int j = 0; j < 4; j++)
        t[ty + j * 8][tx] = W[(size_t)(k0 + ty + j * 8) * Nd + n0 + tx];
    __syncthreads();
#pragma unroll
    for (int j = 0; j < 4; j++) {
        float v = t[tx][ty + j * 8];
        size_t idx = (size_t)(n0 + ty + j * 8) * Kd + k0 + tx;
        T[idx] = __float2half_rn(v);
    }
}

// ---------------- block mean reprs ----------------
__global__ void repr_kernel(const float* __restrict__ qkv,
                            float* __restrict__ qrepr, float* __restrict__ krepr)
{
    int idx = blockIdx.x * blockDim.x + threadIdx.x;
    int d = idx & 63;
    int n = (idx >> 6) & 63;
    int h = (idx >> 12) & 15;
    int b = idx >> 16;
    const float* base = qkv + ((size_t)(b * L_ + n * BS_)) * TD_ + h * HD_ + d;
    float sq = 0.f, sk = 0.f;
#pragma unroll 8
    for (int s = 0; s < BS_; s++) {
        sq += base[(size_t)s * TD_];
        sk += base[(size_t)s * TD_ + D_];
    }
    qrepr[idx] = sq * (1.0f / BS_);
    krepr[idx] = sk * (1.0f / BS_);
}

// ---------------- sinkhorn -> P ----------------
__global__ __launch_bounds__(256) void sinkhorn_kernel(
    const float* __restrict__ qrepr, const float* __restrict__ krepr,
    const float* __restrict__ gumbel, float* __restrict__ P)
{
    __shared__ float La[64][65];
    const int bh = blockIdx.x;
    const int tid = threadIdx.x;
    const float* qr = qrepr + bh * NB_ * HD_;
    const float* kr = krepr + bh * NB_ * HD_;

    for (int e = tid; e < NB_ * NB_; e += 256) {
        int nn = e >> 6, m = e & 63;
        float s = 0.f;
#pragma unroll 16
        for (int d = 0; d < HD_; d++) s += qr[nn * HD_ + d] * kr[m * HD_ + d];
        La[nn][m] = (s * SCALE_ + gumbel[bh * NB_ * NB_ + e]) * (1.0f / TEMP_);
    }
    __syncthreads();

    for (int it = 0; it < 7; it++) {
        if (tid < 64) {
            float mx = -1e30f;
            for (int m = 0; m < 64; m++) mx = fmaxf(mx, La[tid][m]);
            float se = 0.f;
            for (int m = 0; m < 64; m++) se += expf(La[tid][m] - mx);
            float ls = mx + logf(se);
            for (int m = 0; m < 64; m++) La[tid][m] -= ls;
        }
        __syncthreads();
        if (tid < 64) {
            float mx = -1e30f;
            for (int r = 0; r < 64; r++) mx = fmaxf(mx, La[r][tid]);
            float se = 0.f;
            for (int r = 0; r < 64; r++) se += expf(La[r][tid] - mx);
            float ls = mx + logf(se);
            for (int r = 0; r < 64; r++) La[r][tid] -= ls;
        }
        __syncthreads();
    }
    for (int e = tid; e < NB_ * NB_; e += 256)
        P[bh * NB_ * NB_ + e] = expf(La[e >> 6][e & 63]);
}

// ---------------- k/v soft permutation -> fp16, split passes ----------------
__global__ __launch_bounds__(256) void sortkv_kernel(
    const float* __restrict__ qkv, const float* __restrict__ P,
    f16* __restrict__ ks16, f16* __restrict__ vs16)
{
    const int bh = blockIdx.x;
    const int b = bh >> 4, h = bh & 15;
    const int f = blockIdx.y * 256 + threadIdx.x;
    const int s = f >> 6, d = f & 63;
    const int which = blockIdx.z;

    __shared__ float Ps[64][64];
    for (int e = threadIdx.x; e < 4096; e += 256)
        Ps[e >> 6][e & 63] = P[bh * 4096 + e];
    __syncthreads();

    const float* base = qkv + ((size_t)(b * L_ + s)) * TD_ + h * HD_ + d
                        + (which ? 2 * D_ : D_);
    float xm[64];
#pragma unroll
    for (int m = 0; m < 64; m++)
        xm[m] = base[(size_t)m * BS_ * TD_];

    f16* dst = which ? vs16 : ks16;
    const size_t obase = (size_t)bh * NB_ * BS_ * HD_ + f;
    for (int n2 = 0; n2 < 64; n2++) {
        float acc = 0.f;
#pragma unroll
        for (int m = 0; m < 64; m++) acc += Ps[n2][m] * xm[m];
        dst[obase + (size_t)n2 * BS_ * HD_] = __float2half_rn(acc);
    }
}

// ---------------- all-fp16 tensor-core block attention ----------------
// cp.async-fed; scores/PV single fp16 mma; V used via ldmatrix.trans.
#define AQ_STR 72       // f16 elems per row (144 B, conflict-free ldsm: 72 = 8*9)
#define AP_STR 136      // 136 = 8*17
#define O_SQ   0
#define O_SK   9216
#define O_SV   27648
#define O_SP   46080
#define O_SCT  63488
#define ATTN_SMEM (O_SCT + 128 * 72 * 4)   // 100352 bytes

__global__ __launch_bounds__(256) void attn_kernel(
    const f16* __restrict__ qkv16, const f16* __restrict__ ks16,
    const f16* __restrict__ vs16, f16* __restrict__ ath)
{
    extern __shared__ __align__(16) char smc[];
    const uint32_t smb = smem_u32(smc);
    f16* SQ = (f16*)(smc + O_SQ);     // [64][72]  s-major
    f16* SK = (f16*)(smc + O_SK);     // [128][72] j-major
    f16* SV = (f16*)(smc + O_SV);     // [128][72] j-major ([K][N] for trans-ldsm)
    f16* SP = (f16*)(smc + O_SP);     // [64][136] s-major probs
    float* SCT = (float*)(smc + O_SCT); // [128][72] fp32 scores

    const int blk = blockIdx.x;
    const int n2 = blk & 63;
    const int h = (blk >> 6) & 15;
    const int b = blk >> 10;
    const int bh = b * H_ + h;
    const int tid = threadIdx.x;
    const int lane = tid & 31, wid = tid >> 5;
    const int quad = lane >> 3, qr = lane & 7;
    const int nn = (n2 + 1) & 63;

    const f16* qb16 = qkv16 + ((size_t)(b * L_ + n2 * BS_)) * TD_ + h * HD_;
    const f16* kn16 = ks16 + ((size_t)(bh * NB_ + nn)) * BS_ * HD_;
    const f16* vn16 = vs16 + ((size_t)(bh * NB_ + nn)) * BS_ * HD_;

    // ---- load: 320 rows x 128B via cp.async ----
#pragma unroll
    for (int it = 0; it < 10; it++) {
        int c = tid + it * 256;      // 0..2559
        int row = c >> 3;            // 0..319
        int ch = c & 7;
        const f16* src;
        uint32_t dst;
        if (row < 64) {
            src = qb16 + (size_t)row * TD_ + ch * 8;
            dst = O_SQ + row * 144 + ch * 16;
        } else if (row < 128) {
            int s = row - 64;
            src = qb16 + D_ + (size_t)s * TD_ + ch * 8;
            dst = O_SK + s * 144 + ch * 16;
        } else if (row < 192) {
            int s = row - 128;
            src = kn16 + s * 64 + ch * 8;
            dst = O_SK + (64 + s) * 144 + ch * 16;
        } else if (row < 256) {
            int s = row - 192;
            src = qb16 + 2 * D_ + (size_t)s * TD_ + ch * 8;
            dst = O_SV + s * 144 + ch * 16;
        } else {
            int s = row - 256;
            src = vn16 + s * 64 + ch * 8;
            dst = O_SV + (64 + s) * 144 + ch * 16;
        }
        CP_ASYNC16(smb + dst, src);
    }
    CP_COMMIT();
    CP_WAIT(0);
    __syncthreads();

    // ---- scores: warp tile 16(s) x 64(j), single fp16 ----
    {
        const int wm = wid & 3, wn = wid >> 2;
        float sacc[8][4] = {};
#pragma unroll
        for (int k16 = 0; k16 < 64; k16 += 16) {
            unsigned aoff = (wm * 16 + qr + ((quad & 1) << 3)) * AQ_STR
                            + k16 + ((quad >> 1) << 3);
            unsigned aF[4];
            ldsm4(aF, smem_u32(SQ + aoff));
#pragma unroll
            for (int nt = 0; nt < 4; nt++) {
                unsigned boff = (wn * 64 + nt * 16 + qr + ((quad >> 1) << 3)) * AQ_STR
                                + k16 + ((quad & 1) << 3);
                unsigned bF[4];
                ldsm4(bF, smem_u32(SK + boff));
                mma16816h(sacc[nt * 2],     aF, bF);
                mma16816h(sacc[nt * 2 + 1], aF, bF + 2);
            }
        }
        const bool maskme = (n2 == NB_ - 1) && (wn == 1);
        const int srow = wm * 16 + (lane >> 2);
#pragma unroll
        for (int p = 0; p < 8; p++) {
            int j0 = wn * 64 + (p >> 1) * 16 + (p & 1) * 8 + (lane & 3) * 2;
            float c0 = sacc[p][0] * SCALE_, c1 = sacc[p][1] * SCALE_;
            float c2 = sacc[p][2] * SCALE_, c3 = sacc[p][3] * SCALE_;
            if (maskme) { c0 = c1 = c2 = c3 = -1e9f; }
            SCT[j0 * 72 + srow]           = c0;
            SCT[(j0 + 1) * 72 + srow]     = c1;
            SCT[j0 * 72 + srow + 8]       = c2;
            SCT[(j0 + 1) * 72 + srow + 8] = c3;
        }
    }
    __syncthreads();

    // ---- softmax: 4 threads per query row ----
    {
        const int sr = tid >> 2;
        const int qd = tid & 3;
        float mx = -1e30f;
#pragma unroll
        for (int jj = 0; jj < 32; jj++) {
            int j = jj * 4 + qd;
            mx = fmaxf(mx, SCT[j * 72 + sr]);
        }
        mx = fmaxf(mx, __shfl_xor_sync(0xffffffffu, mx, 1));
        mx = fmaxf(mx, __shfl_xor_sync(0xffffffffu, mx, 2));
        float se = 0.f;
#pragma unroll
        for (int jj = 0; jj < 32; jj++) {
            int j = jj * 4 + qd;
            float e = __expf(SCT[j * 72 + sr] - mx);
            SCT[j * 72 + sr] = e;
            se += e;
        }
        se += __shfl_xor_sync(0xffffffffu, se, 1);
        se += __shfl_xor_sync(0xffffffffu, se, 2);
        float inv = 1.0f / se;
#pragma unroll
        for (int jj = 0; jj < 32; jj++) {
            int j = jj * 4 + qd;
            SCT[j * 72 + sr] *= inv;
        }
    }
    __syncthreads();

    // ---- probs -> fp16 [64][136] s-major ----
    for (int i = tid; i < 8192; i += 256) {
        int s = i & 63, j = i >> 6;
        SP[s * AP_STR + j] = __float2half_rn(SCT[j * 72 + s]);
    }
    __syncthreads();

    // ---- PV: warp tile 16(s) x 32(d); V via trans-ldsm from [j][d] ----
    {
        const int wm = wid & 3, wn = wid >> 2;
        float oacc[4][4] = {};
#pragma unroll
        for (int k16 = 0; k16 < 128; k16 += 16) {
            unsigned poff = (wm * 16 + qr + ((quad & 1) << 3)) * AP_STR
                            + k16 + ((quad >> 1) << 3);
            unsigned pF[4];
            ldsm4(pF, smem_u32(SP + poff));
#pragma unroll
            for (int nt = 0; nt < 2; nt++) {
                // trans: row = k (j-index), col = n (d-index)
                unsigned voff = (k16 + qr + ((quad & 1) << 3)) * AQ_STR
                                + wn * 32 + nt * 16 + ((quad >> 1) << 3);
                unsigned vF[4];
                ldsm4t(vF, smem_u32(SV + voff));
                mma16816h(oacc[nt * 2],     pF, vF);
                mma16816h(oacc[nt * 2 + 1], pF, vF + 2);
            }
        }
        const int srow = wm * 16 + (lane >> 2);
        const size_t obase = ((size_t)(b * L_ + n2 * BS_)) * D_ + h * HD_;
#pragma unroll
        for (int p = 0; p < 4; p++) {
            int d0 = wn * 32 + (p >> 1) * 16 + (p & 1) * 8 + (lane & 3) * 2;
#pragma unroll
            for (int rr = 0; rr < 2; rr++) {
                float v0 = oacc[p][rr * 2], v1 = oacc[p][rr * 2 + 1];
                size_t o = obase + (size_t)(srow + rr * 8) * D_ + d0;
                *(__half2*)(ath + o) =
                    __half2(__float2half_rn(v0), __float2half_rn(v1));
            }
        }
    }
}

// ---------------- launch ----------------
extern "C" void kernel_launch(void* const* d_in, const int* in_sizes, int n_in,
                              void* d_out, int out_size)
{
    const float* x      = (const float*)d_in[0];
    const float* gumbel = (const float*)d_in[1];
    const float* W_qkv  = (const float*)d_in[2];
    const float* b_qkv  = (const float*)d_in[3];
    const float* W_out  = (const float*)d_in[4];
    const float* b_out  = (const float*)d_in[5];
    float* out = (float*)d_out;

    float *qkv, *qr, *kr, *P;
    f16 *qkv16, *ks16, *vs16, *xh, *w1h, *w2h, *ath;
    cudaGetSymbolAddress((void**)&qkv,   g_qkv);
    cudaGetSymbolAddress((void**)&qkv16, g_qkv16);
    cudaGetSymbolAddress((void**)&qr,  g_qrepr);
    cudaGetSymbolAddress((void**)&kr,  g_krepr);
    cudaGetSymbolAddress((void**)&P,   g_P);
    cudaGetSymbolAddress((void**)&ks16, g_ks16);
    cudaGetSymbolAddress((void**)&vs16, g_vs16);
    cudaGetSymbolAddress((void**)&xh,  g_xh);
    cudaGetSymbolAddress((void**)&w1h, g_w1h);
    cudaGetSymbolAddress((void**)&w2h, g_w2h);
    cudaGetSymbolAddress((void**)&ath, g_ath);

    cudaFuncSetAttribute(attn_kernel,
                         cudaFuncAttributeMaxDynamicSharedMemorySize, ATTN_SMEM);
    cudaFuncSetAttribute(hgemm1_kernel,
                         cudaFuncAttributeMaxDynamicSharedMemorySize, GEMM_SMEM);

    // conversions
    splitx_kernel<<<(M_ * D_ / 4 + 255) / 256, 256>>>(x, xh, M_ * D_ / 4);
    wconv_kernel<<<dim3(TD_ / 32, D_ / 32), dim3(32, 8)>>>(W_qkv, w1h, D_, TD_);
    wconv_kernel<<<dim3(D_ / 32, D_ / 32), dim3(32, 8)>>>(W_out, w2h, D_, D_);

    // 1) qkv = x @ W_qkv + b_qkv  (fp32 + fp16 copy)
    hgemm1_kernel<<<dim3(TD_ / 256, M_ / 128), 256, GEMM_SMEM>>>(
        xh, w1h, b_qkv, qkv, qkv16, M_, TD_, D_);

    // 2) block mean reprs
    repr_kernel<<<(B_ * H_ * NB_ * HD_) / 256, 256>>>(qkv, qr, kr);

    // 3) sinkhorn -> P
    sinkhorn_kernel<<<B_ * H_, 256>>>(qr, kr, gumbel, P);

    // 4) soft-permute K/V blocks -> fp16
    sortkv_kernel<<<dim3(B_ * H_, (BS_ * HD_) / 256, 2), 256>>>(qkv, P, ks16, vs16);

    // 5) all-fp16 tensor-core attention
    attn_kernel<<<B_ * H_ * NB_, 256, ATTN_SMEM>>>(qkv16, ks16, vs16, ath);

    // 6) out = attn @ W_out + b_out
    hgemm1_kernel<<<dim3(D_ / 256, M_ / 128), 256, GEMM_SMEM>>>(
        ath, w2h, b_out, out, (f16*)nullptr, M_, D_, D_);
}

// round 12
// speedup vs baseline: 4.1941x; 1.1405x over previous
#include <cuda_runtime.h>
#include <cuda_fp16.h>
#include <cstdint>

// ---------------- problem constants ----------------
#define B_   4
#define L_   4096
#define D_   1024
#define H_   16
#define BS_  64
#define HD_  64
#define NB_  64
#define TD_  3072           // 3*D
#define M_   (B_*L_)        // 16384
#define SCALE_ 0.125f       // HD^-0.5
#define TEMP_  0.7f

typedef __half f16;

// ---------------- device scratch (allocation-free) ----------------
__device__ f16   g_qkv16[B_*L_*TD_];            // fp16 qkv (all consumers)
__device__ float g_qrepr[B_*H_*NB_*HD_];
__device__ float g_krepr[B_*H_*NB_*HD_];
__device__ float g_P    [B_*H_*NB_*NB_];
__device__ f16   g_ks16 [B_*H_*NB_*BS_*HD_];    // sorted K fp16
__device__ f16   g_vs16 [B_*H_*NB_*BS_*HD_];    // sorted V fp16
__device__ f16   g_xh   [M_*D_];                // x fp16
__device__ f16   g_w1h  [TD_*D_];               // W_qkv^T fp16 [3072][1024]
__device__ f16   g_w2h  [D_*D_];                // W_out^T fp16
__device__ f16   g_ath  [M_*D_];                // attn out fp16

// ---------------- PTX helpers ----------------
__device__ __forceinline__ unsigned smem_u32(const void* p) {
    return (unsigned)__cvta_generic_to_shared(p);
}
__device__ __forceinline__ void ldsm4(unsigned* r, unsigned addr) {
    asm volatile("ldmatrix.sync.aligned.m8n8.x4.shared.b16 {%0,%1,%2,%3}, [%4];\n"
                 : "=r"(r[0]), "=r"(r[1]), "=r"(r[2]), "=r"(r[3]) : "r"(addr));
}
__device__ __forceinline__ void ldsm4t(unsigned* r, unsigned addr) {
    asm volatile("ldmatrix.sync.aligned.m8n8.x4.trans.shared.b16 {%0,%1,%2,%3}, [%4];\n"
                 : "=r"(r[0]), "=r"(r[1]), "=r"(r[2]), "=r"(r[3]) : "r"(addr));
}
__device__ __forceinline__ void mma16816h(float* c, const unsigned* a, const unsigned* b) {
    asm volatile(
        "mma.sync.aligned.m16n8k16.row.col.f32.f16.f16.f32 "
        "{%0,%1,%2,%3}, {%4,%5,%6,%7}, {%8,%9}, {%0,%1,%2,%3};\n"
        : "+f"(c[0]), "+f"(c[1]), "+f"(c[2]), "+f"(c[3])
        : "r"(a[0]), "r"(a[1]), "r"(a[2]), "r"(a[3]), "r"(b[0]), "r"(b[1]));
}
#define CP_ASYNC16(dst, src) \
    asm volatile("cp.async.cg.shared.global [%0], [%1], 16;\n" :: "r"(dst), "l"(src))
#define CP_COMMIT() asm volatile("cp.async.commit_group;\n")
#define CP_WAIT(n)  asm volatile("cp.async.wait_group %0;\n" :: "n"(n))

// ---------------- single-fp16 GEMM: 128x128 tile, 8 warps 32x64, 2 CTAs/SM ----------------
// C[M,N] = A[M,K] @ B[K,N] + bias[N]; B^T supplied as [N][K].
// Outputs: C fp32 (if non-null) and/or C16 fp16 (if non-null).
#define TSTRIDE 40
#define SA_H    0
#define SB_H    (128 * TSTRIDE)            // 5120
#define STG_E   (SB_H + 128 * TSTRIDE)     // 10240 elems / stage
#define NSTG    3
#define GEMM_SMEM (NSTG * STG_E * 2)       // 61440 bytes -> 2 CTAs/SM

__global__ __launch_bounds__(256, 2) void hgemm1_kernel(
    const f16* __restrict__ A, const f16* __restrict__ Bt,
    const float* __restrict__ bias, float* __restrict__ C,
    f16* __restrict__ C16,
    int M, int N, int K)
{
    extern __shared__ f16 sm[];
    const uint32_t smb = smem_u32(sm);
    const int tid = threadIdx.x;
    const int lane = tid & 31, wid = tid >> 5;
    const int wm = wid & 3, wn = wid >> 2;       // 4x2 warp grid, warp tile 32x64
    const int quad = lane >> 3, qr = lane & 7;

    const int aRow0 = blockIdx.y * 128;
    const int bRow0 = blockIdx.x * 128;
    const int nchunks = K >> 5;

    // loader: 256 rows x 4 chunks = 1024 x 16B per stage, 4 per thread
    auto prefetch = [&](int stg, int k0) {
#pragma unroll
        for (int it = 0; it < 4; it++) {
            int c = tid + it * 256;
            int row = c >> 2;                // 0..255
            int ch  = c & 3;
            const f16* gsrc;
            unsigned soff;
            if (row < 128) {
                gsrc = A + (size_t)(aRow0 + row) * K + k0 + ch * 8;
                soff = SA_H + row * TSTRIDE + ch * 8;
            } else {
                int r = row - 128;
                gsrc = Bt + (size_t)(bRow0 + r) * K + k0 + ch * 8;
                soff = SB_H + r * TSTRIDE + ch * 8;
            }
            CP_ASYNC16(smb + (stg * STG_E + soff) * 2, gsrc);
        }
        CP_COMMIT();
    };

    prefetch(0, 0);
    prefetch(1, 32);

    float acc[2][8][4] = {};
    int sidx = 0, pidx = 2;

    for (int ck = 0; ck < nchunks; ck++) {
        if (ck < nchunks - 1) { CP_WAIT(1); } else { CP_WAIT(0); }
        __syncthreads();

        if (ck + 2 < nchunks) {
            prefetch(pidx, (ck + 2) << 5);
            pidx = (pidx == 2) ? 0 : pidx + 1;
        }

        const f16* st = sm + sidx * STG_E;
        sidx = (sidx == 2) ? 0 : sidx + 1;
#pragma unroll
        for (int kk = 0; kk < 32; kk += 16) {
            unsigned af[2][4];
#pragma unroll
            for (int mt = 0; mt < 2; mt++) {
                int arow = wm * 32 + mt * 16 + qr + ((quad & 1) << 3);
                int acol = kk + ((quad >> 1) << 3);
                ldsm4(af[mt], smem_u32(st + SA_H + arow * TSTRIDE + acol));
            }
#pragma unroll
            for (int np = 0; np < 4; np++) {
                int brow = wn * 64 + np * 16 + qr + ((quad >> 1) << 3);
                int bcol = kk + ((quad & 1) << 3);
                unsigned bf[4];
                ldsm4(bf, smem_u32(st + SB_H + brow * TSTRIDE + bcol));
#pragma unroll
                for (int mt = 0; mt < 2; mt++) {
                    mma16816h(acc[mt][np * 2],     af[mt], bf);
                    mma16816h(acc[mt][np * 2 + 1], af[mt], bf + 2);
                }
            }
        }
    }

    const int gr0 = blockIdx.y * 128 + wm * 32 + (lane >> 2);
    const int gc0 = blockIdx.x * 128 + wn * 64 + (lane & 3) * 2;
#pragma unroll
    for (int mt = 0; mt < 2; mt++) {
#pragma unroll
        for (int nt = 0; nt < 8; nt++) {
            int r = gr0 + mt * 16;
            int c = gc0 + nt * 8;
            float b0 = bias[c], b1 = bias[c + 1];
            float v00 = acc[mt][nt][0] + b0, v01 = acc[mt][nt][1] + b1;
            float v10 = acc[mt][nt][2] + b0, v11 = acc[mt][nt][3] + b1;
            if (C) {
                *(float2*)(C + (size_t)r * N + c)       = make_float2(v00, v01);
                *(float2*)(C + (size_t)(r + 8) * N + c) = make_float2(v10, v11);
            }
            if (C16) {
                *(__half2*)(C16 + (size_t)r * N + c) =
                    __half2(__float2half_rn(v00), __float2half_rn(v01));
                *(__half2*)(C16 + (size_t)(r + 8) * N + c) =
                    __half2(__float2half_rn(v10), __float2half_rn(v11));
            }
        }
    }
}

// ---------------- x -> fp16 ----------------
__global__ void splitx_kernel(const float* __restrict__ src,
                              f16* __restrict__ dst, int n4)
{
    int i = blockIdx.x * blockDim.x + threadIdx.x;
    if (i >= n4) return;
    float4 v = ((const float4*)src)[i];
    __half2* dp = (__half2*)(dst + i * 4);
    dp[0] = __half2(__float2half_rn(v.x), __float2half_rn(v.y));
    dp[1] = __half2(__float2half_rn(v.z), __float2half_rn(v.w));
}

// ---------------- transpose + convert: W[K][N] -> T[N][K] fp16 ----------------
__global__ void wconv_kernel(const float* __restrict__ W,
                             f16* __restrict__ T, int Kd, int Nd)
{
    __shared__ float t[32][33];
    const int tx = threadIdx.x, ty = threadIdx.y;
    const int n0 = blockIdx.x * 32, k0 = blockIdx.y * 32;
#pragma unroll
    for (int j = 0; j < 4; j++)
        t[ty + j * 8][tx] = W[(size_t)(k0 + ty + j * 8) * Nd + n0 + tx];
    __syncthreads();
#pragma unroll
    for (int j = 0; j < 4; j++) {
        float v = t[tx][ty + j * 8];
        size_t idx = (size_t)(n0 + ty + j * 8) * Kd + k0 + tx;
        T[idx] = __float2half_rn(v);
    }
}

// ---------------- block mean reprs (fp16 input) ----------------
__global__ void repr_kernel(const f16* __restrict__ qkv16,
                            float* __restrict__ qrepr, float* __restrict__ krepr)
{
    int idx = blockIdx.x * blockDim.x + threadIdx.x;
    int d = idx & 63;
    int n = (idx >> 6) & 63;
    int h = (idx >> 12) & 15;
    int b = idx >> 16;
    const f16* base = qkv16 + ((size_t)(b * L_ + n * BS_)) * TD_ + h * HD_ + d;
    float sq = 0.f, sk = 0.f;
#pragma unroll 8
    for (int s = 0; s < BS_; s++) {
        sq += __half2float(base[(size_t)s * TD_]);
        sk += __half2float(base[(size_t)s * TD_ + D_]);
    }
    qrepr[idx] = sq * (1.0f / BS_);
    krepr[idx] = sk * (1.0f / BS_);
}

// ---------------- sinkhorn -> P ----------------
__global__ __launch_bounds__(256) void sinkhorn_kernel(
    const float* __restrict__ qrepr, const float* __restrict__ krepr,
    const float* __restrict__ gumbel, float* __restrict__ P)
{
    __shared__ float La[64][65];
    const int bh = blockIdx.x;
    const int tid = threadIdx.x;
    const float* qr = qrepr + bh * NB_ * HD_;
    const float* kr = krepr + bh * NB_ * HD_;

    for (int e = tid; e < NB_ * NB_; e += 256) {
        int nn = e >> 6, m = e & 63;
        float s = 0.f;
#pragma unroll 16
        for (int d = 0; d < HD_; d++) s += qr[nn * HD_ + d] * kr[m * HD_ + d];
        La[nn][m] = (s * SCALE_ + gumbel[bh * NB_ * NB_ + e]) * (1.0f / TEMP_);
    }
    __syncthreads();

    for (int it = 0; it < 7; it++) {
        if (tid < 64) {
            float mx = -1e30f;
            for (int m = 0; m < 64; m++) mx = fmaxf(mx, La[tid][m]);
            float se = 0.f;
            for (int m = 0; m < 64; m++) se += expf(La[tid][m] - mx);
            float ls = mx + logf(se);
            for (int m = 0; m < 64; m++) La[tid][m] -= ls;
        }
        __syncthreads();
        if (tid < 64) {
            float mx = -1e30f;
            for (int r = 0; r < 64; r++) mx = fmaxf(mx, La[r][tid]);
            float se = 0.f;
            for (int r = 0; r < 64; r++) se += expf(La[r][tid] - mx);
            float ls = mx + logf(se);
            for (int r = 0; r < 64; r++) La[r][tid] -= ls;
        }
        __syncthreads();
    }
    for (int e = tid; e < NB_ * NB_; e += 256)
        P[bh * NB_ * NB_ + e] = expf(La[e >> 6][e & 63]);
}

// ---------------- k/v soft permutation (fp16 in/out), split passes ----------------
__global__ __launch_bounds__(256) void sortkv_kernel(
    const f16* __restrict__ qkv16, const float* __restrict__ P,
    f16* __restrict__ ks16, f16* __restrict__ vs16)
{
    const int bh = blockIdx.x;
    const int b = bh >> 4, h = bh & 15;
    const int f = blockIdx.y * 256 + threadIdx.x;
    const int s = f >> 6, d = f & 63;
    const int which = blockIdx.z;

    __shared__ float Ps[64][64];
    for (int e = threadIdx.x; e < 4096; e += 256)
        Ps[e >> 6][e & 63] = P[bh * 4096 + e];
    __syncthreads();

    const f16* base = qkv16 + ((size_t)(b * L_ + s)) * TD_ + h * HD_ + d
                      + (which ? 2 * D_ : D_);
    float xm[64];
#pragma unroll
    for (int m = 0; m < 64; m++)
        xm[m] = __half2float(base[(size_t)m * BS_ * TD_]);

    f16* dst = which ? vs16 : ks16;
    const size_t obase = (size_t)bh * NB_ * BS_ * HD_ + f;
    for (int n2 = 0; n2 < 64; n2++) {
        float acc = 0.f;
#pragma unroll
        for (int m = 0; m < 64; m++) acc += Ps[n2][m] * xm[m];
        dst[obase + (size_t)n2 * BS_ * HD_] = __float2half_rn(acc);
    }
}

// ---------------- all-fp16 tensor-core block attention ----------------
#define AQ_STR 72
#define AP_STR 136
#define O_SQ   0
#define O_SK   9216
#define O_SV   27648
#define O_SP   46080
#define O_SCT  63488
#define ATTN_SMEM (O_SCT + 128 * 72 * 4)   // 100352 bytes

__global__ __launch_bounds__(256) void attn_kernel(
    const f16* __restrict__ qkv16, const f16* __restrict__ ks16,
    const f16* __restrict__ vs16, f16* __restrict__ ath)
{
    extern __shared__ __align__(16) char smc[];
    const uint32_t smb = smem_u32(smc);
    f16* SQ = (f16*)(smc + O_SQ);     // [64][72]  s-major
    f16* SK = (f16*)(smc + O_SK);     // [128][72] j-major
    f16* SV = (f16*)(smc + O_SV);     // [128][72] j-major ([K][N] for trans-ldsm)
    f16* SP = (f16*)(smc + O_SP);     // [64][136] s-major probs
    float* SCT = (float*)(smc + O_SCT); // [128][72] fp32 scores

    const int blk = blockIdx.x;
    const int n2 = blk & 63;
    const int h = (blk >> 6) & 15;
    const int b = blk >> 10;
    const int bh = b * H_ + h;
    const int tid = threadIdx.x;
    const int lane = tid & 31, wid = tid >> 5;
    const int quad = lane >> 3, qr = lane & 7;
    const int nn = (n2 + 1) & 63;

    const f16* qb16 = qkv16 + ((size_t)(b * L_ + n2 * BS_)) * TD_ + h * HD_;
    const f16* kn16 = ks16 + ((size_t)(bh * NB_ + nn)) * BS_ * HD_;
    const f16* vn16 = vs16 + ((size_t)(bh * NB_ + nn)) * BS_ * HD_;

#pragma unroll
    for (int it = 0; it < 10; it++) {
        int c = tid + it * 256;      // 0..2559
        int row = c >> 3;            // 0..319
        int ch = c & 7;
        const f16* src;
        uint32_t dst;
        if (row < 64) {
            src = qb16 + (size_t)row * TD_ + ch * 8;
            dst = O_SQ + row * 144 + ch * 16;
        } else if (row < 128) {
            int s = row - 64;
            src = qb16 + D_ + (size_t)s * TD_ + ch * 8;
            dst = O_SK + s * 144 + ch * 16;
        } else if (row < 192) {
            int s = row - 128;
            src = kn16 + s * 64 + ch * 8;
            dst = O_SK + (64 + s) * 144 + ch * 16;
        } else if (row < 256) {
            int s = row - 192;
            src = qb16 + 2 * D_ + (size_t)s * TD_ + ch * 8;
            dst = O_SV + s * 144 + ch * 16;
        } else {
            int s = row - 256;
            src = vn16 + s * 64 + ch * 8;
            dst = O_SV + (64 + s) * 144 + ch * 16;
        }
        CP_ASYNC16(smb + dst, src);
    }
    CP_COMMIT();
    CP_WAIT(0);
    __syncthreads();

    // scores: warp tile 16(s) x 64(j)
    {
        const int wm = wid & 3, wn = wid >> 2;
        float sacc[8][4] = {};
#pragma unroll
        for (int k16 = 0; k16 < 64; k16 += 16) {
            unsigned aoff = (wm * 16 + qr + ((quad & 1) << 3)) * AQ_STR
                            + k16 + ((quad >> 1) << 3);
            unsigned aF[4];
            ldsm4(aF, smem_u32(SQ + aoff));
#pragma unroll
            for (int nt = 0; nt < 4; nt++) {
                unsigned boff = (wn * 64 + nt * 16 + qr + ((quad >> 1) << 3)) * AQ_STR
                                + k16 + ((quad & 1) << 3);
                unsigned bF[4];
                ldsm4(bF, smem_u32(SK + boff));
                mma16816h(sacc[nt * 2],     aF, bF);
                mma16816h(sacc[nt * 2 + 1], aF, bF + 2);
            }
        }
        const bool maskme = (n2 == NB_ - 1) && (wn == 1);
        const int srow = wm * 16 + (lane >> 2);
#pragma unroll
        for (int p = 0; p < 8; p++) {
            int j0 = wn * 64 + (p >> 1) * 16 + (p & 1) * 8 + (lane & 3) * 2;
            float c0 = sacc[p][0] * SCALE_, c1 = sacc[p][1] * SCALE_;
            float c2 = sacc[p][2] * SCALE_, c3 = sacc[p][3] * SCALE_;
            if (maskme) { c0 = c1 = c2 = c3 = -1e9f; }
            SCT[j0 * 72 + srow]           = c0;
            SCT[(j0 + 1) * 72 + srow]     = c1;
            SCT[j0 * 72 + srow + 8]       = c2;
            SCT[(j0 + 1) * 72 + srow + 8] = c3;
        }
    }
    __syncthreads();

    // softmax: 4 threads per query row
    {
        const int sr = tid >> 2;
        const int qd = tid & 3;
        float mx = -1e30f;
#pragma unroll
        for (int jj = 0; jj < 32; jj++) {
            int j = jj * 4 + qd;
            mx = fmaxf(mx, SCT[j * 72 + sr]);
        }
        mx = fmaxf(mx, __shfl_xor_sync(0xffffffffu, mx, 1));
        mx = fmaxf(mx, __shfl_xor_sync(0xffffffffu, mx, 2));
        float se = 0.f;
#pragma unroll
        for (int jj = 0; jj < 32; jj++) {
            int j = jj * 4 + qd;
            float e = __expf(SCT[j * 72 + sr] - mx);
            SCT[j * 72 + sr] = e;
            se += e;
        }
        se += __shfl_xor_sync(0xffffffffu, se, 1);
        se += __shfl_xor_sync(0xffffffffu, se, 2);
        float inv = 1.0f / se;
#pragma unroll
        for (int jj = 0; jj < 32; jj++) {
            int j = jj * 4 + qd;
            SCT[j * 72 + sr] *= inv;
        }
    }
    __syncthreads();

    // probs -> fp16 [64][136] s-major
    for (int i = tid; i < 8192; i += 256) {
        int s = i & 63, j = i >> 6;
        SP[s * AP_STR + j] = __float2half_rn(SCT[j * 72 + s]);
    }
    __syncthreads();

    // PV: warp tile 16(s) x 32(d); V via trans-ldsm from [j][d]
    {
        const int wm = wid & 3, wn = wid >> 2;
        float oacc[4][4] = {};
#pragma unroll
        for (int k16 = 0; k16 < 128; k16 += 16) {
            unsigned poff = (wm * 16 + qr + ((quad & 1) << 3)) * AP_STR
                            + k16 + ((quad >> 1) << 3);
            unsigned pF[4];
            ldsm4(pF, smem_u32(SP + poff));
#pragma unroll
            for (int nt = 0; nt < 2; nt++) {
                unsigned voff = (k16 + qr + ((quad & 1) << 3)) * AQ_STR
                                + wn * 32 + nt * 16 + ((quad >> 1) << 3);
                unsigned vF[4];
                ldsm4t(vF, smem_u32(SV + voff));
                mma16816h(oacc[nt * 2],     pF, vF);
                mma16816h(oacc[nt * 2 + 1], pF, vF + 2);
            }
        }
        const int srow = wm * 16 + (lane >> 2);
        const size_t obase = ((size_t)(b * L_ + n2 * BS_)) * D_ + h * HD_;
#pragma unroll
        for (int p = 0; p < 4; p++) {
            int d0 = wn * 32 + (p >> 1) * 16 + (p & 1) * 8 + (lane & 3) * 2;
#pragma unroll
            for (int rr = 0; rr < 2; rr++) {
                float v0 = oacc[p][rr * 2], v1 = oacc[p][rr * 2 + 1];
                size_t o = obase + (size_t)(srow + rr * 8) * D_ + d0;
                *(__half2*)(ath + o) =
                    __half2(__float2half_rn(v0), __float2half_rn(v1));
            }
        }
    }
}

// ---------------- launch ----------------
extern "C" void kernel_launch(void* const* d_in, const int* in_sizes, int n_in,
                              void* d_out, int out_size)
{
    const float* x      = (const float*)d_in[0];
    const float* gumbel = (const float*)d_in[1];
    const float* W_qkv  = (const float*)d_in[2];
    const float* b_qkv  = (const float*)d_in[3];
    const float* W_out  = (const float*)d_in[4];
    const float* b_out  = (const float*)d_in[5];
    float* out = (float*)d_out;

    float *qr, *kr, *P;
    f16 *qkv16, *ks16, *vs16, *xh, *w1h, *w2h, *ath;
    cudaGetSymbolAddress((void**)&qkv16, g_qkv16);
    cudaGetSymbolAddress((void**)&qr,  g_qrepr);
    cudaGetSymbolAddress((void**)&kr,  g_krepr);
    cudaGetSymbolAddress((void**)&P,   g_P);
    cudaGetSymbolAddress((void**)&ks16, g_ks16);
    cudaGetSymbolAddress((void**)&vs16, g_vs16);
    cudaGetSymbolAddress((void**)&xh,  g_xh);
    cudaGetSymbolAddress((void**)&w1h, g_w1h);
    cudaGetSymbolAddress((void**)&w2h, g_w2h);
    cudaGetSymbolAddress((void**)&ath, g_ath);

    cudaFuncSetAttribute(attn_kernel,
                         cudaFuncAttributeMaxDynamicSharedMemorySize, ATTN_SMEM);
    cudaFuncSetAttribute(hgemm1_kernel,
                         cudaFuncAttributeMaxDynamicSharedMemorySize, GEMM_SMEM);

    // conversions
    splitx_kernel<<<(M_ * D_ / 4 + 255) / 256, 256>>>(x, xh, M_ * D_ / 4);
    wconv_kernel<<<dim3(TD_ / 32, D_ / 32), dim3(32, 8)>>>(W_qkv, w1h, D_, TD_);
    wconv_kernel<<<dim3(D_ / 32, D_ / 32), dim3(32, 8)>>>(W_out, w2h, D_, D_);

    // 1) qkv = x @ W_qkv + b_qkv  (fp16 output only)
    hgemm1_kernel<<<dim3(TD_ / 128, M_ / 128), 256, GEMM_SMEM>>>(
        xh, w1h, b_qkv, (float*)nullptr, qkv16, M_, TD_, D_);

    // 2) block mean reprs (fp16 input)
    repr_kernel<<<(B_ * H_ * NB_ * HD_) / 256, 256>>>(qkv16, qr, kr);

    // 3) sinkhorn -> P
    sinkhorn_kernel<<<B_ * H_, 256>>>(qr, kr, gumbel, P);

    // 4) soft-permute K/V blocks (fp16 in/out)
    sortkv_kernel<<<dim3(B_ * H_, (BS_ * HD_) / 256, 2), 256>>>(qkv16, P, ks16, vs16);

    // 5) all-fp16 tensor-core attention
    attn_kernel<<<B_ * H_ * NB_, 256, ATTN_SMEM>>>(qkv16, ks16, vs16, ath);

    // 6) out = attn @ W_out + b_out  (fp32 output)
    hgemm1_kernel<<<dim3(D_ / 128, M_ / 128), 256, GEMM_SMEM>>>(
        ath, w2h, b_out, out, (f16*)nullptr, M_, D_, D_);
}

// round 13
// speedup vs baseline: 4.8633x; 1.1596x over previous
#include <cuda_runtime.h>
#include <cuda_fp16.h>
#include <cstdint>

// ---------------- problem constants ----------------
#define B_   4
#define L_   4096
#define D_   1024
#define H_   16
#define BS_  64
#define HD_  64
#define NB_  64
#define TD_  3072           // 3*D
#define M_   (B_*L_)        // 16384
#define SCALE_ 0.125f       // HD^-0.5
#define TEMP_  0.7f

typedef __half f16;

// ---------------- device scratch (allocation-free) ----------------
__device__ f16   g_qkv16[B_*L_*TD_];            // fp16 qkv (all consumers)
__device__ float g_qrepr[B_*H_*NB_*HD_];
__device__ float g_krepr[B_*H_*NB_*HD_];
__device__ f16   g_phi  [B_*H_*NB_*NB_];        // P hi (fp16)
__device__ f16   g_plo  [B_*H_*NB_*NB_];        // P lo (fp16 residual)
__device__ f16   g_ks16 [B_*H_*NB_*BS_*HD_];    // sorted K fp16
__device__ f16   g_vs16 [B_*H_*NB_*BS_*HD_];    // sorted V fp16
__device__ f16   g_xh   [M_*D_];                // x fp16
__device__ f16   g_w1h  [TD_*D_];               // W_qkv^T fp16 [3072][1024]
__device__ f16   g_w2h  [D_*D_];                // W_out^T fp16
__device__ f16   g_ath  [M_*D_];                // attn out fp16

// ---------------- PTX helpers ----------------
__device__ __forceinline__ unsigned smem_u32(const void* p) {
    return (unsigned)__cvta_generic_to_shared(p);
}
__device__ __forceinline__ void ldsm4(unsigned* r, unsigned addr) {
    asm volatile("ldmatrix.sync.aligned.m8n8.x4.shared.b16 {%0,%1,%2,%3}, [%4];\n"
                 : "=r"(r[0]), "=r"(r[1]), "=r"(r[2]), "=r"(r[3]) : "r"(addr));
}
__device__ __forceinline__ void ldsm4t(unsigned* r, unsigned addr) {
    asm volatile("ldmatrix.sync.aligned.m8n8.x4.trans.shared.b16 {%0,%1,%2,%3}, [%4];\n"
                 : "=r"(r[0]), "=r"(r[1]), "=r"(r[2]), "=r"(r[3]) : "r"(addr));
}
__device__ __forceinline__ void mma16816h(float* c, const unsigned* a, const unsigned* b) {
    asm volatile(
        "mma.sync.aligned.m16n8k16.row.col.f32.f16.f16.f32 "
        "{%0,%1,%2,%3}, {%4,%5,%6,%7}, {%8,%9}, {%0,%1,%2,%3};\n"
        : "+f"(c[0]), "+f"(c[1]), "+f"(c[2]), "+f"(c[3])
        : "r"(a[0]), "r"(a[1]), "r"(a[2]), "r"(a[3]), "r"(b[0]), "r"(b[1]));
}
#define CP_ASYNC16(dst, src) \
    asm volatile("cp.async.cg.shared.global [%0], [%1], 16;\n" :: "r"(dst), "l"(src))
#define CP_COMMIT() asm volatile("cp.async.commit_group;\n")
#define CP_WAIT(n)  asm volatile("cp.async.wait_group %0;\n" :: "n"(n))

// ---------------- single-fp16 GEMM: 128x128 tile, 8 warps 32x64, 2 CTAs/SM ----------------
#define TSTRIDE 40
#define SA_H    0
#define SB_H    (128 * TSTRIDE)
#define STG_E   (SB_H + 128 * TSTRIDE)     // 10240 elems / stage
#define NSTG    3
#define GEMM_SMEM (NSTG * STG_E * 2)       // 61440 bytes

__global__ __launch_bounds__(256, 2) void hgemm1_kernel(
    const f16* __restrict__ A, const f16* __restrict__ Bt,
    const float* __restrict__ bias, float* __restrict__ C,
    f16* __restrict__ C16,
    int M, int N, int K)
{
    extern __shared__ f16 sm[];
    const uint32_t smb = smem_u32(sm);
    const int tid = threadIdx.x;
    const int lane = tid & 31, wid = tid >> 5;
    const int wm = wid & 3, wn = wid >> 2;
    const int quad = lane >> 3, qr = lane & 7;

    const int aRow0 = blockIdx.y * 128;
    const int bRow0 = blockIdx.x * 128;
    const int nchunks = K >> 5;

    auto prefetch = [&](int stg, int k0) {
#pragma unroll
        for (int it = 0; it < 4; it++) {
            int c = tid + it * 256;
            int row = c >> 2;
            int ch  = c & 3;
            const f16* gsrc;
            unsigned soff;
            if (row < 128) {
                gsrc = A + (size_t)(aRow0 + row) * K + k0 + ch * 8;
                soff = SA_H + row * TSTRIDE + ch * 8;
            } else {
                int r = row - 128;
                gsrc = Bt + (size_t)(bRow0 + r) * K + k0 + ch * 8;
                soff = SB_H + r * TSTRIDE + ch * 8;
            }
            CP_ASYNC16(smb + (stg * STG_E + soff) * 2, gsrc);
        }
        CP_COMMIT();
    };

    prefetch(0, 0);
    prefetch(1, 32);

    float acc[2][8][4] = {};
    int sidx = 0, pidx = 2;

    for (int ck = 0; ck < nchunks; ck++) {
        if (ck < nchunks - 1) { CP_WAIT(1); } else { CP_WAIT(0); }
        __syncthreads();

        if (ck + 2 < nchunks) {
            prefetch(pidx, (ck + 2) << 5);
            pidx = (pidx == 2) ? 0 : pidx + 1;
        }

        const f16* st = sm + sidx * STG_E;
        sidx = (sidx == 2) ? 0 : sidx + 1;
#pragma unroll
        for (int kk = 0; kk < 32; kk += 16) {
            unsigned af[2][4];
#pragma unroll
            for (int mt = 0; mt < 2; mt++) {
                int arow = wm * 32 + mt * 16 + qr + ((quad & 1) << 3);
                int acol = kk + ((quad >> 1) << 3);
                ldsm4(af[mt], smem_u32(st + SA_H + arow * TSTRIDE + acol));
            }
#pragma unroll
            for (int np = 0; np < 4; np++) {
                int brow = wn * 64 + np * 16 + qr + ((quad >> 1) << 3);
                int bcol = kk + ((quad & 1) << 3);
                unsigned bf[4];
                ldsm4(bf, smem_u32(st + SB_H + brow * TSTRIDE + bcol));
#pragma unroll
                for (int mt = 0; mt < 2; mt++) {
                    mma16816h(acc[mt][np * 2],     af[mt], bf);
                    mma16816h(acc[mt][np * 2 + 1], af[mt], bf + 2);
                }
            }
        }
    }

    const int gr0 = blockIdx.y * 128 + wm * 32 + (lane >> 2);
    const int gc0 = blockIdx.x * 128 + wn * 64 + (lane & 3) * 2;
#pragma unroll
    for (int mt = 0; mt < 2; mt++) {
#pragma unroll
        for (int nt = 0; nt < 8; nt++) {
            int r = gr0 + mt * 16;
            int c = gc0 + nt * 8;
            float b0 = bias[c], b1 = bias[c + 1];
            float v00 = acc[mt][nt][0] + b0, v01 = acc[mt][nt][1] + b1;
            float v10 = acc[mt][nt][2] + b0, v11 = acc[mt][nt][3] + b1;
            if (C) {
                *(float2*)(C + (size_t)r * N + c)       = make_float2(v00, v01);
                *(float2*)(C + (size_t)(r + 8) * N + c) = make_float2(v10, v11);
            }
            if (C16) {
                *(__half2*)(C16 + (size_t)r * N + c) =
                    __half2(__float2half_rn(v00), __float2half_rn(v01));
                *(__half2*)(C16 + (size_t)(r + 8) * N + c) =
                    __half2(__float2half_rn(v10), __float2half_rn(v11));
            }
        }
    }
}

// ---------------- x -> fp16 ----------------
__global__ void splitx_kernel(const float* __restrict__ src,
                              f16* __restrict__ dst, int n4)
{
    int i = blockIdx.x * blockDim.x + threadIdx.x;
    if (i >= n4) return;
    float4 v = ((const float4*)src)[i];
    __half2* dp = (__half2*)(dst + i * 4);
    dp[0] = __half2(__float2half_rn(v.x), __float2half_rn(v.y));
    dp[1] = __half2(__float2half_rn(v.z), __float2half_rn(v.w));
}

// ---------------- transpose + convert: W[K][N] -> T[N][K] fp16 ----------------
__global__ void wconv_kernel(const float* __restrict__ W,
                             f16* __restrict__ T, int Kd, int Nd)
{
    __shared__ float t[32][33];
    const int tx = threadIdx.x, ty = threadIdx.y;
    const int n0 = blockIdx.x * 32, k0 = blockIdx.y * 32;
#pragma unroll
    for (int j = 0; j < 4; j++)
        t[ty + j * 8][tx] = W[(size_t)(k0 + ty + j * 8) * Nd + n0 + tx];
    __syncthreads();
#pragma unroll
    for (int j = 0; j < 4; j++) {
        float v = t[tx][ty + j * 8];
        size_t idx = (size_t)(n0 + ty + j * 8) * Kd + k0 + tx;
        T[idx] = __float2half_rn(v);
    }
}

// ---------------- block mean reprs (fp16 input) ----------------
__global__ void repr_kernel(const f16* __restrict__ qkv16,
                            float* __restrict__ qrepr, float* __restrict__ krepr)
{
    int idx = blockIdx.x * blockDim.x + threadIdx.x;
    int d = idx & 63;
    int n = (idx >> 6) & 63;
    int h = (idx >> 12) & 15;
    int b = idx >> 16;
    const f16* base = qkv16 + ((size_t)(b * L_ + n * BS_)) * TD_ + h * HD_ + d;
    float sq = 0.f, sk = 0.f;
#pragma unroll 8
    for (int s = 0; s < BS_; s++) {
        sq += __half2float(base[(size_t)s * TD_]);
        sk += __half2float(base[(size_t)s * TD_ + D_]);
    }
    qrepr[idx] = sq * (1.0f / BS_);
    krepr[idx] = sk * (1.0f / BS_);
}

// ---------------- sinkhorn -> P (fp16 hi/lo) ----------------
__global__ __launch_bounds__(256) void sinkhorn_kernel(
    const float* __restrict__ qrepr, const float* __restrict__ krepr,
    const float* __restrict__ gumbel,
    f16* __restrict__ Phi, f16* __restrict__ Plo)
{
    __shared__ float La[64][65];
    const int bh = blockIdx.x;
    const int tid = threadIdx.x;
    const float* qr = qrepr + bh * NB_ * HD_;
    const float* kr = krepr + bh * NB_ * HD_;

    for (int e = tid; e < NB_ * NB_; e += 256) {
        int nn = e >> 6, m = e & 63;
        float s = 0.f;
#pragma unroll 16
        for (int d = 0; d < HD_; d++) s += qr[nn * HD_ + d] * kr[m * HD_ + d];
        La[nn][m] = (s * SCALE_ + gumbel[bh * NB_ * NB_ + e]) * (1.0f / TEMP_);
    }
    __syncthreads();

    for (int it = 0; it < 7; it++) {
        if (tid < 64) {
            float mx = -1e30f;
            for (int m = 0; m < 64; m++) mx = fmaxf(mx, La[tid][m]);
            float se = 0.f;
            for (int m = 0; m < 64; m++) se += expf(La[tid][m] - mx);
            float ls = mx + logf(se);
            for (int m = 0; m < 64; m++) La[tid][m] -= ls;
        }
        __syncthreads();
        if (tid < 64) {
            float mx = -1e30f;
            for (int r = 0; r < 64; r++) mx = fmaxf(mx, La[r][tid]);
            float se = 0.f;
            for (int r = 0; r < 64; r++) se += expf(La[r][tid] - mx);
            float ls = mx + logf(se);
            for (int r = 0; r < 64; r++) La[r][tid] -= ls;
        }
        __syncthreads();
    }
    for (int e = tid; e < NB_ * NB_; e += 256) {
        float p = expf(La[e >> 6][e & 63]);
        f16 hp = __float2half_rn(p);
        Phi[bh * 4096 + e] = hp;
        Plo[bh * 4096 + e] = __float2half_rn(p - __half2float(hp));
    }
}

// ---------------- tensor-core k/v soft permutation ----------------
// C[64 n2, 4096 f] = P[64,64] @ X[64 m, 4096 f], per (bh, which); 2-term exact.
// grid (64, 16, 2): 256-f chunks. A via ldsm4 (P n2-major), B via ldsm4t (X [K][N]).
#define PP_STR 72
#define XX_STR 264
#define SO_PHI 0
#define SO_PLO 9216
#define SO_X   18432
#define SORT_SMEM (SO_X + 64 * XX_STR * 2)   // 52224 bytes

__global__ __launch_bounds__(256, 2) void sortp_kernel(
    const f16* __restrict__ qkv16, const f16* __restrict__ Phi,
    const f16* __restrict__ Plo,
    f16* __restrict__ ks16, f16* __restrict__ vs16)
{
    extern __shared__ __align__(16) char smc[];
    const uint32_t smb = smem_u32(smc);
    f16* SPH = (f16*)(smc + SO_PHI);   // [64 n2][72] (A hi)
    f16* SPL = (f16*)(smc + SO_PLO);   // [64 n2][72] (A lo)
    f16* SX  = (f16*)(smc + SO_X);     // [64 m][264] (B, [K][N] for trans-ldsm)

    const int bh = blockIdx.x;
    const int fc = blockIdx.y;
    const int which = blockIdx.z;
    const int b = bh >> 4, h = bh & 15;
    const int tid = threadIdx.x;
    const int lane = tid & 31, wid = tid >> 5;
    const int quad = lane >> 3, qr = lane & 7;

    const f16* pg_hi = Phi + (size_t)bh * 4096;
    const f16* pg_lo = Plo + (size_t)bh * 4096;
    const f16* xbase = qkv16 + (size_t)b * L_ * TD_ + (which ? 2 * D_ : D_) + h * HD_;

#pragma unroll
    for (int it = 0; it < 12; it++) {
        int c = tid + it * 256;          // 0..3071
        if (c < 512) {
            int row = c >> 3, ch = c & 7;
            CP_ASYNC16(smb + SO_PHI + row * 144 + ch * 16, pg_hi + row * 64 + ch * 8);
        } else if (c < 1024) {
            int cc = c - 512;
            int row = cc >> 3, ch = cc & 7;
            CP_ASYNC16(smb + SO_PLO + row * 144 + ch * 16, pg_lo + row * 64 + ch * 8);
        } else {
            int cx = c - 1024;           // 0..2047
            int m = cx >> 5;
            int sidx = (cx >> 3) & 3;
            int ch = cx & 7;
            const f16* src = xbase + (size_t)(m * 64 + fc * 4 + sidx) * TD_ + ch * 8;
            CP_ASYNC16(smb + SO_X + m * (XX_STR * 2) + sidx * 128 + ch * 16, src);
        }
    }
    CP_COMMIT(); CP_WAIT(0);
    __syncthreads();

    const int mt = wid & 3, nh = wid >> 2;   // n2-tile, f-half
    float acc[8][2][4] = {};
#pragma unroll
    for (int k16 = 0; k16 < 4; k16++) {
        unsigned aoff = (mt * 16 + qr + ((quad & 1) << 3)) * PP_STR
                        + k16 * 16 + ((quad >> 1) << 3);
        unsigned aH[4], aL[4];
        ldsm4(aH, smem_u32(SPH + aoff));
        ldsm4(aL, smem_u32(SPL + aoff));
#pragma unroll
        for (int nt = 0; nt < 8; nt++) {
            unsigned voff = (k16 * 16 + qr + ((quad & 1) << 3)) * XX_STR
                            + nh * 128 + nt * 16 + ((quad >> 1) << 3);
            unsigned xF[4];
            ldsm4t(xF, smem_u32(SX + voff));
            mma16816h(acc[nt][0], aH, xF);
            mma16816h(acc[nt][1], aH, xF + 2);
            mma16816h(acc[nt][0], aL, xF);
            mma16816h(acc[nt][1], aL, xF + 2);
        }
    }

    f16* dstg = which ? vs16 : ks16;
    const int n2r = mt * 16 + (lane >> 2);
    const size_t obase = (size_t)bh * NB_ * 4096 + fc * 256;
#pragma unroll
    for (int nt = 0; nt < 8; nt++) {
#pragma unroll
        for (int hf = 0; hf < 2; hf++) {
            int c = nh * 128 + nt * 16 + hf * 8 + (lane & 3) * 2;
            *(__half2*)(dstg + obase + (size_t)n2r * 4096 + c) =
                __half2(__float2half_rn(acc[nt][hf][0]),
                        __float2half_rn(acc[nt][hf][1]));
            *(__half2*)(dstg + obase + (size_t)(n2r + 8) * 4096 + c) =
                __half2(__float2half_rn(acc[nt][hf][2]),
                        __float2half_rn(acc[nt][hf][3]));
        }
    }
}

// ---------------- all-fp16 tensor-core block attention ----------------
#define AQ_STR 72
#define AP_STR 136
#define O_SQ   0
#define O_SK   9216
#define O_SV   27648
#define O_SP   46080
#define O_SCT  63488
#define ATTN_SMEM (O_SCT + 128 * 72 * 4)   // 100352 bytes

__global__ __launch_bounds__(256) void attn_kernel(
    const f16* __restrict__ qkv16, const f16* __restrict__ ks16,
    const f16* __restrict__ vs16, f16* __restrict__ ath)
{
    extern __shared__ __align__(16) char smc[];
    const uint32_t smb = smem_u32(smc);
    f16* SQ = (f16*)(smc + O_SQ);
    f16* SK = (f16*)(smc + O_SK);
    f16* SV = (f16*)(smc + O_SV);
    f16* SP = (f16*)(smc + O_SP);
    float* SCT = (float*)(smc + O_SCT);

    const int blk = blockIdx.x;
    const int n2 = blk & 63;
    const int h = (blk >> 6) & 15;
    const int b = blk >> 10;
    const int bh = b * H_ + h;
    const int tid = threadIdx.x;
    const int lane = tid & 31, wid = tid >> 5;
    const int quad = lane >> 3, qr = lane & 7;
    const int nn = (n2 + 1) & 63;

    const f16* qb16 = qkv16 + ((size_t)(b * L_ + n2 * BS_)) * TD_ + h * HD_;
    const f16* kn16 = ks16 + ((size_t)(bh * NB_ + nn)) * BS_ * HD_;
    const f16* vn16 = vs16 + ((size_t)(bh * NB_ + nn)) * BS_ * HD_;

#pragma unroll
    for (int it = 0; it < 10; it++) {
        int c = tid + it * 256;
        int row = c >> 3;
        int ch = c & 7;
        const f16* src;
        uint32_t dst;
        if (row < 64) {
            src = qb16 + (size_t)row * TD_ + ch * 8;
            dst = O_SQ + row * 144 + ch * 16;
        } else if (row < 128) {
            int s = row - 64;
            src = qb16 + D_ + (size_t)s * TD_ + ch * 8;
            dst = O_SK + s * 144 + ch * 16;
        } else if (row < 192) {
            int s = row - 128;
            src = kn16 + s * 64 + ch * 8;
            dst = O_SK + (64 + s) * 144 + ch * 16;
        } else if (row < 256) {
            int s = row - 192;
            src = qb16 + 2 * D_ + (size_t)s * TD_ + ch * 8;
            dst = O_SV + s * 144 + ch * 16;
        } else {
            int s = row - 256;
            src = vn16 + s * 64 + ch * 8;
            dst = O_SV + (64 + s) * 144 + ch * 16;
        }
        CP_ASYNC16(smb + dst, src);
    }
    CP_COMMIT();
    CP_WAIT(0);
    __syncthreads();

    // scores: warp tile 16(s) x 64(j)
    {
        const int wm = wid & 3, wn = wid >> 2;
        float sacc[8][4] = {};
#pragma unroll
        for (int k16 = 0; k16 < 64; k16 += 16) {
            unsigned aoff = (wm * 16 + qr + ((quad & 1) << 3)) * AQ_STR
                            + k16 + ((quad >> 1) << 3);
            unsigned aF[4];
            ldsm4(aF, smem_u32(SQ + aoff));
#pragma unroll
            for (int nt = 0; nt < 4; nt++) {
                unsigned boff = (wn * 64 + nt * 16 + qr + ((quad >> 1) << 3)) * AQ_STR
                                + k16 + ((quad & 1) << 3);
                unsigned bF[4];
                ldsm4(bF, smem_u32(SK + boff));
                mma16816h(sacc[nt * 2],     aF, bF);
                mma16816h(sacc[nt * 2 + 1], aF, bF + 2);
            }
        }
        const bool maskme = (n2 == NB_ - 1) && (wn == 1);
        const int srow = wm * 16 + (lane >> 2);
#pragma unroll
        for (int p = 0; p < 8; p++) {
            int j0 = wn * 64 + (p >> 1) * 16 + (p & 1) * 8 + (lane & 3) * 2;
            float c0 = sacc[p][0] * SCALE_, c1 = sacc[p][1] * SCALE_;
            float c2 = sacc[p][2] * SCALE_, c3 = sacc[p][3] * SCALE_;
            if (maskme) { c0 = c1 = c2 = c3 = -1e9f; }
            SCT[j0 * 72 + srow]           = c0;
            SCT[(j0 + 1) * 72 + srow]     = c1;
            SCT[j0 * 72 + srow + 8]       = c2;
            SCT[(j0 + 1) * 72 + srow + 8] = c3;
        }
    }
    __syncthreads();

    // softmax: 4 threads per query row; normalize fused into fp16 SP write
    {
        const int sr = tid >> 2;
        const int qd = tid & 3;
        float mx = -1e30f;
#pragma unroll
        for (int jj = 0; jj < 32; jj++) {
            int j = jj * 4 + qd;
            mx = fmaxf(mx, SCT[j * 72 + sr]);
        }
        mx = fmaxf(mx, __shfl_xor_sync(0xffffffffu, mx, 1));
        mx = fmaxf(mx, __shfl_xor_sync(0xffffffffu, mx, 2));
        float se = 0.f;
        float ev[32];
#pragma unroll
        for (int jj = 0; jj < 32; jj++) {
            int j = jj * 4 + qd;
            float e = __expf(SCT[j * 72 + sr] - mx);
            ev[jj] = e;
            se += e;
        }
        se += __shfl_xor_sync(0xffffffffu, se, 1);
        se += __shfl_xor_sync(0xffffffffu, se, 2);
        float inv = 1.0f / se;
#pragma unroll
        for (int jj = 0; jj < 32; jj++) {
            int j = jj * 4 + qd;
            SP[sr * AP_STR + j] = __float2half_rn(ev[jj] * inv);
        }
    }
    __syncthreads();

    // PV: warp tile 16(s) x 32(d); V via trans-ldsm from [j][d]
    {
        const int wm = wid & 3, wn = wid >> 2;
        float oacc[4][4] = {};
#pragma unroll
        for (int k16 = 0; k16 < 128; k16 += 16) {
            unsigned poff = (wm * 16 + qr + ((quad & 1) << 3)) * AP_STR
                            + k16 + ((quad >> 1) << 3);
            unsigned pF[4];
            ldsm4(pF, smem_u32(SP + poff));
#pragma unroll
            for (int nt = 0; nt < 2; nt++) {
                unsigned voff = (k16 + qr + ((quad & 1) << 3)) * AQ_STR
                                + wn * 32 + nt * 16 + ((quad >> 1) << 3);
                unsigned vF[4];
                ldsm4t(vF, smem_u32(SV + voff));
                mma16816h(oacc[nt * 2],     pF, vF);
                mma16816h(oacc[nt * 2 + 1], pF, vF + 2);
            }
        }
        const int srow = wm * 16 + (lane >> 2);
        const size_t obase = ((size_t)(b * L_ + n2 * BS_)) * D_ + h * HD_;
#pragma unroll
        for (int p = 0; p < 4; p++) {
            int d0 = wn * 32 + (p >> 1) * 16 + (p & 1) * 8 + (lane & 3) * 2;
#pragma unroll
            for (int rr = 0; rr < 2; rr++) {
                float v0 = oacc[p][rr * 2], v1 = oacc[p][rr * 2 + 1];
                size_t o = obase + (size_t)(srow + rr * 8) * D_ + d0;
                *(__half2*)(ath + o) =
                    __half2(__float2half_rn(v0), __float2half_rn(v1));
            }
        }
    }
}

// ---------------- launch ----------------
extern "C" void kernel_launch(void* const* d_in, const int* in_sizes, int n_in,
                              void* d_out, int out_size)
{
    const float* x      = (const float*)d_in[0];
    const float* gumbel = (const float*)d_in[1];
    const float* W_qkv  = (const float*)d_in[2];
    const float* b_qkv  = (const float*)d_in[3];
    const float* W_out  = (const float*)d_in[4];
    const float* b_out  = (const float*)d_in[5];
    float* out = (float*)d_out;

    float *qr, *kr;
    f16 *qkv16, *phi, *plo, *ks16, *vs16, *xh, *w1h, *w2h, *ath;
    cudaGetSymbolAddress((void**)&qkv16, g_qkv16);
    cudaGetSymbolAddress((void**)&qr,  g_qrepr);
    cudaGetSymbolAddress((void**)&kr,  g_krepr);
    cudaGetSymbolAddress((void**)&phi, g_phi);
    cudaGetSymbolAddress((void**)&plo, g_plo);
    cudaGetSymbolAddress((void**)&ks16, g_ks16);
    cudaGetSymbolAddress((void**)&vs16, g_vs16);
    cudaGetSymbolAddress((void**)&xh,  g_xh);
    cudaGetSymbolAddress((void**)&w1h, g_w1h);
    cudaGetSymbolAddress((void**)&w2h, g_w2h);
    cudaGetSymbolAddress((void**)&ath, g_ath);

    cudaFuncSetAttribute(attn_kernel,
                         cudaFuncAttributeMaxDynamicSharedMemorySize, ATTN_SMEM);
    cudaFuncSetAttribute(hgemm1_kernel,
                         cudaFuncAttributeMaxDynamicSharedMemorySize, GEMM_SMEM);
    cudaFuncSetAttribute(sortp_kernel,
                         cudaFuncAttributeMaxDynamicSharedMemorySize, SORT_SMEM);

    // conversions
    splitx_kernel<<<(M_ * D_ / 4 + 255) / 256, 256>>>(x, xh, M_ * D_ / 4);
    wconv_kernel<<<dim3(TD_ / 32, D_ / 32), dim3(32, 8)>>>(W_qkv, w1h, D_, TD_);
    wconv_kernel<<<dim3(D_ / 32, D_ / 32), dim3(32, 8)>>>(W_out, w2h, D_, D_);

    // 1) qkv = x @ W_qkv + b_qkv  (fp16 output only)
    hgemm1_kernel<<<dim3(TD_ / 128, M_ / 128), 256, GEMM_SMEM>>>(
        xh, w1h, b_qkv, (float*)nullptr, qkv16, M_, TD_, D_);

    // 2) block mean reprs
    repr_kernel<<<(B_ * H_ * NB_ * HD_) / 256, 256>>>(qkv16, qr, kr);

    // 3) sinkhorn -> P (fp16 hi/lo)
    sinkhorn_kernel<<<B_ * H_, 256>>>(qr, kr, gumbel, phi, plo);

    // 4) tensor-core soft permutation of K/V blocks
    sortp_kernel<<<dim3(B_ * H_, 16, 2), 256, SORT_SMEM>>>(
        qkv16, phi, plo, ks16, vs16);

    // 5) all-fp16 tensor-core attention
    attn_kernel<<<B_ * H_ * NB_, 256, ATTN_SMEM>>>(qkv16, ks16, vs16, ath);

    // 6) out = attn @ W_out + b_out
    hgemm1_kernel<<<dim3(D_ / 128, M_ / 128), 256, GEMM_SMEM>>>(
        ath, w2h, b_out, out, (f16*)nullptr, M_, D_, D_);
}

// round 14
// speedup vs baseline: 5.0848x; 1.0455x over previous
#include <cuda_runtime.h>
#include <cuda_fp16.h>
#include <cstdint>

// ---------------- problem constants ----------------
#define B_   4
#define L_   4096
#define D_   1024
#define H_   16
#define BS_  64
#define HD_  64
#define NB_  64
#define TD_  3072           // 3*D
#define M_   (B_*L_)        // 16384
#define SCALE_ 0.125f       // HD^-0.5
#define TEMP_  0.7f

typedef __half f16;

// ---------------- device scratch (allocation-free) ----------------
__device__ f16   g_qkv16[B_*L_*TD_];            // fp16 qkv
__device__ float g_qrepr[B_*H_*NB_*HD_];
__device__ float g_krepr[B_*H_*NB_*HD_];
__device__ f16   g_phi  [B_*H_*NB_*NB_];        // P hi (fp16)
__device__ f16   g_plo  [B_*H_*NB_*NB_];        // P lo (fp16 residual)
__device__ f16   g_ks16 [B_*H_*NB_*BS_*HD_];    // sorted K fp16
__device__ f16   g_vs16 [B_*H_*NB_*BS_*HD_];    // sorted V fp16
__device__ f16   g_xh   [M_*D_];                // x fp16
__device__ f16   g_w1h  [TD_*D_];               // W_qkv^T fp16
__device__ f16   g_w2h  [D_*D_];                // W_out^T fp16
__device__ f16   g_ath  [M_*D_];                // attn out fp16

// ---------------- PTX helpers ----------------
__device__ __forceinline__ unsigned smem_u32(const void* p) {
    return (unsigned)__cvta_generic_to_shared(p);
}
__device__ __forceinline__ void ldsm4(unsigned* r, unsigned addr) {
    asm volatile("ldmatrix.sync.aligned.m8n8.x4.shared.b16 {%0,%1,%2,%3}, [%4];\n"
                 : "=r"(r[0]), "=r"(r[1]), "=r"(r[2]), "=r"(r[3]) : "r"(addr));
}
__device__ __forceinline__ void ldsm4t(unsigned* r, unsigned addr) {
    asm volatile("ldmatrix.sync.aligned.m8n8.x4.trans.shared.b16 {%0,%1,%2,%3}, [%4];\n"
                 : "=r"(r[0]), "=r"(r[1]), "=r"(r[2]), "=r"(r[3]) : "r"(addr));
}
__device__ __forceinline__ void mma16816h(float* c, const unsigned* a, const unsigned* b) {
    asm volatile(
        "mma.sync.aligned.m16n8k16.row.col.f32.f16.f16.f32 "
        "{%0,%1,%2,%3}, {%4,%5,%6,%7}, {%8,%9}, {%0,%1,%2,%3};\n"
        : "+f"(c[0]), "+f"(c[1]), "+f"(c[2]), "+f"(c[3])
        : "r"(a[0]), "r"(a[1]), "r"(a[2]), "r"(a[3]), "r"(b[0]), "r"(b[1]));
}
#define CP_ASYNC16(dst, src) \
    asm volatile("cp.async.cg.shared.global [%0], [%1], 16;\n" :: "r"(dst), "l"(src))
#define CP_COMMIT() asm volatile("cp.async.commit_group;\n")
#define CP_WAIT(n)  asm volatile("cp.async.wait_group %0;\n" :: "n"(n))

// ---------------- single-fp16 GEMM, 128x128 tile, fused repr reduction ----------------
#define TSTRIDE 40
#define SA_H    0
#define SB_H    (128 * TSTRIDE)
#define STG_E   (SB_H + 128 * TSTRIDE)     // 10240 elems / stage
#define NSTG    3
#define GEMM_SMEM (NSTG * STG_E * 2)       // 61440 bytes

__global__ __launch_bounds__(256, 2) void hgemm1_kernel(
    const f16* __restrict__ A, const f16* __restrict__ Bt,
    const float* __restrict__ bias, float* __restrict__ C,
    f16* __restrict__ C16,
    float* __restrict__ QR, float* __restrict__ KR,
    int M, int N, int K)
{
    extern __shared__ f16 sm[];
    const uint32_t smb = smem_u32(sm);
    const int tid = threadIdx.x;
    const int lane = tid & 31, wid = tid >> 5;
    const int wm = wid & 3, wn = wid >> 2;
    const int quad = lane >> 3, qr = lane & 7;

    const int aRow0 = blockIdx.y * 128;
    const int bRow0 = blockIdx.x * 128;
    const int nchunks = K >> 5;

    auto prefetch = [&](int stg, int k0) {
#pragma unroll
        for (int it = 0; it < 4; it++) {
            int c = tid + it * 256;
            int row = c >> 2;
            int ch  = c & 3;
            const f16* gsrc;
            unsigned soff;
            if (row < 128) {
                gsrc = A + (size_t)(aRow0 + row) * K + k0 + ch * 8;
                soff = SA_H + row * TSTRIDE + ch * 8;
            } else {
                int r = row - 128;
                gsrc = Bt + (size_t)(bRow0 + r) * K + k0 + ch * 8;
                soff = SB_H + r * TSTRIDE + ch * 8;
            }
            CP_ASYNC16(smb + (stg * STG_E + soff) * 2, gsrc);
        }
        CP_COMMIT();
    };

    prefetch(0, 0);
    prefetch(1, 32);

    float acc[2][8][4] = {};
    int sidx = 0, pidx = 2;

    for (int ck = 0; ck < nchunks; ck++) {
        if (ck < nchunks - 1) { CP_WAIT(1); } else { CP_WAIT(0); }
        __syncthreads();

        if (ck + 2 < nchunks) {
            prefetch(pidx, (ck + 2) << 5);
            pidx = (pidx == 2) ? 0 : pidx + 1;
        }

        const f16* st = sm + sidx * STG_E;
        sidx = (sidx == 2) ? 0 : sidx + 1;
#pragma unroll
        for (int kk = 0; kk < 32; kk += 16) {
            unsigned af[2][4];
#pragma unroll
            for (int mt = 0; mt < 2; mt++) {
                int arow = wm * 32 + mt * 16 + qr + ((quad & 1) << 3);
                int acol = kk + ((quad >> 1) << 3);
                ldsm4(af[mt], smem_u32(st + SA_H + arow * TSTRIDE + acol));
            }
#pragma unroll
            for (int np = 0; np < 4; np++) {
                int brow = wn * 64 + np * 16 + qr + ((quad >> 1) << 3);
                int bcol = kk + ((quad & 1) << 3);
                unsigned bf[4];
                ldsm4(bf, smem_u32(st + SB_H + brow * TSTRIDE + bcol));
#pragma unroll
                for (int mt = 0; mt < 2; mt++) {
                    mma16816h(acc[mt][np * 2],     af[mt], bf);
                    mma16816h(acc[mt][np * 2 + 1], af[mt], bf + 2);
                }
            }
        }
    }

    const int gr0 = blockIdx.y * 128 + wm * 32 + (lane >> 2);
    const int gc0 = blockIdx.x * 128 + wn * 64 + (lane & 3) * 2;
    const bool do_repr = (QR != nullptr) && (blockIdx.x < 16);

#pragma unroll
    for (int nt = 0; nt < 8; nt++) {
        float s0 = 0.f, s1 = 0.f;
        int c = gc0 + nt * 8;
        float b0 = bias[c], b1 = bias[c + 1];
#pragma unroll
        for (int mt = 0; mt < 2; mt++) {
            int r = gr0 + mt * 16;
            float v00 = acc[mt][nt][0] + b0, v01 = acc[mt][nt][1] + b1;
            float v10 = acc[mt][nt][2] + b0, v11 = acc[mt][nt][3] + b1;
            if (C) {
                *(float2*)(C + (size_t)r * N + c)       = make_float2(v00, v01);
                *(float2*)(C + (size_t)(r + 8) * N + c) = make_float2(v10, v11);
            }
            if (C16) {
                *(__half2*)(C16 + (size_t)r * N + c) =
                    __half2(__float2half_rn(v00), __float2half_rn(v01));
                *(__half2*)(C16 + (size_t)(r + 8) * N + c) =
                    __half2(__float2half_rn(v10), __float2half_rn(v11));
            }
            s0 += v00 + v10;
            s1 += v01 + v11;
        }
        if (do_repr) {
            // reduce over the 8 lane-rows (lane>>2)
            s0 += __shfl_xor_sync(0xffffffffu, s0, 4);
            s0 += __shfl_xor_sync(0xffffffffu, s0, 8);
            s0 += __shfl_xor_sync(0xffffffffu, s0, 16);
            s1 += __shfl_xor_sync(0xffffffffu, s1, 4);
            s1 += __shfl_xor_sync(0xffffffffu, s1, 8);
            s1 += __shfl_xor_sync(0xffffffffu, s1, 16);
            if ((lane >> 2) == 0) {
                int which = c >> 10;            // 0 = q, 1 = k (c < 2048)
                int hh = (c & 1023) >> 6;
                int d  = c & 63;
                int gb = blockIdx.y >> 5;                       // batch
                int nb = ((blockIdx.y & 31) << 1) | (wm >> 1);  // block index
                float* dst = which ? KR : QR;
                int idx = ((gb * H_ + hh) << 12) + (nb << 6) + d;
                atomicAdd(dst + idx,     s0 * 0.015625f);
                atomicAdd(dst + idx + 1, s1 * 0.015625f);
            }
        }
    }
}

// ---------------- x -> fp16 ----------------
__global__ void splitx_kernel(const float* __restrict__ src,
                              f16* __restrict__ dst, int n4)
{
    int i = blockIdx.x * blockDim.x + threadIdx.x;
    if (i >= n4) return;
    float4 v = ((const float4*)src)[i];
    __half2* dp = (__half2*)(dst + i * 4);
    dp[0] = __half2(__float2half_rn(v.x), __float2half_rn(v.y));
    dp[1] = __half2(__float2half_rn(v.z), __float2half_rn(v.w));
}

// ---------------- transpose + convert: W[K][N] -> T[N][K] fp16 ----------------
__global__ void wconv_kernel(const float* __restrict__ W,
                             f16* __restrict__ T, int Kd, int Nd)
{
    __shared__ float t[32][33];
    const int tx = threadIdx.x, ty = threadIdx.y;
    const int n0 = blockIdx.x * 32, k0 = blockIdx.y * 32;
#pragma unroll
    for (int j = 0; j < 4; j++)
        t[ty + j * 8][tx] = W[(size_t)(k0 + ty + j * 8) * Nd + n0 + tx];
    __syncthreads();
#pragma unroll
    for (int j = 0; j < 4; j++) {
        float v = t[tx][ty + j * 8];
        size_t idx = (size_t)(n0 + ty + j * 8) * Kd + k0 + tx;
        T[idx] = __float2half_rn(v);
    }
}

// ---------------- sinkhorn -> P (fp16 hi/lo), parallel logsumexp ----------------
__global__ __launch_bounds__(256) void sinkhorn_kernel(
    const float* __restrict__ qrepr, const float* __restrict__ krepr,
    const float* __restrict__ gumbel,
    f16* __restrict__ Phi, f16* __restrict__ Plo)
{
    __shared__ float La[64][65];
    const int bh = blockIdx.x;
    const int tid = threadIdx.x;
    const float* qr = qrepr + bh * NB_ * HD_;
    const float* kr = krepr + bh * NB_ * HD_;

    for (int e = tid; e < NB_ * NB_; e += 256) {
        int nn = e >> 6, m = e & 63;
        float s = 0.f;
#pragma unroll 16
        for (int d = 0; d < HD_; d++) s += qr[nn * HD_ + d] * kr[m * HD_ + d];
        La[nn][m] = (s * SCALE_ + gumbel[bh * NB_ * NB_ + e]) * (1.0f / TEMP_);
    }
    __syncthreads();

    const int rr = tid >> 2, qd = tid & 3;
    for (int it = 0; it < 7; it++) {
        {   // row logsumexp (axis -1): 4 threads per row
            float mx = -1e30f;
#pragma unroll
            for (int i = 0; i < 16; i++) mx = fmaxf(mx, La[rr][qd * 16 + i]);
            mx = fmaxf(mx, __shfl_xor_sync(0xffffffffu, mx, 1));
            mx = fmaxf(mx, __shfl_xor_sync(0xffffffffu, mx, 2));
            float se = 0.f;
#pragma unroll
            for (int i = 0; i < 16; i++) se += expf(La[rr][qd * 16 + i] - mx);
            se += __shfl_xor_sync(0xffffffffu, se, 1);
            se += __shfl_xor_sync(0xffffffffu, se, 2);
            float ls = mx + logf(se);
#pragma unroll
            for (int i = 0; i < 16; i++) La[rr][qd * 16 + i] -= ls;
        }
        __syncthreads();
        {   // col logsumexp (axis -2): 4 threads per col
            float mx = -1e30f;
#pragma unroll
            for (int i = 0; i < 16; i++) mx = fmaxf(mx, La[qd * 16 + i][rr]);
            mx = fmaxf(mx, __shfl_xor_sync(0xffffffffu, mx, 1));
            mx = fmaxf(mx, __shfl_xor_sync(0xffffffffu, mx, 2));
            float se = 0.f;
#pragma unroll
            for (int i = 0; i < 16; i++) se += expf(La[qd * 16 + i][rr] - mx);
            se += __shfl_xor_sync(0xffffffffu, se, 1);
            se += __shfl_xor_sync(0xffffffffu, se, 2);
            float ls = mx + logf(se);
#pragma unroll
            for (int i = 0; i < 16; i++) La[qd * 16 + i][rr] -= ls;
        }
        __syncthreads();
    }
    for (int e = tid; e < NB_ * NB_; e += 256) {
        float p = expf(La[e >> 6][e & 63]);
        f16 hp = __float2half_rn(p);
        Phi[bh * 4096 + e] = hp;
        Plo[bh * 4096 + e] = __float2half_rn(p - __half2float(hp));
    }
}

// ---------------- tensor-core k/v soft permutation ----------------
#define PP_STR 72
#define XX_STR 264
#define SO_PHI 0
#define SO_PLO 9216
#define SO_X   18432
#define SORT_SMEM (SO_X + 64 * XX_STR * 2)   // 52224 bytes

__global__ __launch_bounds__(256, 2) void sortp_kernel(
    const f16* __restrict__ qkv16, const f16* __restrict__ Phi,
    const f16* __restrict__ Plo,
    f16* __restrict__ ks16, f16* __restrict__ vs16)
{
    extern __shared__ __align__(16) char smc[];
    const uint32_t smb = smem_u32(smc);
    f16* SPH = (f16*)(smc + SO_PHI);
    f16* SPL = (f16*)(smc + SO_PLO);
    f16* SX  = (f16*)(smc + SO_X);

    const int bh = blockIdx.x;
    const int fc = blockIdx.y;
    const int which = blockIdx.z;
    const int b = bh >> 4, h = bh & 15;
    const int tid = threadIdx.x;
    const int lane = tid & 31, wid = tid >> 5;
    const int quad = lane >> 3, qr = lane & 7;

    const f16* pg_hi = Phi + (size_t)bh * 4096;
    const f16* pg_lo = Plo + (size_t)bh * 4096;
    const f16* xbase = qkv16 + (size_t)b * L_ * TD_ + (which ? 2 * D_ : D_) + h * HD_;

#pragma unroll
    for (int it = 0; it < 12; it++) {
        int c = tid + it * 256;
        if (c < 512) {
            int row = c >> 3, ch = c & 7;
            CP_ASYNC16(smb + SO_PHI + row * 144 + ch * 16, pg_hi + row * 64 + ch * 8);
        } else if (c < 1024) {
            int cc = c - 512;
            int row = cc >> 3, ch = cc & 7;
            CP_ASYNC16(smb + SO_PLO + row * 144 + ch * 16, pg_lo + row * 64 + ch * 8);
        } else {
            int cx = c - 1024;
            int m = cx >> 5;
            int sidx = (cx >> 3) & 3;
            int ch = cx & 7;
            const f16* src = xbase + (size_t)(m * 64 + fc * 4 + sidx) * TD_ + ch * 8;
            CP_ASYNC16(smb + SO_X + m * (XX_STR * 2) + sidx * 128 + ch * 16, src);
        }
    }
    CP_COMMIT(); CP_WAIT(0);
    __syncthreads();

    const int mt = wid & 3, nh = wid >> 2;
    float acc[8][2][4] = {};
#pragma unroll
    for (int k16 = 0; k16 < 4; k16++) {
        unsigned aoff = (mt * 16 + qr + ((quad & 1) << 3)) * PP_STR
                        + k16 * 16 + ((quad >> 1) << 3);
        unsigned aH[4], aL[4];
        ldsm4(aH, smem_u32(SPH + aoff));
        ldsm4(aL, smem_u32(SPL + aoff));
#pragma unroll
        for (int nt = 0; nt < 8; nt++) {
            unsigned voff = (k16 * 16 + qr + ((quad & 1) << 3)) * XX_STR
                            + nh * 128 + nt * 16 + ((quad >> 1) << 3);
            unsigned xF[4];
            ldsm4t(xF, smem_u32(SX + voff));
            mma16816h(acc[nt][0], aH, xF);
            mma16816h(acc[nt][1], aH, xF + 2);
            mma16816h(acc[nt][0], aL, xF);
            mma16816h(acc[nt][1], aL, xF + 2);
        }
    }

    f16* dstg = which ? vs16 : ks16;
    const int n2r = mt * 16 + (lane >> 2);
    const size_t obase = (size_t)bh * NB_ * 4096 + fc * 256;
#pragma unroll
    for (int nt = 0; nt < 8; nt++) {
#pragma unroll
        for (int hf = 0; hf < 2; hf++) {
            int c = nh * 128 + nt * 16 + hf * 8 + (lane & 3) * 2;
            *(__half2*)(dstg + obase + (size_t)n2r * 4096 + c) =
                __half2(__float2half_rn(acc[nt][hf][0]),
                        __float2half_rn(acc[nt][hf][1]));
            *(__half2*)(dstg + obase + (size_t)(n2r + 8) * 4096 + c) =
                __half2(__float2half_rn(acc[nt][hf][2]),
                        __float2half_rn(acc[nt][hf][3]));
        }
    }
}

// ---------------- all-fp16 tensor-core block attention (split load groups) ----------------
#define AQ_STR 72
#define AP_STR 136
#define O_SQ   0
#define O_SK   9216
#define O_SV   27648
#define O_SP   46080
#define O_SCT  63488
#define ATTN_SMEM (O_SCT + 128 * 72 * 4)   // 100352 bytes

__global__ __launch_bounds__(256) void attn_kernel(
    const f16* __restrict__ qkv16, const f16* __restrict__ ks16,
    const f16* __restrict__ vs16, f16* __restrict__ ath)
{
    extern __shared__ __align__(16) char smc[];
    const uint32_t smb = smem_u32(smc);
    f16* SQ = (f16*)(smc + O_SQ);
    f16* SK = (f16*)(smc + O_SK);
    f16* SV = (f16*)(smc + O_SV);
    f16* SP = (f16*)(smc + O_SP);
    float* SCT = (float*)(smc + O_SCT);

    const int blk = blockIdx.x;
    const int n2 = blk & 63;
    const int h = (blk >> 6) & 15;
    const int b = blk >> 10;
    const int bh = b * H_ + h;
    const int tid = threadIdx.x;
    const int lane = tid & 31, wid = tid >> 5;
    const int quad = lane >> 3, qr = lane & 7;
    const int nn = (n2 + 1) & 63;

    const f16* qb16 = qkv16 + ((size_t)(b * L_ + n2 * BS_)) * TD_ + h * HD_;
    const f16* kn16 = ks16 + ((size_t)(bh * NB_ + nn)) * BS_ * HD_;
    const f16* vn16 = vs16 + ((size_t)(bh * NB_ + nn)) * BS_ * HD_;

    // group 0: Q, K, Kn (192 rows)
#pragma unroll
    for (int it = 0; it < 6; it++) {
        int c = tid + it * 256;      // 0..1535
        int row = c >> 3;
        int ch = c & 7;
        const f16* src;
        uint32_t dst;
        if (row < 64) {
            src = qb16 + (size_t)row * TD_ + ch * 8;
            dst = O_SQ + row * 144 + ch * 16;
        } else if (row < 128) {
            int s = row - 64;
            src = qb16 + D_ + (size_t)s * TD_ + ch * 8;
            dst = O_SK + s * 144 + ch * 16;
        } else {
            int s = row - 128;
            src = kn16 + s * 64 + ch * 8;
            dst = O_SK + (64 + s) * 144 + ch * 16;
        }
        CP_ASYNC16(smb + dst, src);
    }
    CP_COMMIT();
    // group 1: V, Vn (128 rows) — overlaps with scores/softmax
#pragma unroll
    for (int it = 0; it < 4; it++) {
        int c = tid + it * 256;      // 0..1023
        int row = c >> 3;
        int ch = c & 7;
        const f16* src;
        uint32_t dst;
        if (row < 64) {
            src = qb16 + 2 * D_ + (size_t)row * TD_ + ch * 8;
            dst = O_SV + row * 144 + ch * 16;
        } else {
            int s = row - 64;
            src = vn16 + s * 64 + ch * 8;
            dst = O_SV + (64 + s) * 144 + ch * 16;
        }
        CP_ASYNC16(smb + dst, src);
    }
    CP_COMMIT();
    CP_WAIT(1);          // Q/K/Kn ready; V still in flight
    __syncthreads();

    // scores: warp tile 16(s) x 64(j)
    {
        const int wm = wid & 3, wn = wid >> 2;
        float sacc[8][4] = {};
#pragma unroll
        for (int k16 = 0; k16 < 64; k16 += 16) {
            unsigned aoff = (wm * 16 + qr + ((quad & 1) << 3)) * AQ_STR
                            + k16 + ((quad >> 1) << 3);
            unsigned aF[4];
            ldsm4(aF, smem_u32(SQ + aoff));
#pragma unroll
            for (int nt = 0; nt < 4; nt++) {
                unsigned boff = (wn * 64 + nt * 16 + qr + ((quad >> 1) << 3)) * AQ_STR
                                + k16 + ((quad & 1) << 3);
                unsigned bF[4];
                ldsm4(bF, smem_u32(SK + boff));
                mma16816h(sacc[nt * 2],     aF, bF);
                mma16816h(sacc[nt * 2 + 1], aF, bF + 2);
            }
        }
        const bool maskme = (n2 == NB_ - 1) && (wn == 1);
        const int srow = wm * 16 + (lane >> 2);
#pragma unroll
        for (int p = 0; p < 8; p++) {
            int j0 = wn * 64 + (p >> 1) * 16 + (p & 1) * 8 + (lane & 3) * 2;
            float c0 = sacc[p][0] * SCALE_, c1 = sacc[p][1] * SCALE_;
            float c2 = sacc[p][2] * SCALE_, c3 = sacc[p][3] * SCALE_;
            if (maskme) { c0 = c1 = c2 = c3 = -1e9f; }
            SCT[j0 * 72 + srow]           = c0;
            SCT[(j0 + 1) * 72 + srow]     = c1;
            SCT[j0 * 72 + srow + 8]       = c2;
            SCT[(j0 + 1) * 72 + srow + 8] = c3;
        }
    }
    __syncthreads();

    // softmax: 4 threads per query row; normalize fused into fp16 SP write
    {
        const int sr = tid >> 2;
        const int qd = tid & 3;
        float mx = -1e30f;
#pragma unroll
        for (int jj = 0; jj < 32; jj++) {
            int j = jj * 4 + qd;
            mx = fmaxf(mx, SCT[j * 72 + sr]);
        }
        mx = fmaxf(mx, __shfl_xor_sync(0xffffffffu, mx, 1));
        mx = fmaxf(mx, __shfl_xor_sync(0xffffffffu, mx, 2));
        float se = 0.f;
        float ev[32];
#pragma unroll
        for (int jj = 0; jj < 32; jj++) {
            int j = jj * 4 + qd;
            float e = __expf(SCT[j * 72 + sr] - mx);
            ev[jj] = e;
            se += e;
        }
        se += __shfl_xor_sync(0xffffffffu, se, 1);
        se += __shfl_xor_sync(0xffffffffu, se, 2);
        float inv = 1.0f / se;
#pragma unroll
        for (int jj = 0; jj < 32; jj++) {
            int j = jj * 4 + qd;
            SP[sr * AP_STR + j] = __float2half_rn(ev[jj] * inv);
        }
    }
    CP_WAIT(0);          // V/Vn ready
    __syncthreads();

    // PV: warp tile 16(s) x 32(d); V via trans-ldsm from [j][d]
    {
        const int wm = wid & 3, wn = wid >> 2;
        float oacc[4][4] = {};
#pragma unroll
        for (int k16 = 0; k16 < 128; k16 += 16) {
            unsigned poff = (wm * 16 + qr + ((quad & 1) << 3)) * AP_STR
                            + k16 + ((quad >> 1) << 3);
            unsigned pF[4];
            ldsm4(pF, smem_u32(SP + poff));
#pragma unroll
            for (int nt = 0; nt < 2; nt++) {
                unsigned voff = (k16 + qr + ((quad & 1) << 3)) * AQ_STR
                                + wn * 32 + nt * 16 + ((quad >> 1) << 3);
                unsigned vF[4];
                ldsm4t(vF, smem_u32(SV + voff));
                mma16816h(oacc[nt * 2],     pF, vF);
                mma16816h(oacc[nt * 2 + 1], pF, vF + 2);
            }
        }
        const int srow = wm * 16 + (lane >> 2);
        const size_t obase = ((size_t)(b * L_ + n2 * BS_)) * D_ + h * HD_;
#pragma unroll
        for (int p = 0; p < 4; p++) {
            int d0 = wn * 32 + (p >> 1) * 16 + (p & 1) * 8 + (lane & 3) * 2;
#pragma unroll
            for (int rr = 0; rr < 2; rr++) {
                float v0 = oacc[p][rr * 2], v1 = oacc[p][rr * 2 + 1];
                size_t o = obase + (size_t)(srow + rr * 8) * D_ + d0;
                *(__half2*)(ath + o) =
                    __half2(__float2half_rn(v0), __float2half_rn(v1));
            }
        }
    }
}

// ---------------- launch ----------------
extern "C" void kernel_launch(void* const* d_in, const int* in_sizes, int n_in,
                              void* d_out, int out_size)
{
    const float* x      = (const float*)d_in[0];
    const float* gumbel = (const float*)d_in[1];
    const float* W_qkv  = (const float*)d_in[2];
    const float* b_qkv  = (const float*)d_in[3];
    const float* W_out  = (const float*)d_in[4];
    const float* b_out  = (const float*)d_in[5];
    float* out = (float*)d_out;

    float *qr, *kr;
    f16 *qkv16, *phi, *plo, *ks16, *vs16, *xh, *w1h, *w2h, *ath;
    cudaGetSymbolAddress((void**)&qkv16, g_qkv16);
    cudaGetSymbolAddress((void**)&qr,  g_qrepr);
    cudaGetSymbolAddress((void**)&kr,  g_krepr);
    cudaGetSymbolAddress((void**)&phi, g_phi);
    cudaGetSymbolAddress((void**)&plo, g_plo);
    cudaGetSymbolAddress((void**)&ks16, g_ks16);
    cudaGetSymbolAddress((void**)&vs16, g_vs16);
    cudaGetSymbolAddress((void**)&xh,  g_xh);
    cudaGetSymbolAddress((void**)&w1h, g_w1h);
    cudaGetSymbolAddress((void**)&w2h, g_w2h);
    cudaGetSymbolAddress((void**)&ath, g_ath);

    cudaFuncSetAttribute(attn_kernel,
                         cudaFuncAttributeMaxDynamicSharedMemorySize, ATTN_SMEM);
    cudaFuncSetAttribute(hgemm1_kernel,
                         cudaFuncAttributeMaxDynamicSharedMemorySize, GEMM_SMEM);
    cudaFuncSetAttribute(sortp_kernel,
                         cudaFuncAttributeMaxDynamicSharedMemorySize, SORT_SMEM);

    // conversions
    splitx_kernel<<<(M_ * D_ / 4 + 255) / 256, 256>>>(x, xh, M_ * D_ / 4);
    wconv_kernel<<<dim3(TD_ / 32, D_ / 32), dim3(32, 8)>>>(W_qkv, w1h, D_, TD_);
    wconv_kernel<<<dim3(D_ / 32, D_ / 32), dim3(32, 8)>>>(W_out, w2h, D_, D_);

    // zero repr accumulators (fused reduction uses atomicAdd)
    cudaMemsetAsync(qr, 0, B_ * H_ * NB_ * HD_ * sizeof(float));
    cudaMemsetAsync(kr, 0, B_ * H_ * NB_ * HD_ * sizeof(float));

    // 1) qkv = x @ W_qkv + b_qkv  (fp16 out + fused repr sums)
    hgemm1_kernel<<<dim3(TD_ / 128, M_ / 128), 256, GEMM_SMEM>>>(
        xh, w1h, b_qkv, (float*)nullptr, qkv16, qr, kr, M_, TD_, D_);

    // 2) sinkhorn -> P (fp16 hi/lo)
    sinkhorn_kernel<<<B_ * H_, 256>>>(qr, kr, gumbel, phi, plo);

    // 3) tensor-core soft permutation of K/V blocks
    sortp_kernel<<<dim3(B_ * H_, 16, 2), 256, SORT_SMEM>>>(
        qkv16, phi, plo, ks16, vs16);

    // 4) all-fp16 tensor-core attention
    attn_kernel<<<B_ * H_ * NB_, 256, ATTN_SMEM>>>(qkv16, ks16, vs16, ath);

    // 5) out = attn @ W_out + b_out
    hgemm1_kernel<<<dim3(D_ / 128, M_ / 128), 256, GEMM_SMEM>>>(
        ath, w2h, b_out, out, (f16*)nullptr, (float*)nullptr, (float*)nullptr,
        M_, D_, D_);
}

// round 15
// speedup vs baseline: 5.1111x; 1.0052x over previous
#include <cuda_runtime.h>
#include <cuda_fp16.h>
#include <cstdint>

// ---------------- problem constants ----------------
#define B_   4
#define L_   4096
#define D_   1024
#define H_   16
#define BS_  64
#define HD_  64
#define NB_  64
#define TD_  3072           // 3*D
#define M_   (B_*L_)        // 16384
#define SCALE_ 0.125f       // HD^-0.5
#define TEMP_  0.7f

typedef __half f16;

// ---------------- device scratch (allocation-free) ----------------
__device__ f16   g_qkv16[B_*L_*TD_];            // fp16 qkv
__device__ float g_qrepr[B_*H_*NB_*HD_];
__device__ float g_krepr[B_*H_*NB_*HD_];
__device__ f16   g_phi  [B_*H_*NB_*NB_];        // P hi (fp16)
__device__ f16   g_plo  [B_*H_*NB_*NB_];        // P lo (fp16 residual)
__device__ f16   g_ks16 [B_*H_*NB_*BS_*HD_];    // sorted K fp16
__device__ f16   g_vs16 [B_*H_*NB_*BS_*HD_];    // sorted V fp16
__device__ f16   g_xh   [M_*D_];                // x fp16
__device__ f16   g_w1h  [TD_*D_];               // W_qkv^T fp16
__device__ f16   g_w2h  [D_*D_];                // W_out^T fp16
__device__ f16   g_ath  [M_*D_];                // attn out fp16

// ---------------- PTX helpers ----------------
__device__ __forceinline__ unsigned smem_u32(const void* p) {
    return (unsigned)__cvta_generic_to_shared(p);
}
__device__ __forceinline__ void ldsm4(unsigned* r, unsigned addr) {
    asm volatile("ldmatrix.sync.aligned.m8n8.x4.shared.b16 {%0,%1,%2,%3}, [%4];\n"
                 : "=r"(r[0]), "=r"(r[1]), "=r"(r[2]), "=r"(r[3]) : "r"(addr));
}
__device__ __forceinline__ void ldsm4t(unsigned* r, unsigned addr) {
    asm volatile("ldmatrix.sync.aligned.m8n8.x4.trans.shared.b16 {%0,%1,%2,%3}, [%4];\n"
                 : "=r"(r[0]), "=r"(r[1]), "=r"(r[2]), "=r"(r[3]) : "r"(addr));
}
__device__ __forceinline__ void mma16816h(float* c, const unsigned* a, const unsigned* b) {
    asm volatile(
        "mma.sync.aligned.m16n8k16.row.col.f32.f16.f16.f32 "
        "{%0,%1,%2,%3}, {%4,%5,%6,%7}, {%8,%9}, {%0,%1,%2,%3};\n"
        : "+f"(c[0]), "+f"(c[1]), "+f"(c[2]), "+f"(c[3])
        : "r"(a[0]), "r"(a[1]), "r"(a[2]), "r"(a[3]), "r"(b[0]), "r"(b[1]));
}
#define CP_ASYNC16(dst, src) \
    asm volatile("cp.async.cg.shared.global [%0], [%1], 16;\n" :: "r"(dst), "l"(src))
#define CP_COMMIT() asm volatile("cp.async.commit_group;\n")
#define CP_WAIT(n)  asm volatile("cp.async.wait_group %0;\n" :: "n"(n))

// ---------------- single-fp16 GEMM, 128x128 tile, fused repr reduction ----------------
#define TSTRIDE 40
#define SA_H    0
#define SB_H    (128 * TSTRIDE)
#define STG_E   (SB_H + 128 * TSTRIDE)     // 10240 elems / stage
#define NSTG    3
#define GEMM_SMEM (NSTG * STG_E * 2)       // 61440 bytes

__global__ __launch_bounds__(256, 2) void hgemm1_kernel(
    const f16* __restrict__ A, const f16* __restrict__ Bt,
    const float* __restrict__ bias, float* __restrict__ C,
    f16* __restrict__ C16,
    float* __restrict__ QR, float* __restrict__ KR,
    int M, int N, int K)
{
    extern __shared__ f16 sm[];
    const uint32_t smb = smem_u32(sm);
    const int tid = threadIdx.x;
    const int lane = tid & 31, wid = tid >> 5;
    const int wm = wid & 3, wn = wid >> 2;
    const int quad = lane >> 3, qr = lane & 7;

    const int aRow0 = blockIdx.y * 128;
    const int bRow0 = blockIdx.x * 128;
    const int nchunks = K >> 5;

    auto prefetch = [&](int stg, int k0) {
#pragma unroll
        for (int it = 0; it < 4; it++) {
            int c = tid + it * 256;
            int row = c >> 2;
            int ch  = c & 3;
            const f16* gsrc;
            unsigned soff;
            if (row < 128) {
                gsrc = A + (size_t)(aRow0 + row) * K + k0 + ch * 8;
                soff = SA_H + row * TSTRIDE + ch * 8;
            } else {
                int r = row - 128;
                gsrc = Bt + (size_t)(bRow0 + r) * K + k0 + ch * 8;
                soff = SB_H + r * TSTRIDE + ch * 8;
            }
            CP_ASYNC16(smb + (stg * STG_E + soff) * 2, gsrc);
        }
        CP_COMMIT();
    };

    prefetch(0, 0);
    prefetch(1, 32);

    float acc[2][8][4] = {};
    int sidx = 0, pidx = 2;

    for (int ck = 0; ck < nchunks; ck++) {
        if (ck < nchunks - 1) { CP_WAIT(1); } else { CP_WAIT(0); }
        __syncthreads();

        if (ck + 2 < nchunks) {
            prefetch(pidx, (ck + 2) << 5);
            pidx = (pidx == 2) ? 0 : pidx + 1;
        }

        const f16* st = sm + sidx * STG_E;
        sidx = (sidx == 2) ? 0 : sidx + 1;
#pragma unroll
        for (int kk = 0; kk < 32; kk += 16) {
            unsigned af[2][4];
#pragma unroll
            for (int mt = 0; mt < 2; mt++) {
                int arow = wm * 32 + mt * 16 + qr + ((quad & 1) << 3);
                int acol = kk + ((quad >> 1) << 3);
                ldsm4(af[mt], smem_u32(st + SA_H + arow * TSTRIDE + acol));
            }
#pragma unroll
            for (int np = 0; np < 4; np++) {
                int brow = wn * 64 + np * 16 + qr + ((quad >> 1) << 3);
                int bcol = kk + ((quad & 1) << 3);
                unsigned bf[4];
                ldsm4(bf, smem_u32(st + SB_H + brow * TSTRIDE + bcol));
#pragma unroll
                for (int mt = 0; mt < 2; mt++) {
                    mma16816h(acc[mt][np * 2],     af[mt], bf);
                    mma16816h(acc[mt][np * 2 + 1], af[mt], bf + 2);
                }
            }
        }
    }

    const int gr0 = blockIdx.y * 128 + wm * 32 + (lane >> 2);
    const int gc0 = blockIdx.x * 128 + wn * 64 + (lane & 3) * 2;
    const bool do_repr = (QR != nullptr) && (blockIdx.x < 16);

#pragma unroll
    for (int nt = 0; nt < 8; nt++) {
        float s0 = 0.f, s1 = 0.f;
        int c = gc0 + nt * 8;
        float b0 = bias[c], b1 = bias[c + 1];
#pragma unroll
        for (int mt = 0; mt < 2; mt++) {
            int r = gr0 + mt * 16;
            float v00 = acc[mt][nt][0] + b0, v01 = acc[mt][nt][1] + b1;
            float v10 = acc[mt][nt][2] + b0, v11 = acc[mt][nt][3] + b1;
            if (C) {
                *(float2*)(C + (size_t)r * N + c)       = make_float2(v00, v01);
                *(float2*)(C + (size_t)(r + 8) * N + c) = make_float2(v10, v11);
            }
            if (C16) {
                *(__half2*)(C16 + (size_t)r * N + c) =
                    __half2(__float2half_rn(v00), __float2half_rn(v01));
                *(__half2*)(C16 + (size_t)(r + 8) * N + c) =
                    __half2(__float2half_rn(v10), __float2half_rn(v11));
            }
            s0 += v00 + v10;
            s1 += v01 + v11;
        }
        if (do_repr) {
            s0 += __shfl_xor_sync(0xffffffffu, s0, 4);
            s0 += __shfl_xor_sync(0xffffffffu, s0, 8);
            s0 += __shfl_xor_sync(0xffffffffu, s0, 16);
            s1 += __shfl_xor_sync(0xffffffffu, s1, 4);
            s1 += __shfl_xor_sync(0xffffffffu, s1, 8);
            s1 += __shfl_xor_sync(0xffffffffu, s1, 16);
            if ((lane >> 2) == 0) {
                int which = c >> 10;
                int hh = (c & 1023) >> 6;
                int d  = c & 63;
                int gb = blockIdx.y >> 5;
                int nb = ((blockIdx.y & 31) << 1) | (wm >> 1);
                float* dst = which ? KR : QR;
                int idx = ((gb * H_ + hh) << 12) + (nb << 6) + d;
                atomicAdd(dst + idx,     s0 * 0.015625f);
                atomicAdd(dst + idx + 1, s1 * 0.015625f);
            }
        }
    }
}

// ---------------- x -> fp16 ----------------
__global__ void splitx_kernel(const float* __restrict__ src,
                              f16* __restrict__ dst, int n4)
{
    int i = blockIdx.x * blockDim.x + threadIdx.x;
    if (i >= n4) return;
    float4 v = ((const float4*)src)[i];
    __half2* dp = (__half2*)(dst + i * 4);
    dp[0] = __half2(__float2half_rn(v.x), __float2half_rn(v.y));
    dp[1] = __half2(__float2half_rn(v.z), __float2half_rn(v.w));
}

// ---------------- transpose + convert: W[K][N] -> T[N][K] fp16 ----------------
__global__ void wconv_kernel(const float* __restrict__ W,
                             f16* __restrict__ T, int Kd, int Nd)
{
    __shared__ float t[32][33];
    const int tx = threadIdx.x, ty = threadIdx.y;
    const int n0 = blockIdx.x * 32, k0 = blockIdx.y * 32;
#pragma unroll
    for (int j = 0; j < 4; j++)
        t[ty + j * 8][tx] = W[(size_t)(k0 + ty + j * 8) * Nd + n0 + tx];
    __syncthreads();
#pragma unroll
    for (int j = 0; j < 4; j++) {
        float v = t[tx][ty + j * 8];
        size_t idx = (size_t)(n0 + ty + j * 8) * Kd + k0 + tx;
        T[idx] = __float2half_rn(v);
    }
}

// ---------------- sinkhorn -> P (fp16 hi/lo), parallel logsumexp ----------------
__global__ __launch_bounds__(256) void sinkhorn_kernel(
    const float* __restrict__ qrepr, const float* __restrict__ krepr,
    const float* __restrict__ gumbel,
    f16* __restrict__ Phi, f16* __restrict__ Plo)
{
    __shared__ float La[64][65];
    const int bh = blockIdx.x;
    const int tid = threadIdx.x;
    const float* qr = qrepr + bh * NB_ * HD_;
    const float* kr = krepr + bh * NB_ * HD_;

    for (int e = tid; e < NB_ * NB_; e += 256) {
        int nn = e >> 6, m = e & 63;
        float s = 0.f;
#pragma unroll 16
        for (int d = 0; d < HD_; d++) s += qr[nn * HD_ + d] * kr[m * HD_ + d];
        La[nn][m] = (s * SCALE_ + gumbel[bh * NB_ * NB_ + e]) * (1.0f / TEMP_);
    }
    __syncthreads();

    const int rr = tid >> 2, qd = tid & 3;
    for (int it = 0; it < 7; it++) {
        {
            float mx = -1e30f;
#pragma unroll
            for (int i = 0; i < 16; i++) mx = fmaxf(mx, La[rr][qd * 16 + i]);
            mx = fmaxf(mx, __shfl_xor_sync(0xffffffffu, mx, 1));
            mx = fmaxf(mx, __shfl_xor_sync(0xffffffffu, mx, 2));
            float se = 0.f;
#pragma unroll
            for (int i = 0; i < 16; i++) se += expf(La[rr][qd * 16 + i] - mx);
            se += __shfl_xor_sync(0xffffffffu, se, 1);
            se += __shfl_xor_sync(0xffffffffu, se, 2);
            float ls = mx + logf(se);
#pragma unroll
            for (int i = 0; i < 16; i++) La[rr][qd * 16 + i] -= ls;
        }
        __syncthreads();
        {
            float mx = -1e30f;
#pragma unroll
            for (int i = 0; i < 16; i++) mx = fmaxf(mx, La[qd * 16 + i][rr]);
            mx = fmaxf(mx, __shfl_xor_sync(0xffffffffu, mx, 1));
            mx = fmaxf(mx, __shfl_xor_sync(0xffffffffu, mx, 2));
            float se = 0.f;
#pragma unroll
            for (int i = 0; i < 16; i++) se += expf(La[qd * 16 + i][rr] - mx);
            se += __shfl_xor_sync(0xffffffffu, se, 1);
            se += __shfl_xor_sync(0xffffffffu, se, 2);
            float ls = mx + logf(se);
#pragma unroll
            for (int i = 0; i < 16; i++) La[qd * 16 + i][rr] -= ls;
        }
        __syncthreads();
    }
    for (int e = tid; e < NB_ * NB_; e += 256) {
        float p = expf(La[e >> 6][e & 63]);
        f16 hp = __float2half_rn(p);
        Phi[bh * 4096 + e] = hp;
        Plo[bh * 4096 + e] = __float2half_rn(p - __half2float(hp));
    }
}

// ---------------- tensor-core k/v soft permutation ----------------
#define PP_STR 72
#define XX_STR 264
#define SO_PHI 0
#define SO_PLO 9216
#define SO_X   18432
#define SORT_SMEM (SO_X + 64 * XX_STR * 2)   // 52224 bytes

__global__ __launch_bounds__(256, 2) void sortp_kernel(
    const f16* __restrict__ qkv16, const f16* __restrict__ Phi,
    const f16* __restrict__ Plo,
    f16* __restrict__ ks16, f16* __restrict__ vs16)
{
    extern __shared__ __align__(16) char smc[];
    const uint32_t smb = smem_u32(smc);
    f16* SPH = (f16*)(smc + SO_PHI);
    f16* SPL = (f16*)(smc + SO_PLO);
    f16* SX  = (f16*)(smc + SO_X);

    const int bh = blockIdx.x;
    const int fc = blockIdx.y;
    const int which = blockIdx.z;
    const int b = bh >> 4, h = bh & 15;
    const int tid = threadIdx.x;
    const int lane = tid & 31, wid = tid >> 5;
    const int quad = lane >> 3, qr = lane & 7;

    const f16* pg_hi = Phi + (size_t)bh * 4096;
    const f16* pg_lo = Plo + (size_t)bh * 4096;
    const f16* xbase = qkv16 + (size_t)b * L_ * TD_ + (which ? 2 * D_ : D_) + h * HD_;

#pragma unroll
    for (int it = 0; it < 12; it++) {
        int c = tid + it * 256;
        if (c < 512) {
            int row = c >> 3, ch = c & 7;
            CP_ASYNC16(smb + SO_PHI + row * 144 + ch * 16, pg_hi + row * 64 + ch * 8);
        } else if (c < 1024) {
            int cc = c - 512;
            int row = cc >> 3, ch = cc & 7;
            CP_ASYNC16(smb + SO_PLO + row * 144 + ch * 16, pg_lo + row * 64 + ch * 8);
        } else {
            int cx = c - 1024;
            int m = cx >> 5;
            int sidx = (cx >> 3) & 3;
            int ch = cx & 7;
            const f16* src = xbase + (size_t)(m * 64 + fc * 4 + sidx) * TD_ + ch * 8;
            CP_ASYNC16(smb + SO_X + m * (XX_STR * 2) + sidx * 128 + ch * 16, src);
        }
    }
    CP_COMMIT(); CP_WAIT(0);
    __syncthreads();

    const int mt = wid & 3, nh = wid >> 2;
    float acc[8][2][4] = {};
#pragma unroll
    for (int k16 = 0; k16 < 4; k16++) {
        unsigned aoff = (mt * 16 + qr + ((quad & 1) << 3)) * PP_STR
                        + k16 * 16 + ((quad >> 1) << 3);
        unsigned aH[4], aL[4];
        ldsm4(aH, smem_u32(SPH + aoff));
        ldsm4(aL, smem_u32(SPL + aoff));
#pragma unroll
        for (int nt = 0; nt < 8; nt++) {
            unsigned voff = (k16 * 16 + qr + ((quad & 1) << 3)) * XX_STR
                            + nh * 128 + nt * 16 + ((quad >> 1) << 3);
            unsigned xF[4];
            ldsm4t(xF, smem_u32(SX + voff));
            mma16816h(acc[nt][0], aH, xF);
            mma16816h(acc[nt][1], aH, xF + 2);
            mma16816h(acc[nt][0], aL, xF);
            mma16816h(acc[nt][1], aL, xF + 2);
        }
    }

    f16* dstg = which ? vs16 : ks16;
    const int n2r = mt * 16 + (lane >> 2);
    const size_t obase = (size_t)bh * NB_ * 4096 + fc * 256;
#pragma unroll
    for (int nt = 0; nt < 8; nt++) {
#pragma unroll
        for (int hf = 0; hf < 2; hf++) {
            int c = nh * 128 + nt * 16 + hf * 8 + (lane & 3) * 2;
            *(__half2*)(dstg + obase + (size_t)n2r * 4096 + c) =
                __half2(__float2half_rn(acc[nt][hf][0]),
                        __float2half_rn(acc[nt][hf][1]));
            *(__half2*)(dstg + obase + (size_t)(n2r + 8) * 4096 + c) =
                __half2(__float2half_rn(acc[nt][hf][2]),
                        __float2half_rn(acc[nt][hf][3]));
        }
    }
}

// ---------------- all-fp16 attention: register softmax, 2 CTAs/SM ----------------
#define AQ_STR 72
#define AP_STR 136
#define O_SQ   0
#define O_SK   9216
#define O_SV   27648
#define O_SP   46080
#define O_EXC  63488
#define ATTN_SMEM (O_EXC + 2 * 64 * 8)     // 64512 bytes

__global__ __launch_bounds__(256, 2) void attn_kernel(
    const f16* __restrict__ qkv16, const f16* __restrict__ ks16,
    const f16* __restrict__ vs16, f16* __restrict__ ath)
{
    extern __shared__ __align__(16) char smc[];
    const uint32_t smb = smem_u32(smc);
    f16* SQ = (f16*)(smc + O_SQ);
    f16* SK = (f16*)(smc + O_SK);
    f16* SV = (f16*)(smc + O_SV);
    f16* SP = (f16*)(smc + O_SP);
    float2* EXC = (float2*)(smc + O_EXC);   // [2 wn][64 row] (m, s)

    const int blk = blockIdx.x;
    const int n2 = blk & 63;
    const int h = (blk >> 6) & 15;
    const int b = blk >> 10;
    const int bh = b * H_ + h;
    const int tid = threadIdx.x;
    const int lane = tid & 31, wid = tid >> 5;
    const int quad = lane >> 3, qr = lane & 7;
    const int nn = (n2 + 1) & 63;

    const f16* qb16 = qkv16 + ((size_t)(b * L_ + n2 * BS_)) * TD_ + h * HD_;
    const f16* kn16 = ks16 + ((size_t)(bh * NB_ + nn)) * BS_ * HD_;
    const f16* vn16 = vs16 + ((size_t)(bh * NB_ + nn)) * BS_ * HD_;

    // group 0: Q, K, Kn
#pragma unroll
    for (int it = 0; it < 6; it++) {
        int c = tid + it * 256;
        int row = c >> 3;
        int ch = c & 7;
        const f16* src;
        uint32_t dst;
        if (row < 64) {
            src = qb16 + (size_t)row * TD_ + ch * 8;
            dst = O_SQ + row * 144 + ch * 16;
        } else if (row < 128) {
            int s = row - 64;
            src = qb16 + D_ + (size_t)s * TD_ + ch * 8;
            dst = O_SK + s * 144 + ch * 16;
        } else {
            int s = row - 128;
            src = kn16 + s * 64 + ch * 8;
            dst = O_SK + (64 + s) * 144 + ch * 16;
        }
        CP_ASYNC16(smb + dst, src);
    }
    CP_COMMIT();
    // group 1: V, Vn (overlaps scores/softmax)
#pragma unroll
    for (int it = 0; it < 4; it++) {
        int c = tid + it * 256;
        int row = c >> 3;
        int ch = c & 7;
        const f16* src;
        uint32_t dst;
        if (row < 64) {
            src = qb16 + 2 * D_ + (size_t)row * TD_ + ch * 8;
            dst = O_SV + row * 144 + ch * 16;
        } else {
            int s = row - 64;
            src = vn16 + s * 64 + ch * 8;
            dst = O_SV + (64 + s) * 144 + ch * 16;
        }
        CP_ASYNC16(smb + dst, src);
    }
    CP_COMMIT();
    CP_WAIT(1);
    __syncthreads();

    const int wm = wid & 3, wn = wid >> 2;
    const int r0 = wm * 16 + (lane >> 2);

    // ---- scores in registers ----
    float sacc[8][4] = {};
#pragma unroll
    for (int k16 = 0; k16 < 64; k16 += 16) {
        unsigned aoff = (wm * 16 + qr + ((quad & 1) << 3)) * AQ_STR
                        + k16 + ((quad >> 1) << 3);
        unsigned aF[4];
        ldsm4(aF, smem_u32(SQ + aoff));
#pragma unroll
        for (int nt = 0; nt < 4; nt++) {
            unsigned boff = (wn * 64 + nt * 16 + qr + ((quad >> 1) << 3)) * AQ_STR
                            + k16 + ((quad & 1) << 3);
            unsigned bF[4];
            ldsm4(bF, smem_u32(SK + boff));
            mma16816h(sacc[nt * 2],     aF, bF);
            mma16816h(sacc[nt * 2 + 1], aF, bF + 2);
        }
    }
    {
        const bool maskme = (n2 == NB_ - 1) && (wn == 1);
#pragma unroll
        for (int p = 0; p < 8; p++)
#pragma unroll
            for (int q = 0; q < 4; q++)
                sacc[p][q] = maskme ? -1e9f : sacc[p][q] * SCALE_;
    }

    // ---- register softmax: local (m,s) per (row, wn-half) ----
    {
        float m0 = -1e30f, m1 = -1e30f;
#pragma unroll
        for (int p = 0; p < 8; p++) {
            m0 = fmaxf(m0, fmaxf(sacc[p][0], sacc[p][1]));
            m1 = fmaxf(m1, fmaxf(sacc[p][2], sacc[p][3]));
        }
        m0 = fmaxf(m0, __shfl_xor_sync(0xffffffffu, m0, 1));
        m0 = fmaxf(m0, __shfl_xor_sync(0xffffffffu, m0, 2));
        m1 = fmaxf(m1, __shfl_xor_sync(0xffffffffu, m1, 1));
        m1 = fmaxf(m1, __shfl_xor_sync(0xffffffffu, m1, 2));
        float s0 = 0.f, s1 = 0.f;
#pragma unroll
        for (int p = 0; p < 8; p++) {
            s0 += __expf(sacc[p][0] - m0) + __expf(sacc[p][1] - m0);
            s1 += __expf(sacc[p][2] - m1) + __expf(sacc[p][3] - m1);
        }
        s0 += __shfl_xor_sync(0xffffffffu, s0, 1);
        s0 += __shfl_xor_sync(0xffffffffu, s0, 2);
        s1 += __shfl_xor_sync(0xffffffffu, s1, 1);
        s1 += __shfl_xor_sync(0xffffffffu, s1, 2);
        if ((lane & 3) == 0) {
            EXC[wn * 64 + r0]     = make_float2(m0, s0);
            EXC[wn * 64 + r0 + 8] = make_float2(m1, s1);
        }
    }
    __syncthreads();

    // ---- merge halves, write fp16 probs ----
    {
        float2 a0 = EXC[r0],      b0 = EXC[64 + r0];
        float2 a1 = EXC[r0 + 8],  b1 = EXC[64 + r0 + 8];
        float g0 = fmaxf(a0.x, b0.x);
        float inv0 = 1.0f / (a0.y * __expf(a0.x - g0) + b0.y * __expf(b0.x - g0));
        float g1 = fmaxf(a1.x, b1.x);
        float inv1 = 1.0f / (a1.y * __expf(a1.x - g1) + b1.y * __expf(b1.x - g1));
#pragma unroll
        for (int p = 0; p < 8; p++) {
            int j0 = wn * 64 + (p >> 1) * 16 + (p & 1) * 8 + (lane & 3) * 2;
            *(__half2*)(SP + r0 * AP_STR + j0) =
                __half2(__float2half_rn(__expf(sacc[p][0] - g0) * inv0),
                        __float2half_rn(__expf(sacc[p][1] - g0) * inv0));
            *(__half2*)(SP + (r0 + 8) * AP_STR + j0) =
                __half2(__float2half_rn(__expf(sacc[p][2] - g1) * inv1),
                        __float2half_rn(__expf(sacc[p][3] - g1) * inv1));
        }
    }
    CP_WAIT(0);
    __syncthreads();

    // ---- PV: warp tile 16(s) x 32(d); V via trans-ldsm ----
    {
        float oacc[4][4] = {};
#pragma unroll
        for (int k16 = 0; k16 < 128; k16 += 16) {
            unsigned poff = (wm * 16 + qr + ((quad & 1) << 3)) * AP_STR
                            + k16 + ((quad >> 1) << 3);
            unsigned pF[4];
            ldsm4(pF, smem_u32(SP + poff));
#pragma unroll
            for (int nt = 0; nt < 2; nt++) {
                unsigned voff = (k16 + qr + ((quad & 1) << 3)) * AQ_STR
                                + wn * 32 + nt * 16 + ((quad >> 1) << 3);
                unsigned vF[4];
                ldsm4t(vF, smem_u32(SV + voff));
                mma16816h(oacc[nt * 2],     pF, vF);
                mma16816h(oacc[nt * 2 + 1], pF, vF + 2);
            }
        }
        const size_t obase = ((size_t)(b * L_ + n2 * BS_)) * D_ + h * HD_;
#pragma unroll
        for (int p = 0; p < 4; p++) {
            int d0 = wn * 32 + (p >> 1) * 16 + (p & 1) * 8 + (lane & 3) * 2;
#pragma unroll
            for (int rr = 0; rr < 2; rr++) {
                float v0 = oacc[p][rr * 2], v1 = oacc[p][rr * 2 + 1];
                size_t o = obase + (size_t)(r0 + rr * 8) * D_ + d0;
                *(__half2*)(ath + o) =
                    __half2(__float2half_rn(v0), __float2half_rn(v1));
            }
        }
    }
}

// ---------------- launch ----------------
extern "C" void kernel_launch(void* const* d_in, const int* in_sizes, int n_in,
                              void* d_out, int out_size)
{
    const float* x      = (const float*)d_in[0];
    const float* gumbel = (const float*)d_in[1];
    const float* W_qkv  = (const float*)d_in[2];
    const float* b_qkv  = (const float*)d_in[3];
    const float* W_out  = (const float*)d_in[4];
    const float* b_out  = (const float*)d_in[5];
    float* out = (float*)d_out;

    float *qr, *kr;
    f16 *qkv16, *phi, *plo, *ks16, *vs16, *xh, *w1h, *w2h, *ath;
    cudaGetSymbolAddress((void**)&qkv16, g_qkv16);
    cudaGetSymbolAddress((void**)&qr,  g_qrepr);
    cudaGetSymbolAddress((void**)&kr,  g_krepr);
    cudaGetSymbolAddress((void**)&phi, g_phi);
    cudaGetSymbolAddress((void**)&plo, g_plo);
    cudaGetSymbolAddress((void**)&ks16, g_ks16);
    cudaGetSymbolAddress((void**)&vs16, g_vs16);
    cudaGetSymbolAddress((void**)&xh,  g_xh);
    cudaGetSymbolAddress((void**)&w1h, g_w1h);
    cudaGetSymbolAddress((void**)&w2h, g_w2h);
    cudaGetSymbolAddress((void**)&ath, g_ath);

    cudaFuncSetAttribute(attn_kernel,
                         cudaFuncAttributeMaxDynamicSharedMemorySize, ATTN_SMEM);
    cudaFuncSetAttribute(hgemm1_kernel,
                         cudaFuncAttributeMaxDynamicSharedMemorySize, GEMM_SMEM);
    cudaFuncSetAttribute(sortp_kernel,
                         cudaFuncAttributeMaxDynamicSharedMemorySize, SORT_SMEM);

    // conversions
    splitx_kernel<<<(M_ * D_ / 4 + 255) / 256, 256>>>(x, xh, M_ * D_ / 4);
    wconv_kernel<<<dim3(TD_ / 32, D_ / 32), dim3(32, 8)>>>(W_qkv, w1h, D_, TD_);
    wconv_kernel<<<dim3(D_ / 32, D_ / 32), dim3(32, 8)>>>(W_out, w2h, D_, D_);

    cudaMemsetAsync(qr, 0, B_ * H_ * NB_ * HD_ * sizeof(float));
    cudaMemsetAsync(kr, 0, B_ * H_ * NB_ * HD_ * sizeof(float));

    // 1) qkv = x @ W_qkv + b_qkv  (fp16 out + fused repr sums)
    hgemm1_kernel<<<dim3(TD_ / 128, M_ / 128), 256, GEMM_SMEM>>>(
        xh, w1h, b_qkv, (float*)nullptr, qkv16, qr, kr, M_, TD_, D_);

    // 2) sinkhorn -> P (fp16 hi/lo)
    sinkhorn_kernel<<<B_ * H_, 256>>>(qr, kr, gumbel, phi, plo);

    // 3) tensor-core soft permutation of K/V blocks
    sortp_kernel<<<dim3(B_ * H_, 16, 2), 256, SORT_SMEM>>>(
        qkv16, phi, plo, ks16, vs16);

    // 4) attention (register softmax, 2 CTAs/SM)
    attn_kernel<<<B_ * H_ * NB_, 256, ATTN_SMEM>>>(qkv16, ks16, vs16, ath);

    // 5) out = attn @ W_out + b_out
    hgemm1_kernel<<<dim3(D_ / 128, M_ / 128), 256, GEMM_SMEM>>>(
        ath, w2h, b_out, out, (f16*)nullptr, (float*)nullptr, (float*)nullptr,
        M_, D_, D_);
}